// round 3
// baseline (speedup 1.0000x reference)
#include <cuda_runtime.h>
#include <cuda_bf16.h>
#include <math.h>

// Problem constants
#define BATCH    2
#define SEQ      2048
#define DMODEL   2048
#define NHEADS   16
#define NKV      4
#define HDIM     128
#define NREP     4
#define MTOT     (BATCH * SEQ)          // 4096
#define KVDIM    (NKV * HDIM)           // 512

// ---------------- scratch (device globals; no allocation allowed) -----------
__device__ float g_q[MTOT * DMODEL];     // 32 MB
__device__ float g_k[MTOT * KVDIM];      // 8 MB
__device__ float g_v[MTOT * KVDIM];      // 8 MB
__device__ float g_att[MTOT * DMODEL];   // 32 MB

// ---------------- SGEMM: C[M,N] = A[M,K] @ B[K,N], all row-major ------------
#define GBM 128
#define GBN 128
#define GBK 8
#define GTM 8
#define GTN 8

__global__ __launch_bounds__(256, 2)
void sgemm_kernel(const float* __restrict__ A, const float* __restrict__ B,
                  float* __restrict__ C, int M, int N, int K) {
    __shared__ float As[GBK][GBM];
    __shared__ float Bs[GBK][GBN];

    const int bx = blockIdx.x;   // along N
    const int by = blockIdx.y;   // along M
    const int tid = threadIdx.x; // 256 threads
    const int tx = tid % 16;     // 16 along N
    const int ty = tid / 16;     // 16 along M

    const float* Ab = A + (size_t)by * GBM * K;
    const float* Bb = B + (size_t)bx * GBN;

    const int aRow = tid >> 1;          // 0..127
    const int aCol = (tid & 1) * 4;     // 0 or 4
    const int bRow = tid >> 5;          // 0..7
    const int bCol = (tid & 31) * 4;    // 0..124

    float acc[GTM][GTN];
    #pragma unroll
    for (int i = 0; i < GTM; i++)
        #pragma unroll
        for (int j = 0; j < GTN; j++) acc[i][j] = 0.f;

    for (int k0 = 0; k0 < K; k0 += GBK) {
        float4 av = *(const float4*)(Ab + (size_t)aRow * K + k0 + aCol);
        As[aCol + 0][aRow] = av.x;
        As[aCol + 1][aRow] = av.y;
        As[aCol + 2][aRow] = av.z;
        As[aCol + 3][aRow] = av.w;
        float4 bv = *(const float4*)(Bb + (size_t)(k0 + bRow) * N + bCol);
        *(float4*)&Bs[bRow][bCol] = bv;
        __syncthreads();

        #pragma unroll
        for (int kk = 0; kk < GBK; kk++) {
            float a[GTM], b[GTN];
            #pragma unroll
            for (int i = 0; i < GTM; i++) a[i] = As[kk][ty * GTM + i];
            #pragma unroll
            for (int j = 0; j < GTN; j++) b[j] = Bs[kk][tx * GTN + j];
            #pragma unroll
            for (int i = 0; i < GTM; i++)
                #pragma unroll
                for (int j = 0; j < GTN; j++)
                    acc[i][j] += a[i] * b[j];
        }
        __syncthreads();
    }

    float* Cb = C + (size_t)(by * GBM) * N + bx * GBN;
    #pragma unroll
    for (int i = 0; i < GTM; i++) {
        #pragma unroll
        for (int j = 0; j < GTN; j += 4) {
            float4 v;
            v.x = acc[i][j + 0]; v.y = acc[i][j + 1];
            v.z = acc[i][j + 2]; v.w = acc[i][j + 3];
            *(float4*)(Cb + (size_t)(ty * GTM + i) * N + tx * GTN + j) = v;
        }
    }
}

// ---------------- Flash attention (causal, GQA) -----------------------------
// One CTA handles 64 query rows for one (batch, head). 256 threads:
// thread t -> row = t/4 (0..63), quarter q4 = t%4.
#define FBR 64
#define FBC 64
#define DHP 132   // padded stride (floats) to avoid stride-128 bank conflicts
#define PSP 65    // padded stride for P tile

#define SMEM_FLOATS (3 * FBR * DHP + FBR * PSP)
#define SMEM_BYTES  (SMEM_FLOATS * 4)

__global__ void attn_kernel(const float* __restrict__ Q,
                            const float* __restrict__ K,
                            const float* __restrict__ V,
                            float* __restrict__ O) {
    extern __shared__ float sm[];
    float* Qs = sm;                    // FBR * DHP
    float* Ks = Qs + FBR * DHP;        // FBC * DHP
    float* Vs = Ks + FBC * DHP;        // FBC * DHP
    float* Ps = Vs + FBC * DHP;        // FBR * PSP

    const int tid = threadIdx.x;       // 256
    const int row = tid >> 2;          // 0..63
    const int q4  = tid & 3;           // 0..3
    const int bh  = blockIdx.y;        // 0..31
    const int b   = bh >> 4;
    const int h   = bh & 15;
    const int kv  = h >> 2;            // h / NREP
    const int q0  = blockIdx.x * FBR;

    // load Q tile [64,128]
    for (int i = tid; i < FBR * (HDIM / 4); i += 256) {
        int r  = i / (HDIM / 4);
        int c4 = (i % (HDIM / 4)) * 4;
        float4 v = *(const float4*)(Q + (size_t)(b * SEQ + q0 + r) * DMODEL + h * HDIM + c4);
        *(float4*)&Qs[r * DHP + c4] = v;
    }

    float m_i = -1e30f, l_i = 0.f;
    float acc[32];
    #pragma unroll
    for (int i = 0; i < 32; i++) acc[i] = 0.f;

    const float scale = 0.08838834764831845f;  // 1/sqrt(128)
    const int qglob = q0 + row;
    const int ntiles = q0 / FBC + 1;

    for (int t = 0; t < ntiles; t++) {
        const int k0 = t * FBC;
        __syncthreads();  // protect Ks/Vs/Ps reuse from previous iteration
        for (int i = tid; i < FBC * (HDIM / 4); i += 256) {
            int r  = i / (HDIM / 4);
            int c4 = (i % (HDIM / 4)) * 4;
            size_t base = (size_t)(b * SEQ + k0 + r) * KVDIM + kv * HDIM + c4;
            *(float4*)&Ks[r * DHP + c4] = *(const float4*)(K + base);
            *(float4*)&Vs[r * DHP + c4] = *(const float4*)(V + base);
        }
        __syncthreads();

        // scores: my row, 16 columns [q4*16, q4*16+16)
        float s[16];
        #pragma unroll
        for (int j = 0; j < 16; j++) s[j] = 0.f;
        #pragma unroll 4
        for (int d = 0; d < HDIM; d += 4) {
            float4 qv = *(const float4*)&Qs[row * DHP + d];
            #pragma unroll
            for (int j = 0; j < 16; j++) {
                float4 kvv = *(const float4*)&Ks[(q4 * 16 + j) * DHP + d];
                s[j] += qv.x * kvv.x + qv.y * kvv.y + qv.z * kvv.z + qv.w * kvv.w;
            }
        }

        float tmax = -1e30f;
        #pragma unroll
        for (int j = 0; j < 16; j++) {
            int kg = k0 + q4 * 16 + j;
            s[j] = (kg <= qglob) ? s[j] * scale : -1e30f;
            tmax = fmaxf(tmax, s[j]);
        }
        tmax = fmaxf(tmax, __shfl_xor_sync(0xffffffffu, tmax, 1));
        tmax = fmaxf(tmax, __shfl_xor_sync(0xffffffffu, tmax, 2));

        float m_new = fmaxf(m_i, tmax);
        float corr  = __expf(m_i - m_new);
        float psum = 0.f;
        #pragma unroll
        for (int j = 0; j < 16; j++) {
            float p = __expf(s[j] - m_new);
            s[j] = p;
            psum += p;
        }
        psum += __shfl_xor_sync(0xffffffffu, psum, 1);
        psum += __shfl_xor_sync(0xffffffffu, psum, 2);
        l_i = l_i * corr + psum;
        m_i = m_new;
        #pragma unroll
        for (int i = 0; i < 32; i++) acc[i] *= corr;

        #pragma unroll
        for (int j = 0; j < 16; j++) Ps[row * PSP + q4 * 16 + j] = s[j];
        __syncthreads();

        // O += P @ V  (my 32 output dims: d = q4*32 + i)
        #pragma unroll 4
        for (int c = 0; c < FBC; c++) {
            float p = Ps[row * PSP + c];
            const float4* vrow = (const float4*)&Vs[c * DHP + q4 * 32];
            #pragma unroll
            for (int i4 = 0; i4 < 8; i4++) {
                float4 vv = vrow[i4];
                acc[i4 * 4 + 0] += p * vv.x;
                acc[i4 * 4 + 1] += p * vv.y;
                acc[i4 * 4 + 2] += p * vv.z;
                acc[i4 * 4 + 3] += p * vv.w;
            }
        }
    }

    const float inv = 1.f / l_i;
    float* out = O + (size_t)(b * SEQ + q0 + row) * DMODEL + h * HDIM + q4 * 32;
    #pragma unroll
    for (int i4 = 0; i4 < 8; i4++) {
        float4 v;
        v.x = acc[i4 * 4 + 0] * inv;
        v.y = acc[i4 * 4 + 1] * inv;
        v.z = acc[i4 * 4 + 2] * inv;
        v.w = acc[i4 * 4 + 3] * inv;
        *(float4*)(out + i4 * 4) = v;
    }
}

// ---------------- launch -----------------------------------------------------
extern "C" void kernel_launch(void* const* d_in, const int* in_sizes, int n_in,
                              void* d_out, int out_size) {
    const float* x  = (const float*)d_in[0];
    const float* wq = (const float*)d_in[1];
    const float* wk = (const float*)d_in[2];
    const float* wv = (const float*)d_in[3];
    const float* wo = (const float*)d_in[4];
    float* out = (float*)d_out;

    float *q, *k, *v, *att;
    cudaGetSymbolAddress((void**)&q,   g_q);
    cudaGetSymbolAddress((void**)&k,   g_k);
    cudaGetSymbolAddress((void**)&v,   g_v);
    cudaGetSymbolAddress((void**)&att, g_att);

    cudaFuncSetAttribute(attn_kernel, cudaFuncAttributeMaxDynamicSharedMemorySize, SMEM_BYTES);

    dim3 blk(256);
    // Q projection: [4096,2048] @ [2048,2048]
    sgemm_kernel<<<dim3(DMODEL / GBN, MTOT / GBM), blk>>>(x, wq, q, MTOT, DMODEL, DMODEL);
    // K/V projections: [4096,2048] @ [2048,512]
    sgemm_kernel<<<dim3(KVDIM / GBN, MTOT / GBM), blk>>>(x, wk, k, MTOT, KVDIM, DMODEL);
    sgemm_kernel<<<dim3(KVDIM / GBN, MTOT / GBM), blk>>>(x, wv, v, MTOT, KVDIM, DMODEL);
    // attention: 32 query tiles x (2 batches * 16 heads)
    attn_kernel<<<dim3(SEQ / FBR, BATCH * NHEADS), blk, SMEM_BYTES>>>(q, k, v, att);
    // output projection: [4096,2048] @ [2048,2048]
    sgemm_kernel<<<dim3(DMODEL / GBN, MTOT / GBM), blk>>>(att, wo, out, MTOT, DMODEL, DMODEL);
}

// round 5
// speedup vs baseline: 3.1403x; 3.1403x over previous
#include <cuda_runtime.h>
#include <cuda_bf16.h>
#include <math.h>

// Problem constants
#define BATCH    2
#define SEQ      2048
#define DMODEL   2048
#define NHEADS   16
#define NKV      4
#define HDIM     128
#define NREP     4
#define MTOT     (BATCH * SEQ)          // 4096
#define KVDIM    (NKV * HDIM)           // 512

// ---------------- scratch (device globals; no allocation allowed) -----------
__device__ float g_qT[DMODEL * MTOT];    // Q^T: [h*128+d][b*2048+s]  32 MB
__device__ float g_kT[KVDIM * MTOT];     // K^T: [kv*128+d][b*2048+s]  8 MB
__device__ float g_v[MTOT * KVDIM];      // V natural [b*2048+s][kv*128+d]
__device__ float g_att[MTOT * DMODEL];   // attention output, natural

// ---------------- SGEMM: C[M,N] = A[M,K] @ B[K,N], all row-major ------------
#define GBM 128
#define GBN 128
#define GBK 8
#define GTM 8
#define GTN 8

__global__ __launch_bounds__(256, 2)
void sgemm_kernel(const float* __restrict__ A, const float* __restrict__ B,
                  float* __restrict__ C, int M, int N, int K) {
    __shared__ float As[GBK][GBM];
    __shared__ float Bs[GBK][GBN];

    const int bx = blockIdx.x;
    const int by = blockIdx.y;
    const int tid = threadIdx.x;
    const int tx = tid % 16;
    const int ty = tid / 16;

    const float* Ab = A + (size_t)by * GBM * K;
    const float* Bb = B + (size_t)bx * GBN;

    const int aRow = tid >> 1;
    const int aCol = (tid & 1) * 4;
    const int bRow = tid >> 5;
    const int bCol = (tid & 31) * 4;

    float acc[GTM][GTN];
    #pragma unroll
    for (int i = 0; i < GTM; i++)
        #pragma unroll
        for (int j = 0; j < GTN; j++) acc[i][j] = 0.f;

    for (int k0 = 0; k0 < K; k0 += GBK) {
        float4 av = *(const float4*)(Ab + (size_t)aRow * K + k0 + aCol);
        As[aCol + 0][aRow] = av.x;
        As[aCol + 1][aRow] = av.y;
        As[aCol + 2][aRow] = av.z;
        As[aCol + 3][aRow] = av.w;
        float4 bv = *(const float4*)(Bb + (size_t)(k0 + bRow) * N + bCol);
        *(float4*)&Bs[bRow][bCol] = bv;
        __syncthreads();

        #pragma unroll
        for (int kk = 0; kk < GBK; kk++) {
            float a[GTM], b[GTN];
            #pragma unroll
            for (int i = 0; i < GTM; i++) a[i] = As[kk][ty * GTM + i];
            #pragma unroll
            for (int j = 0; j < GTN; j++) b[j] = Bs[kk][tx * GTN + j];
            #pragma unroll
            for (int i = 0; i < GTM; i++)
                #pragma unroll
                for (int j = 0; j < GTN; j++)
                    acc[i][j] += a[i] * b[j];
        }
        __syncthreads();
    }

    float* Cb = C + (size_t)(by * GBM) * N + bx * GBN;
    #pragma unroll
    for (int i = 0; i < GTM; i++) {
        #pragma unroll
        for (int j = 0; j < GTN; j += 4) {
            float4 v;
            v.x = acc[i][j + 0]; v.y = acc[i][j + 1];
            v.z = acc[i][j + 2]; v.w = acc[i][j + 3];
            *(float4*)(Cb + (size_t)(ty * GTM + i) * N + tx * GTN + j) = v;
        }
    }
}

// Same GEMM but stores C transposed: CT[n][m], n in [0,N), m in [0,M).
__global__ __launch_bounds__(256, 2)
void sgemm_t_kernel(const float* __restrict__ A, const float* __restrict__ B,
                    float* __restrict__ CT, int M, int N, int K) {
    __shared__ float As[GBK][GBM];
    __shared__ float Bs[GBK][GBN];

    const int bx = blockIdx.x;
    const int by = blockIdx.y;
    const int tid = threadIdx.x;
    const int tx = tid % 16;
    const int ty = tid / 16;

    const float* Ab = A + (size_t)by * GBM * K;
    const float* Bb = B + (size_t)bx * GBN;

    const int aRow = tid >> 1;
    const int aCol = (tid & 1) * 4;
    const int bRow = tid >> 5;
    const int bCol = (tid & 31) * 4;

    float acc[GTM][GTN];
    #pragma unroll
    for (int i = 0; i < GTM; i++)
        #pragma unroll
        for (int j = 0; j < GTN; j++) acc[i][j] = 0.f;

    for (int k0 = 0; k0 < K; k0 += GBK) {
        float4 av = *(const float4*)(Ab + (size_t)aRow * K + k0 + aCol);
        As[aCol + 0][aRow] = av.x;
        As[aCol + 1][aRow] = av.y;
        As[aCol + 2][aRow] = av.z;
        As[aCol + 3][aRow] = av.w;
        float4 bv = *(const float4*)(Bb + (size_t)(k0 + bRow) * N + bCol);
        *(float4*)&Bs[bRow][bCol] = bv;
        __syncthreads();

        #pragma unroll
        for (int kk = 0; kk < GBK; kk++) {
            float a[GTM], b[GTN];
            #pragma unroll
            for (int i = 0; i < GTM; i++) a[i] = As[kk][ty * GTM + i];
            #pragma unroll
            for (int j = 0; j < GTN; j++) b[j] = Bs[kk][tx * GTN + j];
            #pragma unroll
            for (int i = 0; i < GTM; i++)
                #pragma unroll
                for (int j = 0; j < GTN; j++)
                    acc[i][j] += a[i] * b[j];
        }
        __syncthreads();
    }

    // transposed store: CT[bx*128 + tx*8 + j][by*128 + ty*8 + i]
    #pragma unroll
    for (int j = 0; j < GTN; j++) {
        #pragma unroll
        for (int i4 = 0; i4 < GTM; i4 += 4) {
            float4 v;
            v.x = acc[i4 + 0][j]; v.y = acc[i4 + 1][j];
            v.z = acc[i4 + 2][j]; v.w = acc[i4 + 3][j];
            *(float4*)(CT + (size_t)(bx * GBN + tx * GTN + j) * M
                          + by * GBM + ty * GTM + i4) = v;
        }
    }
}

// ---------------- Flash attention (causal, GQA), register-tiled -------------
// 128 q-rows x 128 kv-cols per tile, 256 threads, 8x8 accumulators/thread.
#define ATP 132                         // padded minor stride (floats)
#define SMEM_FLOATS (3 * 128 * ATP)
#define SMEM_BYTES  (SMEM_FLOATS * 4)   // 202752 B

__global__ __launch_bounds__(256, 1)
void attn_kernel(const float* __restrict__ QT, const float* __restrict__ KT,
                 const float* __restrict__ V, float* __restrict__ O) {
    extern __shared__ float smf[];
    float* Qs  = smf;                   // Q^T tile  [d=128][m=128] pad 132
    float* KVs = smf + 128 * ATP;       // K^T tile [d][n]  OR  V tile [n][d]
    float* Ps  = smf + 2 * 128 * ATP;   // P tile [m=128][k=128] pad 132

    const int tid = threadIdx.x;
    const int tx  = tid & 15;           // 16 along cols
    const int ty  = tid >> 4;           // 16 along rows
    const int bh  = blockIdx.y;
    const int b   = bh >> 4;
    const int h   = bh & 15;
    const int kv  = h >> 2;
    const int bxe = gridDim.x - 1 - blockIdx.x;   // heavy tiles launch first
    const int q0  = bxe * 128;

    // load Q^T tile: rows d, cols m (coalesced along m)
    for (int i = tid; i < 128 * 32; i += 256) {
        int d  = i >> 5;
        int m4 = (i & 31) << 2;
        *(float4*)&Qs[d * ATP + m4] =
            *(const float4*)&QT[(size_t)(h * HDIM + d) * MTOT + b * SEQ + q0 + m4];
    }

    float o[8][8];
    float mrow[8], lrow[8];
    #pragma unroll
    for (int i = 0; i < 8; i++) {
        mrow[i] = -1e30f; lrow[i] = 0.f;
        #pragma unroll
        for (int j = 0; j < 8; j++) o[i][j] = 0.f;
    }

    const float scale = 0.08838834764831845f;  // 1/sqrt(128)

    for (int t = 0; t <= bxe; t++) {
        const int k0 = t * 128;

        __syncthreads();   // previous PV reads of KVs complete
        // load K^T tile: rows d, cols n (kv position)
        for (int i = tid; i < 128 * 32; i += 256) {
            int d  = i >> 5;
            int m4 = (i & 31) << 2;
            *(float4*)&KVs[d * ATP + m4] =
                *(const float4*)&KT[(size_t)(kv * HDIM + d) * MTOT + b * SEQ + k0 + m4];
        }
        __syncthreads();

        // S = Q K^T : 8x8 per thread over 128 k(d)-steps
        float s[8][8];
        #pragma unroll
        for (int i = 0; i < 8; i++)
            #pragma unroll
            for (int j = 0; j < 8; j++) s[i][j] = 0.f;

        #pragma unroll 8
        for (int kk = 0; kk < HDIM; kk++) {
            float4 a0 = *(const float4*)&Qs[kk * ATP + ty * 8];
            float4 a1 = *(const float4*)&Qs[kk * ATP + ty * 8 + 4];
            float4 b0 = *(const float4*)&KVs[kk * ATP + tx * 8];
            float4 b1 = *(const float4*)&KVs[kk * ATP + tx * 8 + 4];
            float a[8] = {a0.x, a0.y, a0.z, a0.w, a1.x, a1.y, a1.z, a1.w};
            float bb[8] = {b0.x, b0.y, b0.z, b0.w, b1.x, b1.y, b1.z, b1.w};
            #pragma unroll
            for (int i = 0; i < 8; i++)
                #pragma unroll
                for (int j = 0; j < 8; j++)
                    s[i][j] += a[i] * bb[j];
        }

        // online softmax (row-wise; rows replicated across the 16 tx threads)
        const bool diag = (t == bxe);
        #pragma unroll
        for (int i = 0; i < 8; i++) {
            const int qg = q0 + ty * 8 + i;
            #pragma unroll
            for (int j = 0; j < 8; j++) {
                float val = s[i][j] * scale;
                if (diag && (k0 + tx * 8 + j > qg)) val = -1e30f;
                s[i][j] = val;
            }
            float mx = s[i][0];
            #pragma unroll
            for (int j = 1; j < 8; j++) mx = fmaxf(mx, s[i][j]);
            mx = fmaxf(mx, __shfl_xor_sync(0xffffffffu, mx, 1));
            mx = fmaxf(mx, __shfl_xor_sync(0xffffffffu, mx, 2));
            mx = fmaxf(mx, __shfl_xor_sync(0xffffffffu, mx, 4));
            mx = fmaxf(mx, __shfl_xor_sync(0xffffffffu, mx, 8));
            float mn   = fmaxf(mrow[i], mx);
            float corr = __expf(mrow[i] - mn);
            float rs = 0.f;
            #pragma unroll
            for (int j = 0; j < 8; j++) {
                float p = __expf(s[i][j] - mn);
                s[i][j] = p;
                rs += p;
            }
            rs += __shfl_xor_sync(0xffffffffu, rs, 1);
            rs += __shfl_xor_sync(0xffffffffu, rs, 2);
            rs += __shfl_xor_sync(0xffffffffu, rs, 4);
            rs += __shfl_xor_sync(0xffffffffu, rs, 8);
            lrow[i] = lrow[i] * corr + rs;
            mrow[i] = mn;
            #pragma unroll
            for (int j = 0; j < 8; j++) o[i][j] *= corr;
        }

        // store P [m][k]
        #pragma unroll
        for (int i = 0; i < 8; i++) {
            #pragma unroll
            for (int j4 = 0; j4 < 8; j4 += 4) {
                float4 v;
                v.x = s[i][j4 + 0]; v.y = s[i][j4 + 1];
                v.z = s[i][j4 + 2]; v.w = s[i][j4 + 3];
                *(float4*)&Ps[(ty * 8 + i) * ATP + tx * 8 + j4] = v;
            }
        }
        __syncthreads();   // P visible; K reads finished

        // load V tile (natural [n][d]) into the K buffer
        for (int i = tid; i < 128 * 32; i += 256) {
            int r  = i >> 5;
            int c4 = (i & 31) << 2;
            *(float4*)&KVs[r * ATP + c4] =
                *(const float4*)&V[(size_t)(b * SEQ + k0 + r) * KVDIM + kv * HDIM + c4];
        }
        __syncthreads();

        // O += P @ V : loop over 128 kv positions, unrolled by 4
        #pragma unroll 2
        for (int k4 = 0; k4 < 128; k4 += 4) {
            float pr[8][4];
            #pragma unroll
            for (int i = 0; i < 8; i++) {
                float4 p4 = *(const float4*)&Ps[(ty * 8 + i) * ATP + k4];
                pr[i][0] = p4.x; pr[i][1] = p4.y; pr[i][2] = p4.z; pr[i][3] = p4.w;
            }
            #pragma unroll
            for (int u = 0; u < 4; u++) {
                float4 v0 = *(const float4*)&KVs[(k4 + u) * ATP + tx * 8];
                float4 v1 = *(const float4*)&KVs[(k4 + u) * ATP + tx * 8 + 4];
                float vv[8] = {v0.x, v0.y, v0.z, v0.w, v1.x, v1.y, v1.z, v1.w};
                #pragma unroll
                for (int i = 0; i < 8; i++) {
                    float p = pr[i][u];
                    #pragma unroll
                    for (int j = 0; j < 8; j++) o[i][j] += p * vv[j];
                }
            }
        }
    }

    // epilogue: normalize and store
    #pragma unroll
    for (int i = 0; i < 8; i++) {
        const float inv = 1.f / lrow[i];
        float* outp = O + (size_t)(b * SEQ + q0 + ty * 8 + i) * DMODEL
                        + h * HDIM + tx * 8;
        #pragma unroll
        for (int j4 = 0; j4 < 8; j4 += 4) {
            float4 v;
            v.x = o[i][j4 + 0] * inv; v.y = o[i][j4 + 1] * inv;
            v.z = o[i][j4 + 2] * inv; v.w = o[i][j4 + 3] * inv;
            *(float4*)(outp + j4) = v;
        }
    }
}

// ---------------- launch -----------------------------------------------------
extern "C" void kernel_launch(void* const* d_in, const int* in_sizes, int n_in,
                              void* d_out, int out_size) {
    const float* x  = (const float*)d_in[0];
    const float* wq = (const float*)d_in[1];
    const float* wk = (const float*)d_in[2];
    const float* wv = (const float*)d_in[3];
    const float* wo = (const float*)d_in[4];
    float* out = (float*)d_out;

    float *qT, *kT, *v, *att;
    cudaGetSymbolAddress((void**)&qT,  g_qT);
    cudaGetSymbolAddress((void**)&kT,  g_kT);
    cudaGetSymbolAddress((void**)&v,   g_v);
    cudaGetSymbolAddress((void**)&att, g_att);

    cudaFuncSetAttribute(attn_kernel, cudaFuncAttributeMaxDynamicSharedMemorySize, SMEM_BYTES);

    dim3 blk(256);
    // Q projection -> transposed layout [2048][4096]
    sgemm_t_kernel<<<dim3(DMODEL / GBN, MTOT / GBM), blk>>>(x, wq, qT, MTOT, DMODEL, DMODEL);
    // K projection -> transposed layout [512][4096]
    sgemm_t_kernel<<<dim3(KVDIM / GBN, MTOT / GBM), blk>>>(x, wk, kT, MTOT, KVDIM, DMODEL);
    // V projection -> natural layout
    sgemm_kernel<<<dim3(KVDIM / GBN, MTOT / GBM), blk>>>(x, wv, v, MTOT, KVDIM, DMODEL);
    // attention: 16 q-tiles x 32 (batch,head)
    attn_kernel<<<dim3(SEQ / 128, BATCH * NHEADS), blk, SMEM_BYTES>>>(qT, kT, v, att);
    // output projection
    sgemm_kernel<<<dim3(DMODEL / GBN, MTOT / GBM), blk>>>(att, wo, out, MTOT, DMODEL, DMODEL);
}

// round 6
// speedup vs baseline: 6.1538x; 1.9596x over previous
#include <cuda_runtime.h>
#include <cuda_bf16.h>
#include <math.h>
#include <stdint.h>

// Problem constants
#define BATCH    2
#define SEQ      2048
#define DMODEL   2048
#define NHEADS   16
#define NKV      4
#define HDIM     128
#define NREP     4
#define MTOT     (BATCH * SEQ)          // 4096
#define KVDIM    (NKV * HDIM)           // 512

// ---------------- scratch (device globals; no allocation allowed) -----------
__device__ float g_qT[DMODEL * MTOT];    // Q^T: [h*128+d][b*2048+s]  32 MB
__device__ float g_kT[KVDIM * MTOT];     // K^T: [kv*128+d][b*2048+s]  8 MB
__device__ float g_v[MTOT * KVDIM];      // V natural [b*2048+s][kv*128+d]
__device__ float g_att[MTOT * DMODEL];   // attention output, natural

// ---------------- tf32 tensor-core GEMM -------------------------------------
// C[M,N] = A[M,K] @ B[K,N], row-major. 128x128x16 CTA tile, 256 threads.
// Warp w: warp_m = (w&3)*32 rows, warp_n = (w>>2)*64 cols -> 2x8 m16n8k8 frags.
// Smem layout [k][m] / [k][n], stride 136 floats: compute-side LDS conflict-free.
#define AP 136
#define KLOOP_SMEM   (2 * 2 * 16 * AP * 4)      // 34816 B (A+B double buffered)
#define TRANS_SMEM   (128 * 129 * 4)            // 66048 B (C transpose staging)

__device__ __forceinline__ uint32_t f2tf32(float x) {
    uint32_t u;
    asm("cvt.rna.tf32.f32 %0, %1;" : "=r"(u) : "f"(x));
    return u;
}

__device__ __forceinline__ void mma_tf32(float c[4], const uint32_t a[4],
                                         const uint32_t b[2]) {
    asm volatile(
        "mma.sync.aligned.m16n8k8.row.col.f32.tf32.tf32.f32 "
        "{%0,%1,%2,%3}, {%4,%5,%6,%7}, {%8,%9}, {%0,%1,%2,%3};\n"
        : "+f"(c[0]), "+f"(c[1]), "+f"(c[2]), "+f"(c[3])
        : "r"(a[0]), "r"(a[1]), "r"(a[2]), "r"(a[3]), "r"(b[0]), "r"(b[1]));
}

template <bool TRANSC>
__global__ __launch_bounds__(256)
void tf32_gemm(const float* __restrict__ A, const float* __restrict__ B,
               float* __restrict__ C, int M, int N, int K) {
    extern __shared__ float sh[];
    float* As = sh;                   // 2 bufs x 16 x AP   ([k][m])
    float* Bs = sh + 2 * 16 * AP;     // 2 bufs x 16 x AP   ([k][n])

    const int tid  = threadIdx.x;
    const int lane = tid & 31;
    const int g    = lane >> 2;       // 0..7
    const int t    = lane & 3;        // 0..3
    const int warp = tid >> 5;
    const int wm   = (warp & 3) * 32;
    const int wn   = (warp >> 2) * 64;
    const int bx   = blockIdx.x;
    const int by   = blockIdx.y;

    // global load anchors
    const int am  = tid >> 2;               // 0..63 (+64 for second elem)
    const int ac4 = (tid & 3) * 4;
    const int brw = tid >> 5;               // 0..7 (+8 for second elem)
    const int bn4 = (tid & 31) * 4;
    const float* Ag = A + (size_t)(by * 128 + am) * K + ac4;
    const float* Bg = B + (size_t)brw * N + bx * 128 + bn4;

    float c[2][8][4];
    #pragma unroll
    for (int mt = 0; mt < 2; mt++)
        #pragma unroll
        for (int nt = 0; nt < 8; nt++)
            #pragma unroll
            for (int r = 0; r < 4; r++) c[mt][nt][r] = 0.f;

    float4 pa0, pa1, pb0, pb1;
    pa0 = *(const float4*)(Ag);
    pa1 = *(const float4*)(Ag + (size_t)64 * K);
    pb0 = *(const float4*)(Bg);
    pb1 = *(const float4*)(Bg + (size_t)8 * N);

    // stash tile 0 into buffer 0
    {
        float* Ab = As;
        float* Bb = Bs;
        const float av0[4] = {pa0.x, pa0.y, pa0.z, pa0.w};
        const float av1[4] = {pa1.x, pa1.y, pa1.z, pa1.w};
        #pragma unroll
        for (int j = 0; j < 4; j++) {
            Ab[(ac4 + j) * AP + am]      = __uint_as_float(f2tf32(av0[j]));
            Ab[(ac4 + j) * AP + am + 64] = __uint_as_float(f2tf32(av1[j]));
        }
        uint4 u0 = {f2tf32(pb0.x), f2tf32(pb0.y), f2tf32(pb0.z), f2tf32(pb0.w)};
        uint4 u1 = {f2tf32(pb1.x), f2tf32(pb1.y), f2tf32(pb1.z), f2tf32(pb1.w)};
        *(uint4*)&Bb[brw * AP + bn4]       = u0;
        *(uint4*)&Bb[(brw + 8) * AP + bn4] = u1;
    }
    __syncthreads();

    const int NT = K >> 4;
    for (int kt = 0; kt < NT; kt++) {
        if (kt + 1 < NT) {
            const float* Ap = Ag + (kt + 1) * 16;
            const float* Bp = Bg + (size_t)(kt + 1) * 16 * N;
            pa0 = *(const float4*)(Ap);
            pa1 = *(const float4*)(Ap + (size_t)64 * K);
            pb0 = *(const float4*)(Bp);
            pb1 = *(const float4*)(Bp + (size_t)8 * N);
        }

        const uint32_t* Au = (const uint32_t*)(As + (kt & 1) * 16 * AP);
        const uint32_t* Bu = (const uint32_t*)(Bs + (kt & 1) * 16 * AP);

        #pragma unroll
        for (int s = 0; s < 2; s++) {
            const int kb = s * 8;
            uint32_t a[2][4], bf[8][2];
            #pragma unroll
            for (int mt = 0; mt < 2; mt++) {
                const int m0 = wm + mt * 16 + g;
                a[mt][0] = Au[(kb + t) * AP + m0];
                a[mt][1] = Au[(kb + t) * AP + m0 + 8];
                a[mt][2] = Au[(kb + t + 4) * AP + m0];
                a[mt][3] = Au[(kb + t + 4) * AP + m0 + 8];
            }
            #pragma unroll
            for (int nt = 0; nt < 8; nt++) {
                const int n0 = wn + nt * 8 + g;
                bf[nt][0] = Bu[(kb + t) * AP + n0];
                bf[nt][1] = Bu[(kb + t + 4) * AP + n0];
            }
            #pragma unroll
            for (int mt = 0; mt < 2; mt++)
                #pragma unroll
                for (int nt = 0; nt < 8; nt++)
                    mma_tf32(c[mt][nt], a[mt], bf[nt]);
        }

        if (kt + 1 < NT) {
            float* Ab = As + ((kt + 1) & 1) * 16 * AP;
            float* Bb = Bs + ((kt + 1) & 1) * 16 * AP;
            const float av0[4] = {pa0.x, pa0.y, pa0.z, pa0.w};
            const float av1[4] = {pa1.x, pa1.y, pa1.z, pa1.w};
            #pragma unroll
            for (int j = 0; j < 4; j++) {
                Ab[(ac4 + j) * AP + am]      = __uint_as_float(f2tf32(av0[j]));
                Ab[(ac4 + j) * AP + am + 64] = __uint_as_float(f2tf32(av1[j]));
            }
            uint4 u0 = {f2tf32(pb0.x), f2tf32(pb0.y), f2tf32(pb0.z), f2tf32(pb0.w)};
            uint4 u1 = {f2tf32(pb1.x), f2tf32(pb1.y), f2tf32(pb1.z), f2tf32(pb1.w)};
            *(uint4*)&Bb[brw * AP + bn4]       = u0;
            *(uint4*)&Bb[(brw + 8) * AP + bn4] = u1;
            __syncthreads();
        }
    }

    if (!TRANSC) {
        // natural store: per frag, two 64-bit stores
        #pragma unroll
        for (int mt = 0; mt < 2; mt++) {
            #pragma unroll
            for (int nt = 0; nt < 8; nt++) {
                const int row = by * 128 + wm + mt * 16 + g;
                const int col = bx * 128 + wn + nt * 8 + t * 2;
                float2 v01 = make_float2(c[mt][nt][0], c[mt][nt][1]);
                float2 v23 = make_float2(c[mt][nt][2], c[mt][nt][3]);
                *(float2*)&C[(size_t)row * N + col]       = v01;
                *(float2*)&C[(size_t)(row + 8) * N + col] = v23;
            }
        }
    } else {
        // transposed store CT[n][m]: stage through smem for coalescing
        __syncthreads();                 // all compute done before overlaying
        float* Cs = sh;                  // 128 x 129
        #pragma unroll
        for (int mt = 0; mt < 2; mt++) {
            #pragma unroll
            for (int nt = 0; nt < 8; nt++) {
                const int r  = wm + mt * 16 + g;
                const int cl = wn + nt * 8 + t * 2;
                Cs[r * 129 + cl]           = c[mt][nt][0];
                Cs[r * 129 + cl + 1]       = c[mt][nt][1];
                Cs[(r + 8) * 129 + cl]     = c[mt][nt][2];
                Cs[(r + 8) * 129 + cl + 1] = c[mt][nt][3];
            }
        }
        __syncthreads();
        #pragma unroll
        for (int r = 0; r < 16; r++) {
            const int i  = tid + 256 * r;
            const int n  = i >> 5;
            const int m4 = (i & 31) << 2;
            float4 v;
            v.x = Cs[(m4 + 0) * 129 + n];
            v.y = Cs[(m4 + 1) * 129 + n];
            v.z = Cs[(m4 + 2) * 129 + n];
            v.w = Cs[(m4 + 3) * 129 + n];
            *(float4*)&C[(size_t)(bx * 128 + n) * M + by * 128 + m4] = v;
        }
    }
}

// ---------------- Flash attention (causal, GQA), register-tiled -------------
// 128 q-rows x 128 kv-cols per tile, 256 threads, 8x8 accumulators/thread.
#define ATP 132                         // padded minor stride (floats)
#define SMEM_FLOATS (3 * 128 * ATP)
#define SMEM_BYTES  (SMEM_FLOATS * 4)   // 202752 B

__global__ __launch_bounds__(256, 1)
void attn_kernel(const float* __restrict__ QT, const float* __restrict__ KT,
                 const float* __restrict__ V, float* __restrict__ O) {
    extern __shared__ float smf[];
    float* Qs  = smf;                   // Q^T tile  [d=128][m=128] pad 132
    float* KVs = smf + 128 * ATP;       // K^T tile [d][n]  OR  V tile [n][d]
    float* Ps  = smf + 2 * 128 * ATP;   // P tile [m=128][k=128] pad 132

    const int tid = threadIdx.x;
    const int tx  = tid & 15;           // 16 along cols
    const int ty  = tid >> 4;           // 16 along rows
    const int bh  = blockIdx.y;
    const int b   = bh >> 4;
    const int h   = bh & 15;
    const int kv  = h >> 2;
    const int bxe = gridDim.x - 1 - blockIdx.x;   // heavy tiles launch first
    const int q0  = bxe * 128;

    // load Q^T tile: rows d, cols m (coalesced along m)
    for (int i = tid; i < 128 * 32; i += 256) {
        int d  = i >> 5;
        int m4 = (i & 31) << 2;
        *(float4*)&Qs[d * ATP + m4] =
            *(const float4*)&QT[(size_t)(h * HDIM + d) * MTOT + b * SEQ + q0 + m4];
    }

    float o[8][8];
    float mrow[8], lrow[8];
    #pragma unroll
    for (int i = 0; i < 8; i++) {
        mrow[i] = -1e30f; lrow[i] = 0.f;
        #pragma unroll
        for (int j = 0; j < 8; j++) o[i][j] = 0.f;
    }

    const float scale = 0.08838834764831845f;  // 1/sqrt(128)

    for (int t = 0; t <= bxe; t++) {
        const int k0 = t * 128;

        __syncthreads();   // previous PV reads of KVs complete
        // load K^T tile: rows d, cols n (kv position)
        for (int i = tid; i < 128 * 32; i += 256) {
            int d  = i >> 5;
            int m4 = (i & 31) << 2;
            *(float4*)&KVs[d * ATP + m4] =
                *(const float4*)&KT[(size_t)(kv * HDIM + d) * MTOT + b * SEQ + k0 + m4];
        }
        __syncthreads();

        // S = Q K^T : 8x8 per thread over 128 k(d)-steps
        float s[8][8];
        #pragma unroll
        for (int i = 0; i < 8; i++)
            #pragma unroll
            for (int j = 0; j < 8; j++) s[i][j] = 0.f;

        #pragma unroll 8
        for (int kk = 0; kk < HDIM; kk++) {
            float4 a0 = *(const float4*)&Qs[kk * ATP + ty * 8];
            float4 a1 = *(const float4*)&Qs[kk * ATP + ty * 8 + 4];
            float4 b0 = *(const float4*)&KVs[kk * ATP + tx * 8];
            float4 b1 = *(const float4*)&KVs[kk * ATP + tx * 8 + 4];
            float a[8] = {a0.x, a0.y, a0.z, a0.w, a1.x, a1.y, a1.z, a1.w};
            float bb[8] = {b0.x, b0.y, b0.z, b0.w, b1.x, b1.y, b1.z, b1.w};
            #pragma unroll
            for (int i = 0; i < 8; i++)
                #pragma unroll
                for (int j = 0; j < 8; j++)
                    s[i][j] += a[i] * bb[j];
        }

        // online softmax (row-wise; rows replicated across the 16 tx threads)
        const bool diag = (t == bxe);
        #pragma unroll
        for (int i = 0; i < 8; i++) {
            const int qg = q0 + ty * 8 + i;
            #pragma unroll
            for (int j = 0; j < 8; j++) {
                float val = s[i][j] * scale;
                if (diag && (k0 + tx * 8 + j > qg)) val = -1e30f;
                s[i][j] = val;
            }
            float mx = s[i][0];
            #pragma unroll
            for (int j = 1; j < 8; j++) mx = fmaxf(mx, s[i][j]);
            mx = fmaxf(mx, __shfl_xor_sync(0xffffffffu, mx, 1));
            mx = fmaxf(mx, __shfl_xor_sync(0xffffffffu, mx, 2));
            mx = fmaxf(mx, __shfl_xor_sync(0xffffffffu, mx, 4));
            mx = fmaxf(mx, __shfl_xor_sync(0xffffffffu, mx, 8));
            float mn   = fmaxf(mrow[i], mx);
            float corr = __expf(mrow[i] - mn);
            float rs = 0.f;
            #pragma unroll
            for (int j = 0; j < 8; j++) {
                float p = __expf(s[i][j] - mn);
                s[i][j] = p;
                rs += p;
            }
            rs += __shfl_xor_sync(0xffffffffu, rs, 1);
            rs += __shfl_xor_sync(0xffffffffu, rs, 2);
            rs += __shfl_xor_sync(0xffffffffu, rs, 4);
            rs += __shfl_xor_sync(0xffffffffu, rs, 8);
            lrow[i] = lrow[i] * corr + rs;
            mrow[i] = mn;
            #pragma unroll
            for (int j = 0; j < 8; j++) o[i][j] *= corr;
        }

        // store P [m][k]
        #pragma unroll
        for (int i = 0; i < 8; i++) {
            #pragma unroll
            for (int j4 = 0; j4 < 8; j4 += 4) {
                float4 v;
                v.x = s[i][j4 + 0]; v.y = s[i][j4 + 1];
                v.z = s[i][j4 + 2]; v.w = s[i][j4 + 3];
                *(float4*)&Ps[(ty * 8 + i) * ATP + tx * 8 + j4] = v;
            }
        }
        __syncthreads();   // P visible; K reads finished

        // load V tile (natural [n][d]) into the K buffer
        for (int i = tid; i < 128 * 32; i += 256) {
            int r  = i >> 5;
            int c4 = (i & 31) << 2;
            *(float4*)&KVs[r * ATP + c4] =
                *(const float4*)&V[(size_t)(b * SEQ + k0 + r) * KVDIM + kv * HDIM + c4];
        }
        __syncthreads();

        // O += P @ V : loop over 128 kv positions, unrolled by 4
        #pragma unroll 2
        for (int k4 = 0; k4 < 128; k4 += 4) {
            float pr[8][4];
            #pragma unroll
            for (int i = 0; i < 8; i++) {
                float4 p4 = *(const float4*)&Ps[(ty * 8 + i) * ATP + k4];
                pr[i][0] = p4.x; pr[i][1] = p4.y; pr[i][2] = p4.z; pr[i][3] = p4.w;
            }
            #pragma unroll
            for (int u = 0; u < 4; u++) {
                float4 v0 = *(const float4*)&KVs[(k4 + u) * ATP + tx * 8];
                float4 v1 = *(const float4*)&KVs[(k4 + u) * ATP + tx * 8 + 4];
                float vv[8] = {v0.x, v0.y, v0.z, v0.w, v1.x, v1.y, v1.z, v1.w};
                #pragma unroll
                for (int i = 0; i < 8; i++) {
                    float p = pr[i][u];
                    #pragma unroll
                    for (int j = 0; j < 8; j++) o[i][j] += p * vv[j];
                }
            }
        }
    }

    // epilogue: normalize and store
    #pragma unroll
    for (int i = 0; i < 8; i++) {
        const float inv = 1.f / lrow[i];
        float* outp = O + (size_t)(b * SEQ + q0 + ty * 8 + i) * DMODEL
                        + h * HDIM + tx * 8;
        #pragma unroll
        for (int j4 = 0; j4 < 8; j4 += 4) {
            float4 v;
            v.x = o[i][j4 + 0] * inv; v.y = o[i][j4 + 1] * inv;
            v.z = o[i][j4 + 2] * inv; v.w = o[i][j4 + 3] * inv;
            *(float4*)(outp + j4) = v;
        }
    }
}

// ---------------- launch -----------------------------------------------------
extern "C" void kernel_launch(void* const* d_in, const int* in_sizes, int n_in,
                              void* d_out, int out_size) {
    const float* x  = (const float*)d_in[0];
    const float* wq = (const float*)d_in[1];
    const float* wk = (const float*)d_in[2];
    const float* wv = (const float*)d_in[3];
    const float* wo = (const float*)d_in[4];
    float* out = (float*)d_out;

    float *qT, *kT, *v, *att;
    cudaGetSymbolAddress((void**)&qT,  g_qT);
    cudaGetSymbolAddress((void**)&kT,  g_kT);
    cudaGetSymbolAddress((void**)&v,   g_v);
    cudaGetSymbolAddress((void**)&att, g_att);

    cudaFuncSetAttribute(attn_kernel, cudaFuncAttributeMaxDynamicSharedMemorySize, SMEM_BYTES);
    cudaFuncSetAttribute(tf32_gemm<true>,  cudaFuncAttributeMaxDynamicSharedMemorySize, TRANS_SMEM);
    cudaFuncSetAttribute(tf32_gemm<false>, cudaFuncAttributeMaxDynamicSharedMemorySize, KLOOP_SMEM);

    dim3 blk(256);
    // Q projection -> transposed layout qT[2048][4096]
    tf32_gemm<true><<<dim3(DMODEL / 128, MTOT / 128), blk, TRANS_SMEM>>>(x, wq, qT, MTOT, DMODEL, DMODEL);
    // K projection -> transposed layout kT[512][4096]
    tf32_gemm<true><<<dim3(KVDIM / 128, MTOT / 128), blk, TRANS_SMEM>>>(x, wk, kT, MTOT, KVDIM, DMODEL);
    // V projection -> natural layout
    tf32_gemm<false><<<dim3(KVDIM / 128, MTOT / 128), blk, KLOOP_SMEM>>>(x, wv, v, MTOT, KVDIM, DMODEL);
    // attention: 16 q-tiles x 32 (batch,head)
    attn_kernel<<<dim3(SEQ / 128, BATCH * NHEADS), blk, SMEM_BYTES>>>(qT, kT, v, att);
    // output projection
    tf32_gemm<false><<<dim3(DMODEL / 128, MTOT / 128), blk, KLOOP_SMEM>>>(att, wo, out, MTOT, DMODEL, DMODEL);
}

// round 7
// speedup vs baseline: 7.8811x; 1.2807x over previous
#include <cuda_runtime.h>
#include <cuda_bf16.h>
#include <math.h>
#include <stdint.h>

// Problem constants
#define BATCH    2
#define SEQ      2048
#define DMODEL   2048
#define NHEADS   16
#define NKV      4
#define HDIM     128
#define NREP     4
#define MTOT     (BATCH * SEQ)          // 4096
#define KVDIM    (NKV * HDIM)           // 512

// ---------------- scratch (device globals; no allocation allowed) -----------
__device__ float g_qT[DMODEL * MTOT];    // Q^T: [h*128+d][b*2048+s]
__device__ float g_kT[KVDIM * MTOT];     // K^T: [kv*128+d][b*2048+s]
__device__ float g_v[MTOT * KVDIM];      // V natural [b*2048+s][kv*128+d]
__device__ float g_att[MTOT * DMODEL];   // attention output, natural

// ---------------- tf32 helpers ----------------------------------------------
__device__ __forceinline__ uint32_t f2tf32(float x) {
    uint32_t u;
    asm("cvt.rna.tf32.f32 %0, %1;" : "=r"(u) : "f"(x));
    return u;
}

__device__ __forceinline__ void mma_tf32(float c[4], const uint32_t a[4],
                                         const uint32_t b[2]) {
    asm volatile(
        "mma.sync.aligned.m16n8k8.row.col.f32.tf32.tf32.f32 "
        "{%0,%1,%2,%3}, {%4,%5,%6,%7}, {%8,%9}, {%0,%1,%2,%3};\n"
        : "+f"(c[0]), "+f"(c[1]), "+f"(c[2]), "+f"(c[3])
        : "r"(a[0]), "r"(a[1]), "r"(a[2]), "r"(a[3]), "r"(b[0]), "r"(b[1]));
}

// ---------------- tf32 tensor-core projection GEMM --------------------------
#define AP 136
#define KLOOP_SMEM   (2 * 2 * 16 * AP * 4)      // 34816 B
#define TRANS_SMEM   (128 * 129 * 4)            // 66048 B

template <bool TRANSC>
__global__ __launch_bounds__(256)
void tf32_gemm(const float* __restrict__ A, const float* __restrict__ B,
               float* __restrict__ C, int M, int N, int K) {
    extern __shared__ float sh[];
    float* As = sh;
    float* Bs = sh + 2 * 16 * AP;

    const int tid  = threadIdx.x;
    const int lane = tid & 31;
    const int g    = lane >> 2;
    const int t    = lane & 3;
    const int warp = tid >> 5;
    const int wm   = (warp & 3) * 32;
    const int wn   = (warp >> 2) * 64;
    const int bx   = blockIdx.x;
    const int by   = blockIdx.y;

    const int am  = tid >> 2;
    const int ac4 = (tid & 3) * 4;
    const int brw = tid >> 5;
    const int bn4 = (tid & 31) * 4;
    const float* Ag = A + (size_t)(by * 128 + am) * K + ac4;
    const float* Bg = B + (size_t)brw * N + bx * 128 + bn4;

    float c[2][8][4];
    #pragma unroll
    for (int mt = 0; mt < 2; mt++)
        #pragma unroll
        for (int nt = 0; nt < 8; nt++)
            #pragma unroll
            for (int r = 0; r < 4; r++) c[mt][nt][r] = 0.f;

    float4 pa0, pa1, pb0, pb1;
    pa0 = *(const float4*)(Ag);
    pa1 = *(const float4*)(Ag + (size_t)64 * K);
    pb0 = *(const float4*)(Bg);
    pb1 = *(const float4*)(Bg + (size_t)8 * N);

    {
        float* Ab = As;
        float* Bb = Bs;
        const float av0[4] = {pa0.x, pa0.y, pa0.z, pa0.w};
        const float av1[4] = {pa1.x, pa1.y, pa1.z, pa1.w};
        #pragma unroll
        for (int j = 0; j < 4; j++) {
            Ab[(ac4 + j) * AP + am]      = __uint_as_float(f2tf32(av0[j]));
            Ab[(ac4 + j) * AP + am + 64] = __uint_as_float(f2tf32(av1[j]));
        }
        uint4 u0 = {f2tf32(pb0.x), f2tf32(pb0.y), f2tf32(pb0.z), f2tf32(pb0.w)};
        uint4 u1 = {f2tf32(pb1.x), f2tf32(pb1.y), f2tf32(pb1.z), f2tf32(pb1.w)};
        *(uint4*)&Bb[brw * AP + bn4]       = u0;
        *(uint4*)&Bb[(brw + 8) * AP + bn4] = u1;
    }
    __syncthreads();

    const int NT = K >> 4;
    for (int kt = 0; kt < NT; kt++) {
        if (kt + 1 < NT) {
            const float* Ap = Ag + (kt + 1) * 16;
            const float* Bp = Bg + (size_t)(kt + 1) * 16 * N;
            pa0 = *(const float4*)(Ap);
            pa1 = *(const float4*)(Ap + (size_t)64 * K);
            pb0 = *(const float4*)(Bp);
            pb1 = *(const float4*)(Bp + (size_t)8 * N);
        }

        const uint32_t* Au = (const uint32_t*)(As + (kt & 1) * 16 * AP);
        const uint32_t* Bu = (const uint32_t*)(Bs + (kt & 1) * 16 * AP);

        #pragma unroll
        for (int s = 0; s < 2; s++) {
            const int kb = s * 8;
            uint32_t a[2][4], bf[8][2];
            #pragma unroll
            for (int mt = 0; mt < 2; mt++) {
                const int m0 = wm + mt * 16 + g;
                a[mt][0] = Au[(kb + t) * AP + m0];
                a[mt][1] = Au[(kb + t) * AP + m0 + 8];
                a[mt][2] = Au[(kb + t + 4) * AP + m0];
                a[mt][3] = Au[(kb + t + 4) * AP + m0 + 8];
            }
            #pragma unroll
            for (int nt = 0; nt < 8; nt++) {
                const int n0 = wn + nt * 8 + g;
                bf[nt][0] = Bu[(kb + t) * AP + n0];
                bf[nt][1] = Bu[(kb + t + 4) * AP + n0];
            }
            #pragma unroll
            for (int mt = 0; mt < 2; mt++)
                #pragma unroll
                for (int nt = 0; nt < 8; nt++)
                    mma_tf32(c[mt][nt], a[mt], bf[nt]);
        }

        if (kt + 1 < NT) {
            float* Ab = As + ((kt + 1) & 1) * 16 * AP;
            float* Bb = Bs + ((kt + 1) & 1) * 16 * AP;
            const float av0[4] = {pa0.x, pa0.y, pa0.z, pa0.w};
            const float av1[4] = {pa1.x, pa1.y, pa1.z, pa1.w};
            #pragma unroll
            for (int j = 0; j < 4; j++) {
                Ab[(ac4 + j) * AP + am]      = __uint_as_float(f2tf32(av0[j]));
                Ab[(ac4 + j) * AP + am + 64] = __uint_as_float(f2tf32(av1[j]));
            }
            uint4 u0 = {f2tf32(pb0.x), f2tf32(pb0.y), f2tf32(pb0.z), f2tf32(pb0.w)};
            uint4 u1 = {f2tf32(pb1.x), f2tf32(pb1.y), f2tf32(pb1.z), f2tf32(pb1.w)};
            *(uint4*)&Bb[brw * AP + bn4]       = u0;
            *(uint4*)&Bb[(brw + 8) * AP + bn4] = u1;
            __syncthreads();
        }
    }

    if (!TRANSC) {
        #pragma unroll
        for (int mt = 0; mt < 2; mt++) {
            #pragma unroll
            for (int nt = 0; nt < 8; nt++) {
                const int row = by * 128 + wm + mt * 16 + g;
                const int col = bx * 128 + wn + nt * 8 + t * 2;
                float2 v01 = make_float2(c[mt][nt][0], c[mt][nt][1]);
                float2 v23 = make_float2(c[mt][nt][2], c[mt][nt][3]);
                *(float2*)&C[(size_t)row * N + col]       = v01;
                *(float2*)&C[(size_t)(row + 8) * N + col] = v23;
            }
        }
    } else {
        __syncthreads();
        float* Cs = sh;   // 128 x 129
        #pragma unroll
        for (int mt = 0; mt < 2; mt++) {
            #pragma unroll
            for (int nt = 0; nt < 8; nt++) {
                const int r  = wm + mt * 16 + g;
                const int cl = wn + nt * 8 + t * 2;
                Cs[r * 129 + cl]           = c[mt][nt][0];
                Cs[r * 129 + cl + 1]       = c[mt][nt][1];
                Cs[(r + 8) * 129 + cl]     = c[mt][nt][2];
                Cs[(r + 8) * 129 + cl + 1] = c[mt][nt][3];
            }
        }
        __syncthreads();
        #pragma unroll
        for (int r = 0; r < 16; r++) {
            const int i  = tid + 256 * r;
            const int n  = i >> 5;
            const int m4 = (i & 31) << 2;
            float4 v;
            v.x = Cs[(m4 + 0) * 129 + n];
            v.y = Cs[(m4 + 1) * 129 + n];
            v.z = Cs[(m4 + 2) * 129 + n];
            v.w = Cs[(m4 + 3) * 129 + n];
            *(float4*)&C[(size_t)(bx * 128 + n) * M + by * 128 + m4] = v;
        }
    }
}

// ---------------- Tensor-core flash attention (causal, GQA) -----------------
// q tile 128 rows per CTA; kv tiles of 64. 8 warps, each 16 q-rows x 64 cols.
// S = QK^T via split tf32 (3 MMAs, ~fp32 accurate); PV via single tf32.
// Smem (floats):
#define QP 136                              // Q plane pad  (mod 32 == 8)
#define KP 72                               // K plane pad  (mod 32 == 8)
#define VP 136                              // V pad        (mod 32 == 8)
#define PP 68                               // P pad        (mod 32 == 4)
#define SM_QHI 0
#define SM_QLO (128 * QP)                   // 17408
#define SM_KHI (2 * 128 * QP)               // 34816
#define SM_KLO (SM_KHI + 128 * KP)          // 44032
#define SM_V   SM_KHI                       // overlays K (sequenced)
#define SM_P   (SM_KHI + 64 * VP)           // 43520
#define ATT_SMEM_FLOATS (SM_KHI + 2 * 128 * KP)   // 53248
#define ATT_SMEM (ATT_SMEM_FLOATS * 4)            // 212992 B

__global__ __launch_bounds__(256, 1)
void attn_kernel(const float* __restrict__ QT, const float* __restrict__ KT,
                 const float* __restrict__ V, float* __restrict__ O) {
    extern __shared__ float smf[];
    float* Qhi = smf + SM_QHI;
    float* Qlo = smf + SM_QLO;
    float* Khi = smf + SM_KHI;
    float* Klo = smf + SM_KLO;
    float* Vs  = smf + SM_V;
    float* Ps  = smf + SM_P;

    const int tid  = threadIdx.x;
    const int lane = tid & 31;
    const int g    = lane >> 2;         // 0..7
    const int lt   = lane & 3;          // 0..3
    const int warp = tid >> 5;          // 0..7
    const int m0   = warp * 16;         // warp's q-row block
    const int bh   = blockIdx.y;
    const int b    = bh >> 4;
    const int h    = bh & 15;
    const int kvh  = h >> 2;
    const int bxe  = gridDim.x - 1 - blockIdx.x;   // heavy tiles first
    const int q0   = bxe * 128;

    // ---- load Q tile [d=128][m=128], split into hi/lo tf32 planes ----
    for (int i = tid; i < 128 * 32; i += 256) {
        int d  = i >> 5;
        int m4 = (i & 31) << 2;
        float4 q = *(const float4*)&QT[(size_t)(h * HDIM + d) * MTOT + b * SEQ + q0 + m4];
        float4 hi, lo;
        hi.x = __uint_as_float(f2tf32(q.x)); lo.x = __uint_as_float(f2tf32(q.x - hi.x));
        hi.y = __uint_as_float(f2tf32(q.y)); lo.y = __uint_as_float(f2tf32(q.y - hi.y));
        hi.z = __uint_as_float(f2tf32(q.z)); lo.z = __uint_as_float(f2tf32(q.z - hi.z));
        hi.w = __uint_as_float(f2tf32(q.w)); lo.w = __uint_as_float(f2tf32(q.w - hi.w));
        *(float4*)&Qhi[d * QP + m4] = hi;
        *(float4*)&Qlo[d * QP + m4] = lo;
    }

    float m_s[2] = {-1e30f, -1e30f};
    float l_s[2] = {0.f, 0.f};
    float o[16][4];
    #pragma unroll
    for (int nt = 0; nt < 16; nt++)
        #pragma unroll
        for (int r = 0; r < 4; r++) o[nt][r] = 0.f;

    const float scale = 0.08838834764831845f;   // 1/sqrt(128)
    const int ntk = 2 * (bxe + 1);
    const int row0 = q0 + m0 + g;               // global q row (and +8)

    for (int tt = 0; tt < ntk; tt++) {
        const int k0 = tt * 64;
        __syncthreads();     // prev PV done reading Vs/Ps before K overwrite

        // ---- load K tile [d=128][n=64], split hi/lo ----
        for (int i = tid; i < 128 * 16; i += 256) {
            int d  = i >> 4;
            int n4 = (i & 15) << 2;
            float4 k = *(const float4*)&KT[(size_t)(kvh * HDIM + d) * MTOT + b * SEQ + k0 + n4];
            float4 hi, lo;
            hi.x = __uint_as_float(f2tf32(k.x)); lo.x = __uint_as_float(f2tf32(k.x - hi.x));
            hi.y = __uint_as_float(f2tf32(k.y)); lo.y = __uint_as_float(f2tf32(k.y - hi.y));
            hi.z = __uint_as_float(f2tf32(k.z)); lo.z = __uint_as_float(f2tf32(k.z - hi.z));
            hi.w = __uint_as_float(f2tf32(k.w)); lo.w = __uint_as_float(f2tf32(k.w - hi.w));
            *(float4*)&Khi[d * KP + n4] = hi;
            *(float4*)&Klo[d * KP + n4] = lo;
        }
        __syncthreads();

        // ---- S = Q K^T (split tf32: hi*hi + hi*lo + lo*hi) ----
        float s[8][4];
        #pragma unroll
        for (int nt = 0; nt < 8; nt++)
            #pragma unroll
            for (int r = 0; r < 4; r++) s[nt][r] = 0.f;

        const uint32_t* Qh = (const uint32_t*)Qhi;
        const uint32_t* Ql = (const uint32_t*)Qlo;
        const uint32_t* Kh = (const uint32_t*)Khi;
        const uint32_t* Kl = (const uint32_t*)Klo;

        #pragma unroll 4
        for (int ks = 0; ks < 16; ks++) {
            const int kb = ks * 8;
            uint32_t ah[4], al[4];
            ah[0] = Qh[(kb + lt) * QP + m0 + g];
            ah[1] = Qh[(kb + lt) * QP + m0 + g + 8];
            ah[2] = Qh[(kb + lt + 4) * QP + m0 + g];
            ah[3] = Qh[(kb + lt + 4) * QP + m0 + g + 8];
            al[0] = Ql[(kb + lt) * QP + m0 + g];
            al[1] = Ql[(kb + lt) * QP + m0 + g + 8];
            al[2] = Ql[(kb + lt + 4) * QP + m0 + g];
            al[3] = Ql[(kb + lt + 4) * QP + m0 + g + 8];
            #pragma unroll
            for (int nt = 0; nt < 8; nt++) {
                const int n0 = nt * 8 + g;
                uint32_t bh_[2], bl_[2];
                bh_[0] = Kh[(kb + lt) * KP + n0];
                bh_[1] = Kh[(kb + lt + 4) * KP + n0];
                bl_[0] = Kl[(kb + lt) * KP + n0];
                bl_[1] = Kl[(kb + lt + 4) * KP + n0];
                mma_tf32(s[nt], ah, bh_);
                mma_tf32(s[nt], ah, bl_);
                mma_tf32(s[nt], al, bh_);
            }
        }

        // ---- online softmax (rows g and g+8, full 64 cols in-warp) ----
        const bool diag = (k0 >= q0);
        #pragma unroll
        for (int nt = 0; nt < 8; nt++) {
            const int c0 = k0 + nt * 8 + 2 * lt;
            float v0 = s[nt][0] * scale;
            float v1 = s[nt][1] * scale;
            float v2 = s[nt][2] * scale;
            float v3 = s[nt][3] * scale;
            if (diag) {
                if (c0     > row0)     v0 = -1e30f;
                if (c0 + 1 > row0)     v1 = -1e30f;
                if (c0     > row0 + 8) v2 = -1e30f;
                if (c0 + 1 > row0 + 8) v3 = -1e30f;
            }
            s[nt][0] = v0; s[nt][1] = v1; s[nt][2] = v2; s[nt][3] = v3;
        }
        float mx0 = -1e30f, mx1 = -1e30f;
        #pragma unroll
        for (int nt = 0; nt < 8; nt++) {
            mx0 = fmaxf(mx0, fmaxf(s[nt][0], s[nt][1]));
            mx1 = fmaxf(mx1, fmaxf(s[nt][2], s[nt][3]));
        }
        mx0 = fmaxf(mx0, __shfl_xor_sync(0xffffffffu, mx0, 1));
        mx0 = fmaxf(mx0, __shfl_xor_sync(0xffffffffu, mx0, 2));
        mx1 = fmaxf(mx1, __shfl_xor_sync(0xffffffffu, mx1, 1));
        mx1 = fmaxf(mx1, __shfl_xor_sync(0xffffffffu, mx1, 2));

        const float mn0 = fmaxf(m_s[0], mx0);
        const float mn1 = fmaxf(m_s[1], mx1);
        const float cr0 = __expf(m_s[0] - mn0);
        const float cr1 = __expf(m_s[1] - mn1);
        float rs0 = 0.f, rs1 = 0.f;
        #pragma unroll
        for (int nt = 0; nt < 8; nt++) {
            s[nt][0] = __expf(s[nt][0] - mn0);
            s[nt][1] = __expf(s[nt][1] - mn0);
            s[nt][2] = __expf(s[nt][2] - mn1);
            s[nt][3] = __expf(s[nt][3] - mn1);
            rs0 += s[nt][0] + s[nt][1];
            rs1 += s[nt][2] + s[nt][3];
        }
        rs0 += __shfl_xor_sync(0xffffffffu, rs0, 1);
        rs0 += __shfl_xor_sync(0xffffffffu, rs0, 2);
        rs1 += __shfl_xor_sync(0xffffffffu, rs1, 1);
        rs1 += __shfl_xor_sync(0xffffffffu, rs1, 2);
        l_s[0] = l_s[0] * cr0 + rs0;  m_s[0] = mn0;
        l_s[1] = l_s[1] * cr1 + rs1;  m_s[1] = mn1;
        #pragma unroll
        for (int nt = 0; nt < 16; nt++) {
            o[nt][0] *= cr0; o[nt][1] *= cr0;
            o[nt][2] *= cr1; o[nt][3] *= cr1;
        }

        __syncthreads();    // all warps done reading K before V/P overwrite

        // ---- store P (tf32-rounded) [m][k], load V tile [k=64][n=128] ----
        #pragma unroll
        for (int nt = 0; nt < 8; nt++) {
            const int cc = nt * 8 + 2 * lt;
            float2 p01 = make_float2(__uint_as_float(f2tf32(s[nt][0])),
                                     __uint_as_float(f2tf32(s[nt][1])));
            float2 p23 = make_float2(__uint_as_float(f2tf32(s[nt][2])),
                                     __uint_as_float(f2tf32(s[nt][3])));
            *(float2*)&Ps[(m0 + g) * PP + cc]     = p01;
            *(float2*)&Ps[(m0 + g + 8) * PP + cc] = p23;
        }
        for (int i = tid; i < 64 * 32; i += 256) {
            int r  = i >> 5;
            int c4 = (i & 31) << 2;
            float4 v = *(const float4*)&V[(size_t)(b * SEQ + k0 + r) * KVDIM + kvh * HDIM + c4];
            v.x = __uint_as_float(f2tf32(v.x));
            v.y = __uint_as_float(f2tf32(v.y));
            v.z = __uint_as_float(f2tf32(v.z));
            v.w = __uint_as_float(f2tf32(v.w));
            *(float4*)&Vs[r * VP + c4] = v;
        }
        __syncthreads();

        // ---- O += P V ----
        const uint32_t* Pu = (const uint32_t*)Ps;
        const uint32_t* Vu = (const uint32_t*)Vs;
        #pragma unroll 2
        for (int ks = 0; ks < 8; ks++) {
            const int kb = ks * 8;
            uint32_t a[4];
            a[0] = Pu[(m0 + g) * PP + kb + lt];
            a[1] = Pu[(m0 + g + 8) * PP + kb + lt];
            a[2] = Pu[(m0 + g) * PP + kb + lt + 4];
            a[3] = Pu[(m0 + g + 8) * PP + kb + lt + 4];
            #pragma unroll
            for (int nt = 0; nt < 16; nt++) {
                const int n0 = nt * 8 + g;
                uint32_t bb[2];
                bb[0] = Vu[(kb + lt) * VP + n0];
                bb[1] = Vu[(kb + lt + 4) * VP + n0];
                mma_tf32(o[nt], a, bb);
            }
        }
    }

    // ---- epilogue: normalize, store ----
    const float inv0 = 1.f / l_s[0];
    const float inv1 = 1.f / l_s[1];
    #pragma unroll
    for (int nt = 0; nt < 16; nt++) {
        const int col = h * HDIM + nt * 8 + 2 * lt;
        float2 v01 = make_float2(o[nt][0] * inv0, o[nt][1] * inv0);
        float2 v23 = make_float2(o[nt][2] * inv1, o[nt][3] * inv1);
        *(float2*)&O[(size_t)(b * SEQ + q0 + m0 + g) * DMODEL + col]     = v01;
        *(float2*)&O[(size_t)(b * SEQ + q0 + m0 + g + 8) * DMODEL + col] = v23;
    }
}

// ---------------- launch -----------------------------------------------------
extern "C" void kernel_launch(void* const* d_in, const int* in_sizes, int n_in,
                              void* d_out, int out_size) {
    const float* x  = (const float*)d_in[0];
    const float* wq = (const float*)d_in[1];
    const float* wk = (const float*)d_in[2];
    const float* wv = (const float*)d_in[3];
    const float* wo = (const float*)d_in[4];
    float* out = (float*)d_out;

    float *qT, *kT, *v, *att;
    cudaGetSymbolAddress((void**)&qT,  g_qT);
    cudaGetSymbolAddress((void**)&kT,  g_kT);
    cudaGetSymbolAddress((void**)&v,   g_v);
    cudaGetSymbolAddress((void**)&att, g_att);

    cudaFuncSetAttribute(attn_kernel, cudaFuncAttributeMaxDynamicSharedMemorySize, ATT_SMEM);
    cudaFuncSetAttribute(tf32_gemm<true>,  cudaFuncAttributeMaxDynamicSharedMemorySize, TRANS_SMEM);
    cudaFuncSetAttribute(tf32_gemm<false>, cudaFuncAttributeMaxDynamicSharedMemorySize, KLOOP_SMEM);

    dim3 blk(256);
    tf32_gemm<true><<<dim3(DMODEL / 128, MTOT / 128), blk, TRANS_SMEM>>>(x, wq, qT, MTOT, DMODEL, DMODEL);
    tf32_gemm<true><<<dim3(KVDIM / 128, MTOT / 128), blk, TRANS_SMEM>>>(x, wk, kT, MTOT, KVDIM, DMODEL);
    tf32_gemm<false><<<dim3(KVDIM / 128, MTOT / 128), blk, KLOOP_SMEM>>>(x, wv, v, MTOT, KVDIM, DMODEL);
    attn_kernel<<<dim3(SEQ / 128, BATCH * NHEADS), blk, ATT_SMEM>>>(qT, kT, v, att);
    tf32_gemm<false><<<dim3(DMODEL / 128, MTOT / 128), blk, KLOOP_SMEM>>>(att, wo, out, MTOT, DMODEL, DMODEL);
}

// round 9
// speedup vs baseline: 8.2045x; 1.0410x over previous
#include <cuda_runtime.h>
#include <cuda_bf16.h>
#include <math.h>
#include <stdint.h>

// Problem constants
#define BATCH    2
#define SEQ      2048
#define DMODEL   2048
#define NHEADS   16
#define NKV      4
#define HDIM     128
#define NREP     4
#define MTOT     (BATCH * SEQ)          // 4096
#define KVDIM    (NKV * HDIM)           // 512

// ---------------- scratch (device globals; no allocation allowed) -----------
__device__ float g_qT[DMODEL * MTOT];    // Q^T: [h*128+d][b*2048+s]
__device__ float g_kT[KVDIM * MTOT];     // K^T: [kv*128+d][b*2048+s]
__device__ float g_v[MTOT * KVDIM];      // V natural [b*2048+s][kv*128+d]
__device__ float g_att[MTOT * DMODEL];   // attention output, natural

// ---------------- mma helpers ------------------------------------------------
__device__ __forceinline__ uint32_t f2tf32(float x) {
    uint32_t u;
    asm("cvt.rna.tf32.f32 %0, %1;" : "=r"(u) : "f"(x));
    return u;
}

__device__ __forceinline__ void mma_tf32(float c[4], const uint32_t a[4],
                                         const uint32_t b[2]) {
    asm volatile(
        "mma.sync.aligned.m16n8k8.row.col.f32.tf32.tf32.f32 "
        "{%0,%1,%2,%3}, {%4,%5,%6,%7}, {%8,%9}, {%0,%1,%2,%3};\n"
        : "+f"(c[0]), "+f"(c[1]), "+f"(c[2]), "+f"(c[3])
        : "r"(a[0]), "r"(a[1]), "r"(a[2]), "r"(a[3]), "r"(b[0]), "r"(b[1]));
}

__device__ __forceinline__ void mma_bf16(float c[4], const uint32_t a[4],
                                         const uint32_t b[2]) {
    asm volatile(
        "mma.sync.aligned.m16n8k16.row.col.f32.bf16.bf16.f32 "
        "{%0,%1,%2,%3}, {%4,%5,%6,%7}, {%8,%9}, {%0,%1,%2,%3};\n"
        : "+f"(c[0]), "+f"(c[1]), "+f"(c[2]), "+f"(c[3])
        : "r"(a[0]), "r"(a[1]), "r"(a[2]), "r"(a[3]), "r"(b[0]), "r"(b[1]));
}

__device__ __forceinline__ uint32_t pack2bf(float x, float y) {
    __nv_bfloat162 h = __floats2bfloat162_rn(x, y);   // x -> low half (even k)
    return *reinterpret_cast<uint32_t*>(&h);
}
__device__ __forceinline__ float bf16rd(float x) {
    return __bfloat162float(__float2bfloat16_rn(x));
}

// ---------------- tf32 tensor-core projection GEMM --------------------------
#define AP 136
#define KLOOP_SMEM   (2 * 2 * 16 * AP * 4)      // 34816 B
#define TRANS_SMEM   (128 * 129 * 4)            // 66048 B

template <bool TRANSC>
__global__ __launch_bounds__(256)
void tf32_gemm(const float* __restrict__ A, const float* __restrict__ B,
               float* __restrict__ C, int M, int N, int K) {
    extern __shared__ float sh[];
    float* As = sh;
    float* Bs = sh + 2 * 16 * AP;

    const int tid  = threadIdx.x;
    const int lane = tid & 31;
    const int g    = lane >> 2;
    const int t    = lane & 3;
    const int warp = tid >> 5;
    const int wm   = (warp & 3) * 32;
    const int wn   = (warp >> 2) * 64;
    const int bx   = blockIdx.x;
    const int by   = blockIdx.y;

    const int am  = tid >> 2;
    const int ac4 = (tid & 3) * 4;
    const int brw = tid >> 5;
    const int bn4 = (tid & 31) * 4;
    const float* Ag = A + (size_t)(by * 128 + am) * K + ac4;
    const float* Bg = B + (size_t)brw * N + bx * 128 + bn4;

    float c[2][8][4];
    #pragma unroll
    for (int mt = 0; mt < 2; mt++)
        #pragma unroll
        for (int nt = 0; nt < 8; nt++)
            #pragma unroll
            for (int r = 0; r < 4; r++) c[mt][nt][r] = 0.f;

    float4 pa0, pa1, pb0, pb1;
    pa0 = *(const float4*)(Ag);
    pa1 = *(const float4*)(Ag + (size_t)64 * K);
    pb0 = *(const float4*)(Bg);
    pb1 = *(const float4*)(Bg + (size_t)8 * N);

    {
        float* Ab = As;
        float* Bb = Bs;
        const float av0[4] = {pa0.x, pa0.y, pa0.z, pa0.w};
        const float av1[4] = {pa1.x, pa1.y, pa1.z, pa1.w};
        #pragma unroll
        for (int j = 0; j < 4; j++) {
            Ab[(ac4 + j) * AP + am]      = __uint_as_float(f2tf32(av0[j]));
            Ab[(ac4 + j) * AP + am + 64] = __uint_as_float(f2tf32(av1[j]));
        }
        uint4 u0 = {f2tf32(pb0.x), f2tf32(pb0.y), f2tf32(pb0.z), f2tf32(pb0.w)};
        uint4 u1 = {f2tf32(pb1.x), f2tf32(pb1.y), f2tf32(pb1.z), f2tf32(pb1.w)};
        *(uint4*)&Bb[brw * AP + bn4]       = u0;
        *(uint4*)&Bb[(brw + 8) * AP + bn4] = u1;
    }
    __syncthreads();

    const int NT = K >> 4;
    for (int kt = 0; kt < NT; kt++) {
        if (kt + 1 < NT) {
            const float* Ap = Ag + (kt + 1) * 16;
            const float* Bp = Bg + (size_t)(kt + 1) * 16 * N;
            pa0 = *(const float4*)(Ap);
            pa1 = *(const float4*)(Ap + (size_t)64 * K);
            pb0 = *(const float4*)(Bp);
            pb1 = *(const float4*)(Bp + (size_t)8 * N);
        }

        const uint32_t* Au = (const uint32_t*)(As + (kt & 1) * 16 * AP);
        const uint32_t* Bu = (const uint32_t*)(Bs + (kt & 1) * 16 * AP);

        #pragma unroll
        for (int s = 0; s < 2; s++) {
            const int kb = s * 8;
            uint32_t a[2][4], bf[8][2];
            #pragma unroll
            for (int mt = 0; mt < 2; mt++) {
                const int m0 = wm + mt * 16 + g;
                a[mt][0] = Au[(kb + t) * AP + m0];
                a[mt][1] = Au[(kb + t) * AP + m0 + 8];
                a[mt][2] = Au[(kb + t + 4) * AP + m0];
                a[mt][3] = Au[(kb + t + 4) * AP + m0 + 8];
            }
            #pragma unroll
            for (int nt = 0; nt < 8; nt++) {
                const int n0 = wn + nt * 8 + g;
                bf[nt][0] = Bu[(kb + t) * AP + n0];
                bf[nt][1] = Bu[(kb + t + 4) * AP + n0];
            }
            #pragma unroll
            for (int mt = 0; mt < 2; mt++)
                #pragma unroll
                for (int nt = 0; nt < 8; nt++)
                    mma_tf32(c[mt][nt], a[mt], bf[nt]);
        }

        if (kt + 1 < NT) {
            float* Ab = As + ((kt + 1) & 1) * 16 * AP;
            float* Bb = Bs + ((kt + 1) & 1) * 16 * AP;
            const float av0[4] = {pa0.x, pa0.y, pa0.z, pa0.w};
            const float av1[4] = {pa1.x, pa1.y, pa1.z, pa1.w};
            #pragma unroll
            for (int j = 0; j < 4; j++) {
                Ab[(ac4 + j) * AP + am]      = __uint_as_float(f2tf32(av0[j]));
                Ab[(ac4 + j) * AP + am + 64] = __uint_as_float(f2tf32(av1[j]));
            }
            uint4 u0 = {f2tf32(pb0.x), f2tf32(pb0.y), f2tf32(pb0.z), f2tf32(pb0.w)};
            uint4 u1 = {f2tf32(pb1.x), f2tf32(pb1.y), f2tf32(pb1.z), f2tf32(pb1.w)};
            *(uint4*)&Bb[brw * AP + bn4]       = u0;
            *(uint4*)&Bb[(brw + 8) * AP + bn4] = u1;
            __syncthreads();
        }
    }

    if (!TRANSC) {
        #pragma unroll
        for (int mt = 0; mt < 2; mt++) {
            #pragma unroll
            for (int nt = 0; nt < 8; nt++) {
                const int row = by * 128 + wm + mt * 16 + g;
                const int col = bx * 128 + wn + nt * 8 + t * 2;
                float2 v01 = make_float2(c[mt][nt][0], c[mt][nt][1]);
                float2 v23 = make_float2(c[mt][nt][2], c[mt][nt][3]);
                *(float2*)&C[(size_t)row * N + col]       = v01;
                *(float2*)&C[(size_t)(row + 8) * N + col] = v23;
            }
        }
    } else {
        __syncthreads();
        float* Cs = sh;   // 128 x 129
        #pragma unroll
        for (int mt = 0; mt < 2; mt++) {
            #pragma unroll
            for (int nt = 0; nt < 8; nt++) {
                const int r  = wm + mt * 16 + g;
                const int cl = wn + nt * 8 + t * 2;
                Cs[r * 129 + cl]           = c[mt][nt][0];
                Cs[r * 129 + cl + 1]       = c[mt][nt][1];
                Cs[(r + 8) * 129 + cl]     = c[mt][nt][2];
                Cs[(r + 8) * 129 + cl + 1] = c[mt][nt][3];
            }
        }
        __syncthreads();
        #pragma unroll
        for (int r = 0; r < 16; r++) {
            const int i  = tid + 256 * r;
            const int n  = i >> 5;
            const int m4 = (i & 31) << 2;
            float4 v;
            v.x = Cs[(m4 + 0) * 129 + n];
            v.y = Cs[(m4 + 1) * 129 + n];
            v.z = Cs[(m4 + 2) * 129 + n];
            v.w = Cs[(m4 + 3) * 129 + n];
            *(float4*)&C[(size_t)(bx * 128 + n) * M + by * 128 + m4] = v;
        }
    }
}

// ---------------- Split-bf16 tensor-core flash attention --------------------
// q tile 128 rows per CTA; kv tiles of 64. 8 warps, each 16 q-rows x 64 cols.
// All operands stored as packed bf16x2 (pairs along the MMA-k dim), hi+lo
// planes. QK^T and PV each use 3 m16n8k16 MMAs (hi*hi + lo*hi + hi*lo).
// Plane strides in uint32 units (pads keep all LDS conflict-free):
#define QP 136                              // Q [d2=64][m=128]  (8lt+g banks)
#define KP 72                               // K [d2=64][n=64]
#define VP 136                              // V [k2=32][n=128]
#define PP 36                               // P [m=128][k2=32]  (4g+lt banks)
#define SM_QHI 0
#define SM_QLO (64 * QP)                    // 8704
#define SM_KHI (2 * 64 * QP)                // 17408
#define SM_KLO (SM_KHI + 64 * KP)           // 22016
#define SM_VHI SM_KHI                       // overlays K (sequenced)
#define SM_VLO (SM_VHI + 32 * VP)           // 21760
#define SM_PHI (SM_VLO + 32 * VP)           // 26112
#define SM_PLO (SM_PHI + 128 * PP)          // 30720
#define ATT_SMEM_U32 (SM_PLO + 128 * PP)    // 35328
#define ATT_SMEM (ATT_SMEM_U32 * 4)         // 141312 B

__global__ __launch_bounds__(256, 1)
void attn_kernel(const float* __restrict__ QT, const float* __restrict__ KT,
                 const float* __restrict__ V, float* __restrict__ O) {
    extern __shared__ uint32_t smu[];
    uint32_t* Qhi = smu + SM_QHI;
    uint32_t* Qlo = smu + SM_QLO;
    uint32_t* Khi = smu + SM_KHI;
    uint32_t* Klo = smu + SM_KLO;
    uint32_t* Vhi = smu + SM_VHI;
    uint32_t* Vlo = smu + SM_VLO;
    uint32_t* Phi = smu + SM_PHI;
    uint32_t* Plo = smu + SM_PLO;

    const int tid  = threadIdx.x;
    const int lane = tid & 31;
    const int g    = lane >> 2;         // 0..7
    const int lt   = lane & 3;          // 0..3
    const int warp = tid >> 5;          // 0..7
    const int m0   = warp * 16;         // warp's q-row block
    const int bh   = blockIdx.y;
    const int b    = bh >> 4;
    const int h    = bh & 15;
    const int kvh  = h >> 2;
    const int bxe  = gridDim.x - 1 - blockIdx.x;   // heavy tiles first
    const int q0   = bxe * 128;

    // ---- load Q tile, split into hi/lo bf16x2 planes [d2][m] ----
    for (int i = tid; i < 64 * 32; i += 256) {
        int d2 = i >> 5;
        int m4 = (i & 31) << 2;
        const float* pa = &QT[(size_t)(h * HDIM + 2 * d2) * MTOT + b * SEQ + q0 + m4];
        float4 qa = *(const float4*)pa;
        float4 qb = *(const float4*)(pa + MTOT);
        const float fa[4] = {qa.x, qa.y, qa.z, qa.w};
        const float fb[4] = {qb.x, qb.y, qb.z, qb.w};
        uint32_t hi[4], lo[4];
        #pragma unroll
        for (int j = 0; j < 4; j++) {
            float ah = bf16rd(fa[j]);
            float bh_ = bf16rd(fb[j]);
            hi[j] = pack2bf(ah, bh_);
            lo[j] = pack2bf(fa[j] - ah, fb[j] - bh_);
        }
        *(uint4*)&Qhi[d2 * QP + m4] = make_uint4(hi[0], hi[1], hi[2], hi[3]);
        *(uint4*)&Qlo[d2 * QP + m4] = make_uint4(lo[0], lo[1], lo[2], lo[3]);
    }

    float m_s[2] = {-1e30f, -1e30f};
    float l_s[2] = {0.f, 0.f};
    float o[16][4];
    #pragma unroll
    for (int nt = 0; nt < 16; nt++)
        #pragma unroll
        for (int r = 0; r < 4; r++) o[nt][r] = 0.f;

    const float scale = 0.08838834764831845f;   // 1/sqrt(128)
    const int ntk = 2 * (bxe + 1);
    const int row0 = q0 + m0 + g;               // global q row (and +8)

    for (int tt = 0; tt < ntk; tt++) {
        const int k0 = tt * 64;
        __syncthreads();     // prev PV done reading V/P before K overwrite

        // ---- load K tile [d2=64][n=64], split hi/lo ----
        for (int i = tid; i < 64 * 16; i += 256) {
            int d2 = i >> 4;
            int n4 = (i & 15) << 2;
            const float* pk = &KT[(size_t)(kvh * HDIM + 2 * d2) * MTOT + b * SEQ + k0 + n4];
            float4 ka = *(const float4*)pk;
            float4 kb = *(const float4*)(pk + MTOT);
            const float fa[4] = {ka.x, ka.y, ka.z, ka.w};
            const float fb[4] = {kb.x, kb.y, kb.z, kb.w};
            uint32_t hi[4], lo[4];
            #pragma unroll
            for (int j = 0; j < 4; j++) {
                float ah = bf16rd(fa[j]);
                float bh_ = bf16rd(fb[j]);
                hi[j] = pack2bf(ah, bh_);
                lo[j] = pack2bf(fa[j] - ah, fb[j] - bh_);
            }
            *(uint4*)&Khi[d2 * KP + n4] = make_uint4(hi[0], hi[1], hi[2], hi[3]);
            *(uint4*)&Klo[d2 * KP + n4] = make_uint4(lo[0], lo[1], lo[2], lo[3]);
        }
        __syncthreads();

        // ---- S = Q K^T : 8 k16 steps, 3 MMAs each ----
        float s[8][4];
        #pragma unroll
        for (int nt = 0; nt < 8; nt++)
            #pragma unroll
            for (int r = 0; r < 4; r++) s[nt][r] = 0.f;

        #pragma unroll 4
        for (int ks = 0; ks < 8; ks++) {
            const int kb = ks * 8;
            uint32_t ah[4], al[4];
            ah[0] = Qhi[(kb + lt) * QP + m0 + g];
            ah[1] = Qhi[(kb + lt) * QP + m0 + g + 8];
            ah[2] = Qhi[(kb + lt + 4) * QP + m0 + g];
            ah[3] = Qhi[(kb + lt + 4) * QP + m0 + g + 8];
            al[0] = Qlo[(kb + lt) * QP + m0 + g];
            al[1] = Qlo[(kb + lt) * QP + m0 + g + 8];
            al[2] = Qlo[(kb + lt + 4) * QP + m0 + g];
            al[3] = Qlo[(kb + lt + 4) * QP + m0 + g + 8];
            #pragma unroll
            for (int nt = 0; nt < 8; nt++) {
                const int n0 = nt * 8 + g;
                uint32_t bh_[2], bl_[2];
                bh_[0] = Khi[(kb + lt) * KP + n0];
                bh_[1] = Khi[(kb + lt + 4) * KP + n0];
                bl_[0] = Klo[(kb + lt) * KP + n0];
                bl_[1] = Klo[(kb + lt + 4) * KP + n0];
                mma_bf16(s[nt], ah, bh_);
                mma_bf16(s[nt], al, bh_);
                mma_bf16(s[nt], ah, bl_);
            }
        }

        // ---- online softmax (rows g and g+8, full 64 cols in-warp) ----
        const bool diag = (k0 >= q0);
        #pragma unroll
        for (int nt = 0; nt < 8; nt++) {
            const int c0 = k0 + nt * 8 + 2 * lt;
            float v0 = s[nt][0] * scale;
            float v1 = s[nt][1] * scale;
            float v2 = s[nt][2] * scale;
            float v3 = s[nt][3] * scale;
            if (diag) {
                if (c0     > row0)     v0 = -1e30f;
                if (c0 + 1 > row0)     v1 = -1e30f;
                if (c0     > row0 + 8) v2 = -1e30f;
                if (c0 + 1 > row0 + 8) v3 = -1e30f;
            }
            s[nt][0] = v0; s[nt][1] = v1; s[nt][2] = v2; s[nt][3] = v3;
        }
        float mx0 = -1e30f, mx1 = -1e30f;
        #pragma unroll
        for (int nt = 0; nt < 8; nt++) {
            mx0 = fmaxf(mx0, fmaxf(s[nt][0], s[nt][1]));
            mx1 = fmaxf(mx1, fmaxf(s[nt][2], s[nt][3]));
        }
        mx0 = fmaxf(mx0, __shfl_xor_sync(0xffffffffu, mx0, 1));
        mx0 = fmaxf(mx0, __shfl_xor_sync(0xffffffffu, mx0, 2));
        mx1 = fmaxf(mx1, __shfl_xor_sync(0xffffffffu, mx1, 1));
        mx1 = fmaxf(mx1, __shfl_xor_sync(0xffffffffu, mx1, 2));

        const float mn0 = fmaxf(m_s[0], mx0);
        const float mn1 = fmaxf(m_s[1], mx1);
        const float cr0 = __expf(m_s[0] - mn0);
        const float cr1 = __expf(m_s[1] - mn1);
        float rs0 = 0.f, rs1 = 0.f;
        #pragma unroll
        for (int nt = 0; nt < 8; nt++) {
            s[nt][0] = __expf(s[nt][0] - mn0);
            s[nt][1] = __expf(s[nt][1] - mn0);
            s[nt][2] = __expf(s[nt][2] - mn1);
            s[nt][3] = __expf(s[nt][3] - mn1);
            rs0 += s[nt][0] + s[nt][1];
            rs1 += s[nt][2] + s[nt][3];
        }
        rs0 += __shfl_xor_sync(0xffffffffu, rs0, 1);
        rs0 += __shfl_xor_sync(0xffffffffu, rs0, 2);
        rs1 += __shfl_xor_sync(0xffffffffu, rs1, 1);
        rs1 += __shfl_xor_sync(0xffffffffu, rs1, 2);
        l_s[0] = l_s[0] * cr0 + rs0;  m_s[0] = mn0;
        l_s[1] = l_s[1] * cr1 + rs1;  m_s[1] = mn1;
        #pragma unroll
        for (int nt = 0; nt < 16; nt++) {
            o[nt][0] *= cr0; o[nt][1] *= cr0;
            o[nt][2] *= cr1; o[nt][3] *= cr1;
        }

        __syncthreads();    // all warps done reading K before V/P overwrite

        // ---- store P split hi/lo (packed pairs along k), rows g and g+8 ----
        #pragma unroll
        for (int nt = 0; nt < 8; nt++) {
            const int kc = nt * 4 + lt;     // pair index
            float h0 = bf16rd(s[nt][0]), h1 = bf16rd(s[nt][1]);
            float h2 = bf16rd(s[nt][2]), h3 = bf16rd(s[nt][3]);
            Phi[(m0 + g) * PP + kc]     = pack2bf(h0, h1);
            Plo[(m0 + g) * PP + kc]     = pack2bf(s[nt][0] - h0, s[nt][1] - h1);
            Phi[(m0 + g + 8) * PP + kc] = pack2bf(h2, h3);
            Plo[(m0 + g + 8) * PP + kc] = pack2bf(s[nt][2] - h2, s[nt][3] - h3);
        }

        // ---- load V tile [k2=32][n=128], split hi/lo ----
        for (int i = tid; i < 32 * 32; i += 256) {
            int k2 = i >> 5;
            int c4 = (i & 31) << 2;
            const float* pv = &V[(size_t)(b * SEQ + k0 + 2 * k2) * KVDIM + kvh * HDIM + c4];
            float4 va = *(const float4*)pv;
            float4 vb = *(const float4*)(pv + KVDIM);
            const float fa[4] = {va.x, va.y, va.z, va.w};
            const float fb[4] = {vb.x, vb.y, vb.z, vb.w};
            uint32_t hi[4], lo[4];
            #pragma unroll
            for (int j = 0; j < 4; j++) {
                float ah = bf16rd(fa[j]);
                float bh_ = bf16rd(fb[j]);
                hi[j] = pack2bf(ah, bh_);
                lo[j] = pack2bf(fa[j] - ah, fb[j] - bh_);
            }
            *(uint4*)&Vhi[k2 * VP + c4] = make_uint4(hi[0], hi[1], hi[2], hi[3]);
            *(uint4*)&Vlo[k2 * VP + c4] = make_uint4(lo[0], lo[1], lo[2], lo[3]);
        }
        __syncthreads();

        // ---- O += P V : 4 k16 steps, 3 MMAs each ----
        #pragma unroll 2
        for (int ks = 0; ks < 4; ks++) {
            const int kb = ks * 8;
            uint32_t ph[4], pl[4];
            ph[0] = Phi[(m0 + g) * PP + kb + lt];
            ph[1] = Phi[(m0 + g + 8) * PP + kb + lt];
            ph[2] = Phi[(m0 + g) * PP + kb + 4 + lt];
            ph[3] = Phi[(m0 + g + 8) * PP + kb + 4 + lt];
            pl[0] = Plo[(m0 + g) * PP + kb + lt];
            pl[1] = Plo[(m0 + g + 8) * PP + kb + lt];
            pl[2] = Plo[(m0 + g) * PP + kb + 4 + lt];
            pl[3] = Plo[(m0 + g + 8) * PP + kb + 4 + lt];
            #pragma unroll
            for (int nt = 0; nt < 16; nt++) {
                const int n0 = nt * 8 + g;
                uint32_t vh[2], vl[2];
                vh[0] = Vhi[(kb + lt) * VP + n0];
                vh[1] = Vhi[(kb + 4 + lt) * VP + n0];
                vl[0] = Vlo[(kb + lt) * VP + n0];
                vl[1] = Vlo[(kb + 4 + lt) * VP + n0];
                mma_bf16(o[nt], ph, vh);
                mma_bf16(o[nt], pl, vh);
                mma_bf16(o[nt], ph, vl);
            }
        }
    }

    // ---- epilogue: normalize, store ----
    const float inv0 = 1.f / l_s[0];
    const float inv1 = 1.f / l_s[1];
    #pragma unroll
    for (int nt = 0; nt < 16; nt++) {
        const int col = h * HDIM + nt * 8 + 2 * lt;
        float2 v01 = make_float2(o[nt][0] * inv0, o[nt][1] * inv0);
        float2 v23 = make_float2(o[nt][2] * inv1, o[nt][3] * inv1);
        *(float2*)&O[(size_t)(b * SEQ + q0 + m0 + g) * DMODEL + col]     = v01;
        *(float2*)&O[(size_t)(b * SEQ + q0 + m0 + g + 8) * DMODEL + col] = v23;
    }
}

// ---------------- launch -----------------------------------------------------
extern "C" void kernel_launch(void* const* d_in, const int* in_sizes, int n_in,
                              void* d_out, int out_size) {
    const float* x  = (const float*)d_in[0];
    const float* wq = (const float*)d_in[1];
    const float* wk = (const float*)d_in[2];
    const float* wv = (const float*)d_in[3];
    const float* wo = (const float*)d_in[4];
    float* out = (float*)d_out;

    float *qT, *kT, *v, *att;
    cudaGetSymbolAddress((void**)&qT,  g_qT);
    cudaGetSymbolAddress((void**)&kT,  g_kT);
    cudaGetSymbolAddress((void**)&v,   g_v);
    cudaGetSymbolAddress((void**)&att, g_att);

    cudaFuncSetAttribute(attn_kernel, cudaFuncAttributeMaxDynamicSharedMemorySize, ATT_SMEM);
    cudaFuncSetAttribute(tf32_gemm<true>,  cudaFuncAttributeMaxDynamicSharedMemorySize, TRANS_SMEM);
    cudaFuncSetAttribute(tf32_gemm<false>, cudaFuncAttributeMaxDynamicSharedMemorySize, KLOOP_SMEM);

    dim3 blk(256);
    tf32_gemm<true><<<dim3(DMODEL / 128, MTOT / 128), blk, TRANS_SMEM>>>(x, wq, qT, MTOT, DMODEL, DMODEL);
    tf32_gemm<true><<<dim3(KVDIM / 128, MTOT / 128), blk, TRANS_SMEM>>>(x, wk, kT, MTOT, KVDIM, DMODEL);
    tf32_gemm<false><<<dim3(KVDIM / 128, MTOT / 128), blk, KLOOP_SMEM>>>(x, wv, v, MTOT, KVDIM, DMODEL);
    attn_kernel<<<dim3(SEQ / 128, BATCH * NHEADS), blk, ATT_SMEM>>>(qT, kT, v, att);
    tf32_gemm<false><<<dim3(DMODEL / 128, MTOT / 128), blk, KLOOP_SMEM>>>(att, wo, out, MTOT, DMODEL, DMODEL);
}

// round 11
// speedup vs baseline: 8.9946x; 1.0963x over previous
#include <cuda_runtime.h>
#include <cuda_bf16.h>
#include <math.h>
#include <stdint.h>

// Problem constants
#define BATCH    2
#define SEQ      2048
#define DMODEL   2048
#define NHEADS   16
#define NKV      4
#define HDIM     128
#define NREP     4
#define MTOT     (BATCH * SEQ)          // 4096
#define KVDIM    (NKV * HDIM)           // 512

// ---------------- scratch (device globals; no allocation allowed) -----------
__device__ float g_qT[DMODEL * MTOT];    // Q^T: [h*128+d][b*2048+s]
__device__ float g_kT[KVDIM * MTOT];     // K^T: [kv*128+d][b*2048+s]
__device__ float g_v[MTOT * KVDIM];      // V natural [b*2048+s][kv*128+d]
__device__ float g_att[MTOT * DMODEL];   // attention output, natural

// ---------------- mma helpers ------------------------------------------------
__device__ __forceinline__ uint32_t f2tf32(float x) {
    uint32_t u;
    asm("cvt.rna.tf32.f32 %0, %1;" : "=r"(u) : "f"(x));
    return u;
}

__device__ __forceinline__ void mma_tf32(float c[4], const uint32_t a[4],
                                         const uint32_t b[2]) {
    asm volatile(
        "mma.sync.aligned.m16n8k8.row.col.f32.tf32.tf32.f32 "
        "{%0,%1,%2,%3}, {%4,%5,%6,%7}, {%8,%9}, {%0,%1,%2,%3};\n"
        : "+f"(c[0]), "+f"(c[1]), "+f"(c[2]), "+f"(c[3])
        : "r"(a[0]), "r"(a[1]), "r"(a[2]), "r"(a[3]), "r"(b[0]), "r"(b[1]));
}

__device__ __forceinline__ void mma_bf16(float c[4], const uint32_t a[4],
                                         const uint32_t b[2]) {
    asm volatile(
        "mma.sync.aligned.m16n8k16.row.col.f32.bf16.bf16.f32 "
        "{%0,%1,%2,%3}, {%4,%5,%6,%7}, {%8,%9}, {%0,%1,%2,%3};\n"
        : "+f"(c[0]), "+f"(c[1]), "+f"(c[2]), "+f"(c[3])
        : "r"(a[0]), "r"(a[1]), "r"(a[2]), "r"(a[3]), "r"(b[0]), "r"(b[1]));
}

__device__ __forceinline__ uint32_t pack2bf(float x, float y) {
    __nv_bfloat162 h = __floats2bfloat162_rn(x, y);   // x -> low half (even k)
    return *reinterpret_cast<uint32_t*>(&h);
}
__device__ __forceinline__ float bf16rd(float x) {
    return __bfloat162float(__float2bfloat16_rn(x));
}

// ---------------- tf32 tensor-core projection GEMM --------------------------
#define AP 136
#define KLOOP_SMEM   (2 * 2 * 16 * AP * 4)      // 34816 B
#define TRANS_SMEM   (128 * 129 * 4)            // 66048 B

template <bool TRANSC>
__global__ __launch_bounds__(256)
void tf32_gemm(const float* __restrict__ A, const float* __restrict__ B,
               float* __restrict__ C, int M, int N, int K) {
    extern __shared__ float sh[];
    float* As = sh;
    float* Bs = sh + 2 * 16 * AP;

    const int tid  = threadIdx.x;
    const int lane = tid & 31;
    const int g    = lane >> 2;
    const int t    = lane & 3;
    const int warp = tid >> 5;
    const int wm   = (warp & 3) * 32;
    const int wn   = (warp >> 2) * 64;
    const int bx   = blockIdx.x;
    const int by   = blockIdx.y;

    const int am  = tid >> 2;
    const int ac4 = (tid & 3) * 4;
    const int brw = tid >> 5;
    const int bn4 = (tid & 31) * 4;
    const float* Ag = A + (size_t)(by * 128 + am) * K + ac4;
    const float* Bg = B + (size_t)brw * N + bx * 128 + bn4;

    float c[2][8][4];
    #pragma unroll
    for (int mt = 0; mt < 2; mt++)
        #pragma unroll
        for (int nt = 0; nt < 8; nt++)
            #pragma unroll
            for (int r = 0; r < 4; r++) c[mt][nt][r] = 0.f;

    float4 pa0, pa1, pb0, pb1;
    pa0 = *(const float4*)(Ag);
    pa1 = *(const float4*)(Ag + (size_t)64 * K);
    pb0 = *(const float4*)(Bg);
    pb1 = *(const float4*)(Bg + (size_t)8 * N);

    {
        float* Ab = As;
        float* Bb = Bs;
        const float av0[4] = {pa0.x, pa0.y, pa0.z, pa0.w};
        const float av1[4] = {pa1.x, pa1.y, pa1.z, pa1.w};
        #pragma unroll
        for (int j = 0; j < 4; j++) {
            Ab[(ac4 + j) * AP + am]      = __uint_as_float(f2tf32(av0[j]));
            Ab[(ac4 + j) * AP + am + 64] = __uint_as_float(f2tf32(av1[j]));
        }
        uint4 u0 = {f2tf32(pb0.x), f2tf32(pb0.y), f2tf32(pb0.z), f2tf32(pb0.w)};
        uint4 u1 = {f2tf32(pb1.x), f2tf32(pb1.y), f2tf32(pb1.z), f2tf32(pb1.w)};
        *(uint4*)&Bb[brw * AP + bn4]       = u0;
        *(uint4*)&Bb[(brw + 8) * AP + bn4] = u1;
    }
    __syncthreads();

    const int NT = K >> 4;
    for (int kt = 0; kt < NT; kt++) {
        if (kt + 1 < NT) {
            const float* Ap = Ag + (kt + 1) * 16;
            const float* Bp = Bg + (size_t)(kt + 1) * 16 * N;
            pa0 = *(const float4*)(Ap);
            pa1 = *(const float4*)(Ap + (size_t)64 * K);
            pb0 = *(const float4*)(Bp);
            pb1 = *(const float4*)(Bp + (size_t)8 * N);
        }

        const uint32_t* Au = (const uint32_t*)(As + (kt & 1) * 16 * AP);
        const uint32_t* Bu = (const uint32_t*)(Bs + (kt & 1) * 16 * AP);

        #pragma unroll
        for (int s = 0; s < 2; s++) {
            const int kb = s * 8;
            uint32_t a[2][4], bf[8][2];
            #pragma unroll
            for (int mt = 0; mt < 2; mt++) {
                const int m0 = wm + mt * 16 + g;
                a[mt][0] = Au[(kb + t) * AP + m0];
                a[mt][1] = Au[(kb + t) * AP + m0 + 8];
                a[mt][2] = Au[(kb + t + 4) * AP + m0];
                a[mt][3] = Au[(kb + t + 4) * AP + m0 + 8];
            }
            #pragma unroll
            for (int nt = 0; nt < 8; nt++) {
                const int n0 = wn + nt * 8 + g;
                bf[nt][0] = Bu[(kb + t) * AP + n0];
                bf[nt][1] = Bu[(kb + t + 4) * AP + n0];
            }
            #pragma unroll
            for (int mt = 0; mt < 2; mt++)
                #pragma unroll
                for (int nt = 0; nt < 8; nt++)
                    mma_tf32(c[mt][nt], a[mt], bf[nt]);
        }

        if (kt + 1 < NT) {
            float* Ab = As + ((kt + 1) & 1) * 16 * AP;
            float* Bb = Bs + ((kt + 1) & 1) * 16 * AP;
            const float av0[4] = {pa0.x, pa0.y, pa0.z, pa0.w};
            const float av1[4] = {pa1.x, pa1.y, pa1.z, pa1.w};
            #pragma unroll
            for (int j = 0; j < 4; j++) {
                Ab[(ac4 + j) * AP + am]      = __uint_as_float(f2tf32(av0[j]));
                Ab[(ac4 + j) * AP + am + 64] = __uint_as_float(f2tf32(av1[j]));
            }
            uint4 u0 = {f2tf32(pb0.x), f2tf32(pb0.y), f2tf32(pb0.z), f2tf32(pb0.w)};
            uint4 u1 = {f2tf32(pb1.x), f2tf32(pb1.y), f2tf32(pb1.z), f2tf32(pb1.w)};
            *(uint4*)&Bb[brw * AP + bn4]       = u0;
            *(uint4*)&Bb[(brw + 8) * AP + bn4] = u1;
            __syncthreads();
        }
    }

    if (!TRANSC) {
        #pragma unroll
        for (int mt = 0; mt < 2; mt++) {
            #pragma unroll
            for (int nt = 0; nt < 8; nt++) {
                const int row = by * 128 + wm + mt * 16 + g;
                const int col = bx * 128 + wn + nt * 8 + t * 2;
                float2 v01 = make_float2(c[mt][nt][0], c[mt][nt][1]);
                float2 v23 = make_float2(c[mt][nt][2], c[mt][nt][3]);
                *(float2*)&C[(size_t)row * N + col]       = v01;
                *(float2*)&C[(size_t)(row + 8) * N + col] = v23;
            }
        }
    } else {
        __syncthreads();
        float* Cs = sh;   // 128 x 129
        #pragma unroll
        for (int mt = 0; mt < 2; mt++) {
            #pragma unroll
            for (int nt = 0; nt < 8; nt++) {
                const int r  = wm + mt * 16 + g;
                const int cl = wn + nt * 8 + t * 2;
                Cs[r * 129 + cl]           = c[mt][nt][0];
                Cs[r * 129 + cl + 1]       = c[mt][nt][1];
                Cs[(r + 8) * 129 + cl]     = c[mt][nt][2];
                Cs[(r + 8) * 129 + cl + 1] = c[mt][nt][3];
            }
        }
        __syncthreads();
        #pragma unroll
        for (int r = 0; r < 16; r++) {
            const int i  = tid + 256 * r;
            const int n  = i >> 5;
            const int m4 = (i & 31) << 2;
            float4 v;
            v.x = Cs[(m4 + 0) * 129 + n];
            v.y = Cs[(m4 + 1) * 129 + n];
            v.z = Cs[(m4 + 2) * 129 + n];
            v.w = Cs[(m4 + 3) * 129 + n];
            *(float4*)&C[(size_t)(bx * 128 + n) * M + by * 128 + m4] = v;
        }
    }
}

// ---------------- Split-bf16 tensor-core flash attention --------------------
// 128 threads (4 warps), q tile 64 rows, kv tiles of 64. Each warp: 16 q-rows
// x 64 cols. Smem 90112 B -> 2 CTAs/SM: two independent barrier domains
// overlap (one CTA's softmax hides the other's MMAs).
// Plane strides in uint32 units (pads keep all LDS conflict-free):
#define QP 72                               // Q [d2=64][m=64]
#define KP 72                               // K [d2=64][n=64]
#define VP 136                              // V [k2=32][n=128]
#define PP 36                               // P [m=64][k2=32]
#define SM_QHI 0
#define SM_QLO (64 * QP)                    // 4608
#define SM_KHI (2 * 64 * QP)                // 9216
#define SM_KLO (SM_KHI + 64 * KP)           // 13824
#define SM_VHI SM_KHI                       // overlays K (sequenced)
#define SM_VLO (SM_VHI + 32 * VP)           // 13568
#define SM_PHI (SM_VLO + 32 * VP)           // 17920 (overlays KLO tail, sequenced)
#define SM_PLO (SM_PHI + 64 * PP)           // 20224
#define ATT_SMEM_U32 (SM_PLO + 64 * PP)     // 22528
#define ATT_SMEM (ATT_SMEM_U32 * 4)         // 90112 B

#define ATT_THREADS 128

__global__ __launch_bounds__(ATT_THREADS, 2)
void attn_kernel(const float* __restrict__ QT, const float* __restrict__ KT,
                 const float* __restrict__ V, float* __restrict__ O) {
    extern __shared__ uint32_t smu[];
    uint32_t* Qhi = smu + SM_QHI;
    uint32_t* Qlo = smu + SM_QLO;
    uint32_t* Khi = smu + SM_KHI;
    uint32_t* Klo = smu + SM_KLO;
    uint32_t* Vhi = smu + SM_VHI;
    uint32_t* Vlo = smu + SM_VLO;
    uint32_t* Phi = smu + SM_PHI;
    uint32_t* Plo = smu + SM_PLO;

    const int tid  = threadIdx.x;
    const int lane = tid & 31;
    const int g    = lane >> 2;         // 0..7
    const int lt   = lane & 3;          // 0..3
    const int warp = tid >> 5;          // 0..3
    const int m0   = warp * 16;         // warp's q-row block (within 64)
    const int bh   = blockIdx.y;
    const int b    = bh >> 4;
    const int h    = bh & 15;
    const int kvh  = h >> 2;
    const int bxe  = gridDim.x - 1 - blockIdx.x;   // heavy tiles first
    const int q0   = bxe * 64;

    // ---- load Q tile, split into hi/lo bf16x2 planes [d2=64][m=64] ----
    for (int i = tid; i < 64 * 16; i += ATT_THREADS) {
        int d2 = i >> 4;
        int m4 = (i & 15) << 2;
        const float* pa = &QT[(size_t)(h * HDIM + 2 * d2) * MTOT + b * SEQ + q0 + m4];
        float4 qa = *(const float4*)pa;
        float4 qb = *(const float4*)(pa + MTOT);
        const float fa[4] = {qa.x, qa.y, qa.z, qa.w};
        const float fb[4] = {qb.x, qb.y, qb.z, qb.w};
        uint32_t hi[4], lo[4];
        #pragma unroll
        for (int j = 0; j < 4; j++) {
            float ah = bf16rd(fa[j]);
            float bh_ = bf16rd(fb[j]);
            hi[j] = pack2bf(ah, bh_);
            lo[j] = pack2bf(fa[j] - ah, fb[j] - bh_);
        }
        *(uint4*)&Qhi[d2 * QP + m4] = make_uint4(hi[0], hi[1], hi[2], hi[3]);
        *(uint4*)&Qlo[d2 * QP + m4] = make_uint4(lo[0], lo[1], lo[2], lo[3]);
    }

    float m_s[2] = {-1e30f, -1e30f};
    float l_s[2] = {0.f, 0.f};
    float o[16][4];
    #pragma unroll
    for (int nt = 0; nt < 16; nt++)
        #pragma unroll
        for (int r = 0; r < 4; r++) o[nt][r] = 0.f;

    const float scale = 0.08838834764831845f;   // 1/sqrt(128)
    const int ntk = bxe + 1;
    const int row0 = q0 + m0 + g;               // global q row (and +8)

    for (int tt = 0; tt < ntk; tt++) {
        const int k0 = tt * 64;
        __syncthreads();     // prev PV done reading V/P before K overwrite

        // ---- load K tile [d2=64][n=64], split hi/lo ----
        for (int i = tid; i < 64 * 16; i += ATT_THREADS) {
            int d2 = i >> 4;
            int n4 = (i & 15) << 2;
            const float* pk = &KT[(size_t)(kvh * HDIM + 2 * d2) * MTOT + b * SEQ + k0 + n4];
            float4 ka = *(const float4*)pk;
            float4 kb = *(const float4*)(pk + MTOT);
            const float fa[4] = {ka.x, ka.y, ka.z, ka.w};
            const float fb[4] = {kb.x, kb.y, kb.z, kb.w};
            uint32_t hi[4], lo[4];
            #pragma unroll
            for (int j = 0; j < 4; j++) {
                float ah = bf16rd(fa[j]);
                float bh_ = bf16rd(fb[j]);
                hi[j] = pack2bf(ah, bh_);
                lo[j] = pack2bf(fa[j] - ah, fb[j] - bh_);
            }
            *(uint4*)&Khi[d2 * KP + n4] = make_uint4(hi[0], hi[1], hi[2], hi[3]);
            *(uint4*)&Klo[d2 * KP + n4] = make_uint4(lo[0], lo[1], lo[2], lo[3]);
        }
        __syncthreads();

        // ---- S = Q K^T : 8 k16 steps, 3 MMAs each ----
        float s[8][4];
        #pragma unroll
        for (int nt = 0; nt < 8; nt++)
            #pragma unroll
            for (int r = 0; r < 4; r++) s[nt][r] = 0.f;

        #pragma unroll 4
        for (int ks = 0; ks < 8; ks++) {
            const int kb = ks * 8;
            uint32_t ah[4], al[4];
            ah[0] = Qhi[(kb + lt) * QP + m0 + g];
            ah[1] = Qhi[(kb + lt) * QP + m0 + g + 8];
            ah[2] = Qhi[(kb + lt + 4) * QP + m0 + g];
            ah[3] = Qhi[(kb + lt + 4) * QP + m0 + g + 8];
            al[0] = Qlo[(kb + lt) * QP + m0 + g];
            al[1] = Qlo[(kb + lt) * QP + m0 + g + 8];
            al[2] = Qlo[(kb + lt + 4) * QP + m0 + g];
            al[3] = Qlo[(kb + lt + 4) * QP + m0 + g + 8];
            #pragma unroll
            for (int nt = 0; nt < 8; nt++) {
                const int n0 = nt * 8 + g;
                uint32_t bh_[2], bl_[2];
                bh_[0] = Khi[(kb + lt) * KP + n0];
                bh_[1] = Khi[(kb + lt + 4) * KP + n0];
                bl_[0] = Klo[(kb + lt) * KP + n0];
                bl_[1] = Klo[(kb + lt + 4) * KP + n0];
                mma_bf16(s[nt], ah, bh_);
                mma_bf16(s[nt], al, bh_);
                mma_bf16(s[nt], ah, bl_);
            }
        }

        // ---- online softmax (rows g and g+8, full 64 cols in-warp) ----
        const bool diag = (k0 >= q0);
        #pragma unroll
        for (int nt = 0; nt < 8; nt++) {
            const int c0 = k0 + nt * 8 + 2 * lt;
            float v0 = s[nt][0] * scale;
            float v1 = s[nt][1] * scale;
            float v2 = s[nt][2] * scale;
            float v3 = s[nt][3] * scale;
            if (diag) {
                if (c0     > row0)     v0 = -1e30f;
                if (c0 + 1 > row0)     v1 = -1e30f;
                if (c0     > row0 + 8) v2 = -1e30f;
                if (c0 + 1 > row0 + 8) v3 = -1e30f;
            }
            s[nt][0] = v0; s[nt][1] = v1; s[nt][2] = v2; s[nt][3] = v3;
        }
        float mx0 = -1e30f, mx1 = -1e30f;
        #pragma unroll
        for (int nt = 0; nt < 8; nt++) {
            mx0 = fmaxf(mx0, fmaxf(s[nt][0], s[nt][1]));
            mx1 = fmaxf(mx1, fmaxf(s[nt][2], s[nt][3]));
        }
        mx0 = fmaxf(mx0, __shfl_xor_sync(0xffffffffu, mx0, 1));
        mx0 = fmaxf(mx0, __shfl_xor_sync(0xffffffffu, mx0, 2));
        mx1 = fmaxf(mx1, __shfl_xor_sync(0xffffffffu, mx1, 1));
        mx1 = fmaxf(mx1, __shfl_xor_sync(0xffffffffu, mx1, 2));

        const float mn0 = fmaxf(m_s[0], mx0);
        const float mn1 = fmaxf(m_s[1], mx1);
        const float cr0 = __expf(m_s[0] - mn0);
        const float cr1 = __expf(m_s[1] - mn1);
        float rs0 = 0.f, rs1 = 0.f;
        #pragma unroll
        for (int nt = 0; nt < 8; nt++) {
            s[nt][0] = __expf(s[nt][0] - mn0);
            s[nt][1] = __expf(s[nt][1] - mn0);
            s[nt][2] = __expf(s[nt][2] - mn1);
            s[nt][3] = __expf(s[nt][3] - mn1);
            rs0 += s[nt][0] + s[nt][1];
            rs1 += s[nt][2] + s[nt][3];
        }
        rs0 += __shfl_xor_sync(0xffffffffu, rs0, 1);
        rs0 += __shfl_xor_sync(0xffffffffu, rs0, 2);
        rs1 += __shfl_xor_sync(0xffffffffu, rs1, 1);
        rs1 += __shfl_xor_sync(0xffffffffu, rs1, 2);
        l_s[0] = l_s[0] * cr0 + rs0;  m_s[0] = mn0;
        l_s[1] = l_s[1] * cr1 + rs1;  m_s[1] = mn1;
        #pragma unroll
        for (int nt = 0; nt < 16; nt++) {
            o[nt][0] *= cr0; o[nt][1] *= cr0;
            o[nt][2] *= cr1; o[nt][3] *= cr1;
        }

        __syncthreads();    // all warps done reading K before V/P overwrite

        // ---- store P split hi/lo (packed pairs along k), rows g and g+8 ----
        #pragma unroll
        for (int nt = 0; nt < 8; nt++) {
            const int kc = nt * 4 + lt;     // pair index
            float h0 = bf16rd(s[nt][0]), h1 = bf16rd(s[nt][1]);
            float h2 = bf16rd(s[nt][2]), h3 = bf16rd(s[nt][3]);
            Phi[(m0 + g) * PP + kc]     = pack2bf(h0, h1);
            Plo[(m0 + g) * PP + kc]     = pack2bf(s[nt][0] - h0, s[nt][1] - h1);
            Phi[(m0 + g + 8) * PP + kc] = pack2bf(h2, h3);
            Plo[(m0 + g + 8) * PP + kc] = pack2bf(s[nt][2] - h2, s[nt][3] - h3);
        }

        // ---- load V tile [k2=32][n=128], split hi/lo ----
        for (int i = tid; i < 32 * 32; i += ATT_THREADS) {
            int k2 = i >> 5;
            int c4 = (i & 31) << 2;
            const float* pv = &V[(size_t)(b * SEQ + k0 + 2 * k2) * KVDIM + kvh * HDIM + c4];
            float4 va = *(const float4*)pv;
            float4 vb = *(const float4*)(pv + KVDIM);
            const float fa[4] = {va.x, va.y, va.z, va.w};
            const float fb[4] = {vb.x, vb.y, vb.z, vb.w};
            uint32_t hi[4], lo[4];
            #pragma unroll
            for (int j = 0; j < 4; j++) {
                float ah = bf16rd(fa[j]);
                float bh_ = bf16rd(fb[j]);
                hi[j] = pack2bf(ah, bh_);
                lo[j] = pack2bf(fa[j] - ah, fb[j] - bh_);
            }
            *(uint4*)&Vhi[k2 * VP + c4] = make_uint4(hi[0], hi[1], hi[2], hi[3]);
            *(uint4*)&Vlo[k2 * VP + c4] = make_uint4(lo[0], lo[1], lo[2], lo[3]);
        }
        __syncthreads();

        // ---- O += P V : 4 k16 steps, 3 MMAs each ----
        #pragma unroll 2
        for (int ks = 0; ks < 4; ks++) {
            const int kb = ks * 8;
            uint32_t ph[4], pl[4];
            ph[0] = Phi[(m0 + g) * PP + kb + lt];
            ph[1] = Phi[(m0 + g + 8) * PP + kb + lt];
            ph[2] = Phi[(m0 + g) * PP + kb + 4 + lt];
            ph[3] = Phi[(m0 + g + 8) * PP + kb + 4 + lt];
            pl[0] = Plo[(m0 + g) * PP + kb + lt];
            pl[1] = Plo[(m0 + g + 8) * PP + kb + lt];
            pl[2] = Plo[(m0 + g) * PP + kb + 4 + lt];
            pl[3] = Plo[(m0 + g + 8) * PP + kb + 4 + lt];
            #pragma unroll
            for (int nt = 0; nt < 16; nt++) {
                const int n0 = nt * 8 + g;
                uint32_t vh[2], vl[2];
                vh[0] = Vhi[(kb + lt) * VP + n0];
                vh[1] = Vhi[(kb + 4 + lt) * VP + n0];
                vl[0] = Vlo[(kb + lt) * VP + n0];
                vl[1] = Vlo[(kb + 4 + lt) * VP + n0];
                mma_bf16(o[nt], ph, vh);
                mma_bf16(o[nt], pl, vh);
                mma_bf16(o[nt], ph, vl);
            }
        }
    }

    // ---- epilogue: normalize, store ----
    const float inv0 = 1.f / l_s[0];
    const float inv1 = 1.f / l_s[1];
    #pragma unroll
    for (int nt = 0; nt < 16; nt++) {
        const int col = h * HDIM + nt * 8 + 2 * lt;
        float2 v01 = make_float2(o[nt][0] * inv0, o[nt][1] * inv0);
        float2 v23 = make_float2(o[nt][2] * inv1, o[nt][3] * inv1);
        *(float2*)&O[(size_t)(b * SEQ + q0 + m0 + g) * DMODEL + col]     = v01;
        *(float2*)&O[(size_t)(b * SEQ + q0 + m0 + g + 8) * DMODEL + col] = v23;
    }
}

// ---------------- launch -----------------------------------------------------
extern "C" void kernel_launch(void* const* d_in, const int* in_sizes, int n_in,
                              void* d_out, int out_size) {
    const float* x  = (const float*)d_in[0];
    const float* wq = (const float*)d_in[1];
    const float* wk = (const float*)d_in[2];
    const float* wv = (const float*)d_in[3];
    const float* wo = (const float*)d_in[4];
    float* out = (float*)d_out;

    float *qT, *kT, *v, *att;
    cudaGetSymbolAddress((void**)&qT,  g_qT);
    cudaGetSymbolAddress((void**)&kT,  g_kT);
    cudaGetSymbolAddress((void**)&v,   g_v);
    cudaGetSymbolAddress((void**)&att, g_att);

    cudaFuncSetAttribute(attn_kernel, cudaFuncAttributeMaxDynamicSharedMemorySize, ATT_SMEM);
    cudaFuncSetAttribute(tf32_gemm<true>,  cudaFuncAttributeMaxDynamicSharedMemorySize, TRANS_SMEM);
    cudaFuncSetAttribute(tf32_gemm<false>, cudaFuncAttributeMaxDynamicSharedMemorySize, KLOOP_SMEM);

    dim3 blk(256);
    tf32_gemm<true><<<dim3(DMODEL / 128, MTOT / 128), blk, TRANS_SMEM>>>(x, wq, qT, MTOT, DMODEL, DMODEL);
    tf32_gemm<true><<<dim3(KVDIM / 128, MTOT / 128), blk, TRANS_SMEM>>>(x, wk, kT, MTOT, KVDIM, DMODEL);
    tf32_gemm<false><<<dim3(KVDIM / 128, MTOT / 128), blk, KLOOP_SMEM>>>(x, wv, v, MTOT, KVDIM, DMODEL);
    // attention: 32 q-tiles (64 rows each) x 32 (batch,head), 128 thr, 2 CTA/SM
    attn_kernel<<<dim3(SEQ / 64, BATCH * NHEADS), dim3(ATT_THREADS), ATT_SMEM>>>(qT, kT, v, att);
    tf32_gemm<false><<<dim3(DMODEL / 128, MTOT / 128), blk, KLOOP_SMEM>>>(att, wo, out, MTOT, DMODEL, DMODEL);
}

// round 12
// speedup vs baseline: 9.8275x; 1.0926x over previous
#include <cuda_runtime.h>
#include <cuda_bf16.h>
#include <math.h>
#include <stdint.h>

// Problem constants
#define BATCH    2
#define SEQ      2048
#define DMODEL   2048
#define NHEADS   16
#define NKV      4
#define HDIM     128
#define NREP     4
#define MTOT     (BATCH * SEQ)          // 4096
#define KVDIM    (NKV * HDIM)           // 512

// ---------------- scratch (device globals; no allocation allowed) -----------
__device__ float g_qT[DMODEL * MTOT];    // Q^T: [h*128+d][b*2048+s]
__device__ float g_kT[KVDIM * MTOT];     // K^T: [kv*128+d][b*2048+s]
__device__ float g_v[MTOT * KVDIM];      // V natural [b*2048+s][kv*128+d]
__device__ float g_att[MTOT * DMODEL];   // attention output, natural

// ---------------- mma helpers ------------------------------------------------
__device__ __forceinline__ uint32_t f2tf32(float x) {
    uint32_t u;
    asm("cvt.rna.tf32.f32 %0, %1;" : "=r"(u) : "f"(x));
    return u;
}

__device__ __forceinline__ void mma_tf32(float c[4], const uint32_t a[4],
                                         const uint32_t b[2]) {
    asm volatile(
        "mma.sync.aligned.m16n8k8.row.col.f32.tf32.tf32.f32 "
        "{%0,%1,%2,%3}, {%4,%5,%6,%7}, {%8,%9}, {%0,%1,%2,%3};\n"
        : "+f"(c[0]), "+f"(c[1]), "+f"(c[2]), "+f"(c[3])
        : "r"(a[0]), "r"(a[1]), "r"(a[2]), "r"(a[3]), "r"(b[0]), "r"(b[1]));
}

__device__ __forceinline__ void mma_bf16(float c[4], const uint32_t a[4],
                                         const uint32_t b[2]) {
    asm volatile(
        "mma.sync.aligned.m16n8k16.row.col.f32.bf16.bf16.f32 "
        "{%0,%1,%2,%3}, {%4,%5,%6,%7}, {%8,%9}, {%0,%1,%2,%3};\n"
        : "+f"(c[0]), "+f"(c[1]), "+f"(c[2]), "+f"(c[3])
        : "r"(a[0]), "r"(a[1]), "r"(a[2]), "r"(a[3]), "r"(b[0]), "r"(b[1]));
}

__device__ __forceinline__ uint32_t pack2bf(float x, float y) {
    __nv_bfloat162 h = __floats2bfloat162_rn(x, y);   // x -> low half (even k)
    return *reinterpret_cast<uint32_t*>(&h);
}
__device__ __forceinline__ float bf16rd(float x) {
    return __bfloat162float(__float2bfloat16_rn(x));
}

// ---------------- tf32 tensor-core projection GEMM --------------------------
// 128x128x16 CTA tile, 128 threads (4 warps, 64x64 each), 2 CTAs/SM.
// A smem: stride 136 + XOR swizzle -> conflict-free STS *and* fragment LDS.
// B smem: stride 136 linear (float4 STS conflict-free; LDS 8t+g pattern).
#define AP 136
#define ASW(k, m) ((k) * AP + ((m) ^ (((((k) >> 2) & 3)) << 3)))
#define KLOOP_SMEM   (2 * 2 * 16 * AP * 4)      // 34816 B
#define TRANS_SMEM   (128 * 129 * 4)            // 66048 B

template <bool TRANSC>
__global__ __launch_bounds__(128, 2)
void tf32_gemm(const float* __restrict__ A, const float* __restrict__ B,
               float* __restrict__ C, int M, int N, int K) {
    extern __shared__ float sh[];
    float* As = sh;                    // 2 bufs x 16 x AP  (swizzled [k][m])
    float* Bs = sh + 2 * 16 * AP;      // 2 bufs x 16 x AP  (linear   [k][n])

    const int tid  = threadIdx.x;
    const int lane = tid & 31;
    const int g    = lane >> 2;
    const int t    = lane & 3;
    const int warp = tid >> 5;          // 0..3
    const int wm   = (warp & 1) * 64;
    const int wn   = (warp >> 1) * 64;
    const int bx   = blockIdx.x;
    const int by   = blockIdx.y;

    // global load anchors (128 threads)
    const int am  = tid >> 2;                // 0..31 (+32,+64,+96)
    const int ac4 = (tid & 3) * 4;           // k offset 0/4/8/12
    const int brw = tid >> 5;                // 0..3 (+4,+8,+12)
    const int bn4 = (tid & 31) * 4;
    const float* Ag = A + (size_t)(by * 128 + am) * K + ac4;
    const float* Bg = B + (size_t)brw * N + bx * 128 + bn4;

    float c[4][8][4];
    #pragma unroll
    for (int mt = 0; mt < 4; mt++)
        #pragma unroll
        for (int nt = 0; nt < 8; nt++)
            #pragma unroll
            for (int r = 0; r < 4; r++) c[mt][nt][r] = 0.f;

    float4 pa[4], pb[4];
    #pragma unroll
    for (int r = 0; r < 4; r++) {
        pa[r] = *(const float4*)(Ag + (size_t)(32 * r) * K);
        pb[r] = *(const float4*)(Bg + (size_t)(4 * r) * N);
    }

    // stash tile 0 into buffer 0
    {
        float* Ab = As;
        float* Bb = Bs;
        #pragma unroll
        for (int r = 0; r < 4; r++) {
            const float av[4] = {pa[r].x, pa[r].y, pa[r].z, pa[r].w};
            #pragma unroll
            for (int j = 0; j < 4; j++)
                Ab[ASW(ac4 + j, am + 32 * r)] = __uint_as_float(f2tf32(av[j]));
            uint4 u = {f2tf32(pb[r].x), f2tf32(pb[r].y), f2tf32(pb[r].z), f2tf32(pb[r].w)};
            *(uint4*)&Bb[(brw + 4 * r) * AP + bn4] = u;
        }
    }
    __syncthreads();

    const int NT = K >> 4;
    for (int kt = 0; kt < NT; kt++) {
        if (kt + 1 < NT) {
            const float* Ap = Ag + (kt + 1) * 16;
            const float* Bp = Bg + (size_t)(kt + 1) * 16 * N;
            #pragma unroll
            for (int r = 0; r < 4; r++) {
                pa[r] = *(const float4*)(Ap + (size_t)(32 * r) * K);
                pb[r] = *(const float4*)(Bp + (size_t)(4 * r) * N);
            }
        }

        const uint32_t* Au = (const uint32_t*)(As + (kt & 1) * 16 * AP);
        const uint32_t* Bu = (const uint32_t*)(Bs + (kt & 1) * 16 * AP);

        #pragma unroll
        for (int s = 0; s < 2; s++) {
            const int kb = s * 8;
            uint32_t a[4][4], bf[8][2];
            #pragma unroll
            for (int mt = 0; mt < 4; mt++) {
                const int m0 = wm + mt * 16 + g;
                a[mt][0] = Au[ASW(kb + t,     m0)];
                a[mt][1] = Au[ASW(kb + t,     m0 + 8)];
                a[mt][2] = Au[ASW(kb + t + 4, m0)];
                a[mt][3] = Au[ASW(kb + t + 4, m0 + 8)];
            }
            #pragma unroll
            for (int nt = 0; nt < 8; nt++) {
                const int n0 = wn + nt * 8 + g;
                bf[nt][0] = Bu[(kb + t) * AP + n0];
                bf[nt][1] = Bu[(kb + t + 4) * AP + n0];
            }
            #pragma unroll
            for (int mt = 0; mt < 4; mt++)
                #pragma unroll
                for (int nt = 0; nt < 8; nt++)
                    mma_tf32(c[mt][nt], a[mt], bf[nt]);
        }

        if (kt + 1 < NT) {
            float* Ab = As + ((kt + 1) & 1) * 16 * AP;
            float* Bb = Bs + ((kt + 1) & 1) * 16 * AP;
            #pragma unroll
            for (int r = 0; r < 4; r++) {
                const float av[4] = {pa[r].x, pa[r].y, pa[r].z, pa[r].w};
                #pragma unroll
                for (int j = 0; j < 4; j++)
                    Ab[ASW(ac4 + j, am + 32 * r)] = __uint_as_float(f2tf32(av[j]));
                uint4 u = {f2tf32(pb[r].x), f2tf32(pb[r].y), f2tf32(pb[r].z), f2tf32(pb[r].w)};
                *(uint4*)&Bb[(brw + 4 * r) * AP + bn4] = u;
            }
            __syncthreads();
        }
    }

    if (!TRANSC) {
        #pragma unroll
        for (int mt = 0; mt < 4; mt++) {
            #pragma unroll
            for (int nt = 0; nt < 8; nt++) {
                const int row = by * 128 + wm + mt * 16 + g;
                const int col = bx * 128 + wn + nt * 8 + t * 2;
                float2 v01 = make_float2(c[mt][nt][0], c[mt][nt][1]);
                float2 v23 = make_float2(c[mt][nt][2], c[mt][nt][3]);
                *(float2*)&C[(size_t)row * N + col]       = v01;
                *(float2*)&C[(size_t)(row + 8) * N + col] = v23;
            }
        }
    } else {
        __syncthreads();                 // compute done before overlay
        float* Cs = sh;                  // 128 x 129
        #pragma unroll
        for (int mt = 0; mt < 4; mt++) {
            #pragma unroll
            for (int nt = 0; nt < 8; nt++) {
                const int r  = wm + mt * 16 + g;
                const int cl = wn + nt * 8 + t * 2;
                Cs[r * 129 + cl]           = c[mt][nt][0];
                Cs[r * 129 + cl + 1]       = c[mt][nt][1];
                Cs[(r + 8) * 129 + cl]     = c[mt][nt][2];
                Cs[(r + 8) * 129 + cl + 1] = c[mt][nt][3];
            }
        }
        __syncthreads();
        #pragma unroll
        for (int r = 0; r < 32; r++) {
            const int i  = tid + 128 * r;
            const int n  = i >> 5;
            const int m4 = (i & 31) << 2;
            float4 v;
            v.x = Cs[(m4 + 0) * 129 + n];
            v.y = Cs[(m4 + 1) * 129 + n];
            v.z = Cs[(m4 + 2) * 129 + n];
            v.w = Cs[(m4 + 3) * 129 + n];
            *(float4*)&C[(size_t)(bx * 128 + n) * M + by * 128 + m4] = v;
        }
    }
}

// ---------------- Split-bf16 tensor-core flash attention --------------------
// 128 threads (4 warps), q tile 64 rows, kv tiles of 64. 2 CTAs/SM.
#define QP 72                               // Q [d2=64][m=64]
#define KP 72                               // K [d2=64][n=64]
#define VP 136                              // V [k2=32][n=128]
#define PP 36                               // P [m=64][k2=32]
#define SM_QHI 0
#define SM_QLO (64 * QP)                    // 4608
#define SM_KHI (2 * 64 * QP)                // 9216
#define SM_KLO (SM_KHI + 64 * KP)           // 13824
#define SM_VHI SM_KHI                       // overlays K (sequenced)
#define SM_VLO (SM_VHI + 32 * VP)           // 13568
#define SM_PHI (SM_VLO + 32 * VP)           // 17920
#define SM_PLO (SM_PHI + 64 * PP)           // 20224
#define ATT_SMEM_U32 (SM_PLO + 64 * PP)     // 22528
#define ATT_SMEM (ATT_SMEM_U32 * 4)         // 90112 B

#define ATT_THREADS 128

__global__ __launch_bounds__(ATT_THREADS, 2)
void attn_kernel(const float* __restrict__ QT, const float* __restrict__ KT,
                 const float* __restrict__ V, float* __restrict__ O) {
    extern __shared__ uint32_t smu[];
    uint32_t* Qhi = smu + SM_QHI;
    uint32_t* Qlo = smu + SM_QLO;
    uint32_t* Khi = smu + SM_KHI;
    uint32_t* Klo = smu + SM_KLO;
    uint32_t* Vhi = smu + SM_VHI;
    uint32_t* Vlo = smu + SM_VLO;
    uint32_t* Phi = smu + SM_PHI;
    uint32_t* Plo = smu + SM_PLO;

    const int tid  = threadIdx.x;
    const int lane = tid & 31;
    const int g    = lane >> 2;         // 0..7
    const int lt   = lane & 3;          // 0..3
    const int warp = tid >> 5;          // 0..3
    const int m0   = warp * 16;         // warp's q-row block (within 64)
    const int bh   = blockIdx.y;
    const int b    = bh >> 4;
    const int h    = bh & 15;
    const int kvh  = h >> 2;
    const int bxe  = gridDim.x - 1 - blockIdx.x;   // heavy tiles first
    const int q0   = bxe * 64;

    // ---- load Q tile, split into hi/lo bf16x2 planes [d2=64][m=64] ----
    for (int i = tid; i < 64 * 16; i += ATT_THREADS) {
        int d2 = i >> 4;
        int m4 = (i & 15) << 2;
        const float* pa = &QT[(size_t)(h * HDIM + 2 * d2) * MTOT + b * SEQ + q0 + m4];
        float4 qa = *(const float4*)pa;
        float4 qb = *(const float4*)(pa + MTOT);
        const float fa[4] = {qa.x, qa.y, qa.z, qa.w};
        const float fb[4] = {qb.x, qb.y, qb.z, qb.w};
        uint32_t hi[4], lo[4];
        #pragma unroll
        for (int j = 0; j < 4; j++) {
            float ah = bf16rd(fa[j]);
            float bh_ = bf16rd(fb[j]);
            hi[j] = pack2bf(ah, bh_);
            lo[j] = pack2bf(fa[j] - ah, fb[j] - bh_);
        }
        *(uint4*)&Qhi[d2 * QP + m4] = make_uint4(hi[0], hi[1], hi[2], hi[3]);
        *(uint4*)&Qlo[d2 * QP + m4] = make_uint4(lo[0], lo[1], lo[2], lo[3]);
    }

    float m_s[2] = {-1e30f, -1e30f};
    float l_s[2] = {0.f, 0.f};
    float o[16][4];
    #pragma unroll
    for (int nt = 0; nt < 16; nt++)
        #pragma unroll
        for (int r = 0; r < 4; r++) o[nt][r] = 0.f;

    const float scale = 0.08838834764831845f;   // 1/sqrt(128)
    const int ntk = bxe + 1;
    const int row0 = q0 + m0 + g;               // global q row (and +8)

    for (int tt = 0; tt < ntk; tt++) {
        const int k0 = tt * 64;
        __syncthreads();     // prev PV done reading V/P before K overwrite

        // ---- load K tile [d2=64][n=64], split hi/lo ----
        for (int i = tid; i < 64 * 16; i += ATT_THREADS) {
            int d2 = i >> 4;
            int n4 = (i & 15) << 2;
            const float* pk = &KT[(size_t)(kvh * HDIM + 2 * d2) * MTOT + b * SEQ + k0 + n4];
            float4 ka = *(const float4*)pk;
            float4 kb = *(const float4*)(pk + MTOT);
            const float fa[4] = {ka.x, ka.y, ka.z, ka.w};
            const float fb[4] = {kb.x, kb.y, kb.z, kb.w};
            uint32_t hi[4], lo[4];
            #pragma unroll
            for (int j = 0; j < 4; j++) {
                float ah = bf16rd(fa[j]);
                float bh_ = bf16rd(fb[j]);
                hi[j] = pack2bf(ah, bh_);
                lo[j] = pack2bf(fa[j] - ah, fb[j] - bh_);
            }
            *(uint4*)&Khi[d2 * KP + n4] = make_uint4(hi[0], hi[1], hi[2], hi[3]);
            *(uint4*)&Klo[d2 * KP + n4] = make_uint4(lo[0], lo[1], lo[2], lo[3]);
        }
        __syncthreads();

        // ---- S = Q K^T : 8 k16 steps, 3 MMAs each ----
        float s[8][4];
        #pragma unroll
        for (int nt = 0; nt < 8; nt++)
            #pragma unroll
            for (int r = 0; r < 4; r++) s[nt][r] = 0.f;

        #pragma unroll 4
        for (int ks = 0; ks < 8; ks++) {
            const int kb = ks * 8;
            uint32_t ah[4], al[4];
            ah[0] = Qhi[(kb + lt) * QP + m0 + g];
            ah[1] = Qhi[(kb + lt) * QP + m0 + g + 8];
            ah[2] = Qhi[(kb + lt + 4) * QP + m0 + g];
            ah[3] = Qhi[(kb + lt + 4) * QP + m0 + g + 8];
            al[0] = Qlo[(kb + lt) * QP + m0 + g];
            al[1] = Qlo[(kb + lt) * QP + m0 + g + 8];
            al[2] = Qlo[(kb + lt + 4) * QP + m0 + g];
            al[3] = Qlo[(kb + lt + 4) * QP + m0 + g + 8];
            #pragma unroll
            for (int nt = 0; nt < 8; nt++) {
                const int n0 = nt * 8 + g;
                uint32_t bh_[2], bl_[2];
                bh_[0] = Khi[(kb + lt) * KP + n0];
                bh_[1] = Khi[(kb + lt + 4) * KP + n0];
                bl_[0] = Klo[(kb + lt) * KP + n0];
                bl_[1] = Klo[(kb + lt + 4) * KP + n0];
                mma_bf16(s[nt], ah, bh_);
                mma_bf16(s[nt], al, bh_);
                mma_bf16(s[nt], ah, bl_);
            }
        }

        // ---- online softmax (rows g and g+8, full 64 cols in-warp) ----
        const bool diag = (k0 >= q0);
        #pragma unroll
        for (int nt = 0; nt < 8; nt++) {
            const int c0 = k0 + nt * 8 + 2 * lt;
            float v0 = s[nt][0] * scale;
            float v1 = s[nt][1] * scale;
            float v2 = s[nt][2] * scale;
            float v3 = s[nt][3] * scale;
            if (diag) {
                if (c0     > row0)     v0 = -1e30f;
                if (c0 + 1 > row0)     v1 = -1e30f;
                if (c0     > row0 + 8) v2 = -1e30f;
                if (c0 + 1 > row0 + 8) v3 = -1e30f;
            }
            s[nt][0] = v0; s[nt][1] = v1; s[nt][2] = v2; s[nt][3] = v3;
        }
        float mx0 = -1e30f, mx1 = -1e30f;
        #pragma unroll
        for (int nt = 0; nt < 8; nt++) {
            mx0 = fmaxf(mx0, fmaxf(s[nt][0], s[nt][1]));
            mx1 = fmaxf(mx1, fmaxf(s[nt][2], s[nt][3]));
        }
        mx0 = fmaxf(mx0, __shfl_xor_sync(0xffffffffu, mx0, 1));
        mx0 = fmaxf(mx0, __shfl_xor_sync(0xffffffffu, mx0, 2));
        mx1 = fmaxf(mx1, __shfl_xor_sync(0xffffffffu, mx1, 1));
        mx1 = fmaxf(mx1, __shfl_xor_sync(0xffffffffu, mx1, 2));

        const float mn0 = fmaxf(m_s[0], mx0);
        const float mn1 = fmaxf(m_s[1], mx1);
        const float cr0 = __expf(m_s[0] - mn0);
        const float cr1 = __expf(m_s[1] - mn1);
        float rs0 = 0.f, rs1 = 0.f;
        #pragma unroll
        for (int nt = 0; nt < 8; nt++) {
            s[nt][0] = __expf(s[nt][0] - mn0);
            s[nt][1] = __expf(s[nt][1] - mn0);
            s[nt][2] = __expf(s[nt][2] - mn1);
            s[nt][3] = __expf(s[nt][3] - mn1);
            rs0 += s[nt][0] + s[nt][1];
            rs1 += s[nt][2] + s[nt][3];
        }
        rs0 += __shfl_xor_sync(0xffffffffu, rs0, 1);
        rs0 += __shfl_xor_sync(0xffffffffu, rs0, 2);
        rs1 += __shfl_xor_sync(0xffffffffu, rs1, 1);
        rs1 += __shfl_xor_sync(0xffffffffu, rs1, 2);
        l_s[0] = l_s[0] * cr0 + rs0;  m_s[0] = mn0;
        l_s[1] = l_s[1] * cr1 + rs1;  m_s[1] = mn1;
        #pragma unroll
        for (int nt = 0; nt < 16; nt++) {
            o[nt][0] *= cr0; o[nt][1] *= cr0;
            o[nt][2] *= cr1; o[nt][3] *= cr1;
        }

        __syncthreads();    // all warps done reading K before V/P overwrite

        // ---- store P split hi/lo (packed pairs along k), rows g and g+8 ----
        #pragma unroll
        for (int nt = 0; nt < 8; nt++) {
            const int kc = nt * 4 + lt;     // pair index
            float h0 = bf16rd(s[nt][0]), h1 = bf16rd(s[nt][1]);
            float h2 = bf16rd(s[nt][2]), h3 = bf16rd(s[nt][3]);
            Phi[(m0 + g) * PP + kc]     = pack2bf(h0, h1);
            Plo[(m0 + g) * PP + kc]     = pack2bf(s[nt][0] - h0, s[nt][1] - h1);
            Phi[(m0 + g + 8) * PP + kc] = pack2bf(h2, h3);
            Plo[(m0 + g + 8) * PP + kc] = pack2bf(s[nt][2] - h2, s[nt][3] - h3);
        }

        // ---- load V tile [k2=32][n=128], split hi/lo ----
        for (int i = tid; i < 32 * 32; i += ATT_THREADS) {
            int k2 = i >> 5;
            int c4 = (i & 31) << 2;
            const float* pv = &V[(size_t)(b * SEQ + k0 + 2 * k2) * KVDIM + kvh * HDIM + c4];
            float4 va = *(const float4*)pv;
            float4 vb = *(const float4*)(pv + KVDIM);
            const float fa[4] = {va.x, va.y, va.z, va.w};
            const float fb[4] = {vb.x, vb.y, vb.z, vb.w};
            uint32_t hi[4], lo[4];
            #pragma unroll
            for (int j = 0; j < 4; j++) {
                float ah = bf16rd(fa[j]);
                float bh_ = bf16rd(fb[j]);
                hi[j] = pack2bf(ah, bh_);
                lo[j] = pack2bf(fa[j] - ah, fb[j] - bh_);
            }
            *(uint4*)&Vhi[k2 * VP + c4] = make_uint4(hi[0], hi[1], hi[2], hi[3]);
            *(uint4*)&Vlo[k2 * VP + c4] = make_uint4(lo[0], lo[1], lo[2], lo[3]);
        }
        __syncthreads();

        // ---- O += P V : 4 k16 steps, 3 MMAs each ----
        #pragma unroll 2
        for (int ks = 0; ks < 4; ks++) {
            const int kb = ks * 8;
            uint32_t ph[4], pl[4];
            ph[0] = Phi[(m0 + g) * PP + kb + lt];
            ph[1] = Phi[(m0 + g + 8) * PP + kb + lt];
            ph[2] = Phi[(m0 + g) * PP + kb + 4 + lt];
            ph[3] = Phi[(m0 + g + 8) * PP + kb + 4 + lt];
            pl[0] = Plo[(m0 + g) * PP + kb + lt];
            pl[1] = Plo[(m0 + g + 8) * PP + kb + lt];
            pl[2] = Plo[(m0 + g) * PP + kb + 4 + lt];
            pl[3] = Plo[(m0 + g + 8) * PP + kb + 4 + lt];
            #pragma unroll
            for (int nt = 0; nt < 16; nt++) {
                const int n0 = nt * 8 + g;
                uint32_t vh[2], vl[2];
                vh[0] = Vhi[(kb + lt) * VP + n0];
                vh[1] = Vhi[(kb + 4 + lt) * VP + n0];
                vl[0] = Vlo[(kb + lt) * VP + n0];
                vl[1] = Vlo[(kb + 4 + lt) * VP + n0];
                mma_bf16(o[nt], ph, vh);
                mma_bf16(o[nt], pl, vh);
                mma_bf16(o[nt], ph, vl);
            }
        }
    }

    // ---- epilogue: normalize, store ----
    const float inv0 = 1.f / l_s[0];
    const float inv1 = 1.f / l_s[1];
    #pragma unroll
    for (int nt = 0; nt < 16; nt++) {
        const int col = h * HDIM + nt * 8 + 2 * lt;
        float2 v01 = make_float2(o[nt][0] * inv0, o[nt][1] * inv0);
        float2 v23 = make_float2(o[nt][2] * inv1, o[nt][3] * inv1);
        *(float2*)&O[(size_t)(b * SEQ + q0 + m0 + g) * DMODEL + col]     = v01;
        *(float2*)&O[(size_t)(b * SEQ + q0 + m0 + g + 8) * DMODEL + col] = v23;
    }
}

// ---------------- launch -----------------------------------------------------
extern "C" void kernel_launch(void* const* d_in, const int* in_sizes, int n_in,
                              void* d_out, int out_size) {
    const float* x  = (const float*)d_in[0];
    const float* wq = (const float*)d_in[1];
    const float* wk = (const float*)d_in[2];
    const float* wv = (const float*)d_in[3];
    const float* wo = (const float*)d_in[4];
    float* out = (float*)d_out;

    float *qT, *kT, *v, *att;
    cudaGetSymbolAddress((void**)&qT,  g_qT);
    cudaGetSymbolAddress((void**)&kT,  g_kT);
    cudaGetSymbolAddress((void**)&v,   g_v);
    cudaGetSymbolAddress((void**)&att, g_att);

    cudaFuncSetAttribute(attn_kernel, cudaFuncAttributeMaxDynamicSharedMemorySize, ATT_SMEM);
    cudaFuncSetAttribute(tf32_gemm<true>,  cudaFuncAttributeMaxDynamicSharedMemorySize, TRANS_SMEM);
    cudaFuncSetAttribute(tf32_gemm<false>, cudaFuncAttributeMaxDynamicSharedMemorySize, KLOOP_SMEM);

    dim3 blk(128);
    tf32_gemm<true><<<dim3(DMODEL / 128, MTOT / 128), blk, TRANS_SMEM>>>(x, wq, qT, MTOT, DMODEL, DMODEL);
    tf32_gemm<true><<<dim3(KVDIM / 128, MTOT / 128), blk, TRANS_SMEM>>>(x, wk, kT, MTOT, KVDIM, DMODEL);
    tf32_gemm<false><<<dim3(KVDIM / 128, MTOT / 128), blk, KLOOP_SMEM>>>(x, wv, v, MTOT, KVDIM, DMODEL);
    attn_kernel<<<dim3(SEQ / 64, BATCH * NHEADS), dim3(ATT_THREADS), ATT_SMEM>>>(qT, kT, v, att);
    tf32_gemm<false><<<dim3(DMODEL / 128, MTOT / 128), blk, KLOOP_SMEM>>>(att, wo, out, MTOT, DMODEL, DMODEL);
}

// round 13
// speedup vs baseline: 10.6405x; 1.0827x over previous
#include <cuda_runtime.h>
#include <cuda_bf16.h>
#include <math.h>
#include <stdint.h>

// Problem constants
#define BATCH    2
#define SEQ      2048
#define DMODEL   2048
#define NHEADS   16
#define NKV      4
#define HDIM     128
#define NREP     4
#define MTOT     (BATCH * SEQ)          // 4096
#define KVDIM    (NKV * HDIM)           // 512

// ---------------- scratch (device globals; no allocation allowed) -----------
__device__ float g_qT[DMODEL * MTOT];    // Q^T: [h*128+d][b*2048+s]
__device__ float g_kT[KVDIM * MTOT];     // K^T: [kv*128+d][b*2048+s]
__device__ float g_v[MTOT * KVDIM];      // V natural [b*2048+s][kv*128+d]
__device__ float g_att[MTOT * DMODEL];   // attention output, natural

// ---------------- mma helpers ------------------------------------------------
__device__ __forceinline__ uint32_t f2tf32(float x) {
    uint32_t u;
    asm("cvt.rna.tf32.f32 %0, %1;" : "=r"(u) : "f"(x));
    return u;
}

__device__ __forceinline__ void mma_tf32(float c[4], const uint32_t a[4],
                                         const uint32_t b[2]) {
    asm volatile(
        "mma.sync.aligned.m16n8k8.row.col.f32.tf32.tf32.f32 "
        "{%0,%1,%2,%3}, {%4,%5,%6,%7}, {%8,%9}, {%0,%1,%2,%3};\n"
        : "+f"(c[0]), "+f"(c[1]), "+f"(c[2]), "+f"(c[3])
        : "r"(a[0]), "r"(a[1]), "r"(a[2]), "r"(a[3]), "r"(b[0]), "r"(b[1]));
}

__device__ __forceinline__ void mma_bf16(float c[4], const uint32_t a[4],
                                         const uint32_t b[2]) {
    asm volatile(
        "mma.sync.aligned.m16n8k16.row.col.f32.bf16.bf16.f32 "
        "{%0,%1,%2,%3}, {%4,%5,%6,%7}, {%8,%9}, {%0,%1,%2,%3};\n"
        : "+f"(c[0]), "+f"(c[1]), "+f"(c[2]), "+f"(c[3])
        : "r"(a[0]), "r"(a[1]), "r"(a[2]), "r"(a[3]), "r"(b[0]), "r"(b[1]));
}

__device__ __forceinline__ uint32_t pack2bf(float x, float y) {
    __nv_bfloat162 h = __floats2bfloat162_rn(x, y);   // x -> low half (even k)
    return *reinterpret_cast<uint32_t*>(&h);
}
__device__ __forceinline__ float bf16rd(float x) {
    return __bfloat162float(__float2bfloat16_rn(x));
}

// ---------------- tf32 tensor-core GEMM core --------------------------------
// 128x128x16 CTA tile, 128 threads (4 warps, 64x64 each), 2 CTAs/SM.
// A smem: stride 136 + XOR swizzle -> conflict-free STS *and* fragment LDS.
// B smem: stride 136 linear.
#define AP 136
#define ASW(k, m) ((k) * AP + ((m) ^ (((((k) >> 2) & 3)) << 3)))
#define KLOOP_SMEM   (2 * 2 * 16 * AP * 4)      // 34816 B
#define TRANS_SMEM   (128 * 129 * 4)            // 66048 B
#define FUSED_SMEM   TRANS_SMEM                 // max of both paths

// Body shared by the fused QKV kernel (runtime transc) and the O kernel.
__device__ __forceinline__
void gemm_body(const float* __restrict__ A, const float* __restrict__ B,
               float* __restrict__ C, int M, int N, int K,
               int bx, int by, bool transc, float* sh) {
    float* As = sh;                    // 2 bufs x 16 x AP  (swizzled [k][m])
    float* Bs = sh + 2 * 16 * AP;      // 2 bufs x 16 x AP  (linear   [k][n])

    const int tid  = threadIdx.x;
    const int lane = tid & 31;
    const int g    = lane >> 2;
    const int t    = lane & 3;
    const int warp = tid >> 5;          // 0..3
    const int wm   = (warp & 1) * 64;
    const int wn   = (warp >> 1) * 64;

    const int am  = tid >> 2;                // 0..31 (+32,+64,+96)
    const int ac4 = (tid & 3) * 4;           // k offset 0/4/8/12
    const int brw = tid >> 5;                // 0..3 (+4,+8,+12)
    const int bn4 = (tid & 31) * 4;
    const float* Ag = A + (size_t)(by * 128 + am) * K + ac4;
    const float* Bg = B + (size_t)brw * N + bx * 128 + bn4;

    float c[4][8][4];
    #pragma unroll
    for (int mt = 0; mt < 4; mt++)
        #pragma unroll
        for (int nt = 0; nt < 8; nt++)
            #pragma unroll
            for (int r = 0; r < 4; r++) c[mt][nt][r] = 0.f;

    float4 pa[4], pb[4];
    #pragma unroll
    for (int r = 0; r < 4; r++) {
        pa[r] = *(const float4*)(Ag + (size_t)(32 * r) * K);
        pb[r] = *(const float4*)(Bg + (size_t)(4 * r) * N);
    }

    {
        float* Ab = As;
        float* Bb = Bs;
        #pragma unroll
        for (int r = 0; r < 4; r++) {
            const float av[4] = {pa[r].x, pa[r].y, pa[r].z, pa[r].w};
            #pragma unroll
            for (int j = 0; j < 4; j++)
                Ab[ASW(ac4 + j, am + 32 * r)] = __uint_as_float(f2tf32(av[j]));
            uint4 u = {f2tf32(pb[r].x), f2tf32(pb[r].y), f2tf32(pb[r].z), f2tf32(pb[r].w)};
            *(uint4*)&Bb[(brw + 4 * r) * AP + bn4] = u;
        }
    }
    __syncthreads();

    const int NT = K >> 4;
    for (int kt = 0; kt < NT; kt++) {
        if (kt + 1 < NT) {
            const float* Ap = Ag + (kt + 1) * 16;
            const float* Bp = Bg + (size_t)(kt + 1) * 16 * N;
            #pragma unroll
            for (int r = 0; r < 4; r++) {
                pa[r] = *(const float4*)(Ap + (size_t)(32 * r) * K);
                pb[r] = *(const float4*)(Bp + (size_t)(4 * r) * N);
            }
        }

        const uint32_t* Au = (const uint32_t*)(As + (kt & 1) * 16 * AP);
        const uint32_t* Bu = (const uint32_t*)(Bs + (kt & 1) * 16 * AP);

        #pragma unroll
        for (int s = 0; s < 2; s++) {
            const int kb = s * 8;
            uint32_t a[4][4], bf[8][2];
            #pragma unroll
            for (int mt = 0; mt < 4; mt++) {
                const int m0 = wm + mt * 16 + g;
                a[mt][0] = Au[ASW(kb + t,     m0)];
                a[mt][1] = Au[ASW(kb + t,     m0 + 8)];
                a[mt][2] = Au[ASW(kb + t + 4, m0)];
                a[mt][3] = Au[ASW(kb + t + 4, m0 + 8)];
            }
            #pragma unroll
            for (int nt = 0; nt < 8; nt++) {
                const int n0 = wn + nt * 8 + g;
                bf[nt][0] = Bu[(kb + t) * AP + n0];
                bf[nt][1] = Bu[(kb + t + 4) * AP + n0];
            }
            #pragma unroll
            for (int mt = 0; mt < 4; mt++)
                #pragma unroll
                for (int nt = 0; nt < 8; nt++)
                    mma_tf32(c[mt][nt], a[mt], bf[nt]);
        }

        if (kt + 1 < NT) {
            float* Ab = As + ((kt + 1) & 1) * 16 * AP;
            float* Bb = Bs + ((kt + 1) & 1) * 16 * AP;
            #pragma unroll
            for (int r = 0; r < 4; r++) {
                const float av[4] = {pa[r].x, pa[r].y, pa[r].z, pa[r].w};
                #pragma unroll
                for (int j = 0; j < 4; j++)
                    Ab[ASW(ac4 + j, am + 32 * r)] = __uint_as_float(f2tf32(av[j]));
                uint4 u = {f2tf32(pb[r].x), f2tf32(pb[r].y), f2tf32(pb[r].z), f2tf32(pb[r].w)};
                *(uint4*)&Bb[(brw + 4 * r) * AP + bn4] = u;
            }
            __syncthreads();
        }
    }

    if (!transc) {
        #pragma unroll
        for (int mt = 0; mt < 4; mt++) {
            #pragma unroll
            for (int nt = 0; nt < 8; nt++) {
                const int row = by * 128 + wm + mt * 16 + g;
                const int col = bx * 128 + wn + nt * 8 + t * 2;
                float2 v01 = make_float2(c[mt][nt][0], c[mt][nt][1]);
                float2 v23 = make_float2(c[mt][nt][2], c[mt][nt][3]);
                *(float2*)&C[(size_t)row * N + col]       = v01;
                *(float2*)&C[(size_t)(row + 8) * N + col] = v23;
            }
        }
    } else {
        __syncthreads();                 // compute done before overlay
        float* Cs = sh;                  // 128 x 129
        #pragma unroll
        for (int mt = 0; mt < 4; mt++) {
            #pragma unroll
            for (int nt = 0; nt < 8; nt++) {
                const int r  = wm + mt * 16 + g;
                const int cl = wn + nt * 8 + t * 2;
                Cs[r * 129 + cl]           = c[mt][nt][0];
                Cs[r * 129 + cl + 1]       = c[mt][nt][1];
                Cs[(r + 8) * 129 + cl]     = c[mt][nt][2];
                Cs[(r + 8) * 129 + cl + 1] = c[mt][nt][3];
            }
        }
        __syncthreads();
        #pragma unroll
        for (int r = 0; r < 32; r++) {
            const int i  = tid + 128 * r;
            const int n  = i >> 5;
            const int m4 = (i & 31) << 2;
            float4 v;
            v.x = Cs[(m4 + 0) * 129 + n];
            v.y = Cs[(m4 + 1) * 129 + n];
            v.z = Cs[(m4 + 2) * 129 + n];
            v.w = Cs[(m4 + 3) * 129 + n];
            *(float4*)&C[(size_t)(bx * 128 + n) * M + by * 128 + m4] = v;
        }
    }
}

// Fused Q/K/V projection: one launch, 24 x 32 CTAs.
//   bx in [0,16)  -> Q  = x @ wq, stored transposed into qT  (N=2048)
//   bx in [16,20) -> K  = x @ wk, stored transposed into kT  (N=512)
//   bx in [20,24) -> V  = x @ wv, stored natural into v      (N=512)
__global__ __launch_bounds__(128, 2)
void qkv_gemm(const float* __restrict__ x,
              const float* __restrict__ wq, const float* __restrict__ wk,
              const float* __restrict__ wv,
              float* __restrict__ qT, float* __restrict__ kT,
              float* __restrict__ v) {
    extern __shared__ float sh[];
    const int bx = blockIdx.x;
    const int by = blockIdx.y;
    const float* B;
    float* C;
    int N, bxl;
    bool transc;
    if (bx < 16)      { B = wq; C = qT; N = DMODEL; bxl = bx;      transc = true;  }
    else if (bx < 20) { B = wk; C = kT; N = KVDIM;  bxl = bx - 16; transc = true;  }
    else              { B = wv; C = v;  N = KVDIM;  bxl = bx - 20; transc = false; }
    gemm_body(x, B, C, MTOT, N, DMODEL, bxl, by, transc, sh);
}

// O projection (natural store only).
__global__ __launch_bounds__(128, 2)
void o_gemm(const float* __restrict__ A, const float* __restrict__ B,
            float* __restrict__ C) {
    extern __shared__ float sh[];
    gemm_body(A, B, C, MTOT, DMODEL, DMODEL, blockIdx.x, blockIdx.y, false, sh);
}

// ---------------- Split-bf16 tensor-core flash attention --------------------
// 128 threads (4 warps), q tile 64 rows, kv tiles of 64. 2 CTAs/SM.
#define QP 72                               // Q [d2=64][m=64]
#define KP 72                               // K [d2=64][n=64]
#define VP 136                              // V [k2=32][n=128]
#define PP 36                               // P [m=64][k2=32]
#define SM_QHI 0
#define SM_QLO (64 * QP)                    // 4608
#define SM_KHI (2 * 64 * QP)                // 9216
#define SM_KLO (SM_KHI + 64 * KP)           // 13824
#define SM_VHI SM_KHI                       // overlays K (sequenced)
#define SM_VLO (SM_VHI + 32 * VP)           // 13568
#define SM_PHI (SM_VLO + 32 * VP)           // 17920
#define SM_PLO (SM_PHI + 64 * PP)           // 20224
#define ATT_SMEM_U32 (SM_PLO + 64 * PP)     // 22528
#define ATT_SMEM (ATT_SMEM_U32 * 4)         // 90112 B

#define ATT_THREADS 128

__global__ __launch_bounds__(ATT_THREADS, 2)
void attn_kernel(const float* __restrict__ QT, const float* __restrict__ KT,
                 const float* __restrict__ V, float* __restrict__ O) {
    extern __shared__ uint32_t smu[];
    uint32_t* Qhi = smu + SM_QHI;
    uint32_t* Qlo = smu + SM_QLO;
    uint32_t* Khi = smu + SM_KHI;
    uint32_t* Klo = smu + SM_KLO;
    uint32_t* Vhi = smu + SM_VHI;
    uint32_t* Vlo = smu + SM_VLO;
    uint32_t* Phi = smu + SM_PHI;
    uint32_t* Plo = smu + SM_PLO;

    const int tid  = threadIdx.x;
    const int lane = tid & 31;
    const int g    = lane >> 2;         // 0..7
    const int lt   = lane & 3;          // 0..3
    const int warp = tid >> 5;          // 0..3
    const int m0   = warp * 16;         // warp's q-row block (within 64)
    const int bh   = blockIdx.y;
    const int b    = bh >> 4;
    const int h    = bh & 15;
    const int kvh  = h >> 2;
    const int bxe  = gridDim.x - 1 - blockIdx.x;   // heavy tiles first
    const int q0   = bxe * 64;

    // ---- load Q tile, split into hi/lo bf16x2 planes [d2=64][m=64] ----
    for (int i = tid; i < 64 * 16; i += ATT_THREADS) {
        int d2 = i >> 4;
        int m4 = (i & 15) << 2;
        const float* pa = &QT[(size_t)(h * HDIM + 2 * d2) * MTOT + b * SEQ + q0 + m4];
        float4 qa = *(const float4*)pa;
        float4 qb = *(const float4*)(pa + MTOT);
        const float fa[4] = {qa.x, qa.y, qa.z, qa.w};
        const float fb[4] = {qb.x, qb.y, qb.z, qb.w};
        uint32_t hi[4], lo[4];
        #pragma unroll
        for (int j = 0; j < 4; j++) {
            float ah = bf16rd(fa[j]);
            float bh_ = bf16rd(fb[j]);
            hi[j] = pack2bf(ah, bh_);
            lo[j] = pack2bf(fa[j] - ah, fb[j] - bh_);
        }
        *(uint4*)&Qhi[d2 * QP + m4] = make_uint4(hi[0], hi[1], hi[2], hi[3]);
        *(uint4*)&Qlo[d2 * QP + m4] = make_uint4(lo[0], lo[1], lo[2], lo[3]);
    }

    float m_s[2] = {-1e30f, -1e30f};
    float l_s[2] = {0.f, 0.f};
    float o[16][4];
    #pragma unroll
    for (int nt = 0; nt < 16; nt++)
        #pragma unroll
        for (int r = 0; r < 4; r++) o[nt][r] = 0.f;

    const float scale = 0.08838834764831845f;   // 1/sqrt(128)
    const int ntk = bxe + 1;
    const int row0 = q0 + m0 + g;               // global q row (and +8)

    for (int tt = 0; tt < ntk; tt++) {
        const int k0 = tt * 64;
        __syncthreads();     // prev PV done reading V/P before K overwrite

        // ---- load K tile [d2=64][n=64], split hi/lo ----
        for (int i = tid; i < 64 * 16; i += ATT_THREADS) {
            int d2 = i >> 4;
            int n4 = (i & 15) << 2;
            const float* pk = &KT[(size_t)(kvh * HDIM + 2 * d2) * MTOT + b * SEQ + k0 + n4];
            float4 ka = *(const float4*)pk;
            float4 kb = *(const float4*)(pk + MTOT);
            const float fa[4] = {ka.x, ka.y, ka.z, ka.w};
            const float fb[4] = {kb.x, kb.y, kb.z, kb.w};
            uint32_t hi[4], lo[4];
            #pragma unroll
            for (int j = 0; j < 4; j++) {
                float ah = bf16rd(fa[j]);
                float bh_ = bf16rd(fb[j]);
                hi[j] = pack2bf(ah, bh_);
                lo[j] = pack2bf(fa[j] - ah, fb[j] - bh_);
            }
            *(uint4*)&Khi[d2 * KP + n4] = make_uint4(hi[0], hi[1], hi[2], hi[3]);
            *(uint4*)&Klo[d2 * KP + n4] = make_uint4(lo[0], lo[1], lo[2], lo[3]);
        }
        __syncthreads();

        // ---- S = Q K^T : 8 k16 steps, 3 MMAs each ----
        float s[8][4];
        #pragma unroll
        for (int nt = 0; nt < 8; nt++)
            #pragma unroll
            for (int r = 0; r < 4; r++) s[nt][r] = 0.f;

        #pragma unroll 4
        for (int ks = 0; ks < 8; ks++) {
            const int kb = ks * 8;
            uint32_t ah[4], al[4];
            ah[0] = Qhi[(kb + lt) * QP + m0 + g];
            ah[1] = Qhi[(kb + lt) * QP + m0 + g + 8];
            ah[2] = Qhi[(kb + lt + 4) * QP + m0 + g];
            ah[3] = Qhi[(kb + lt + 4) * QP + m0 + g + 8];
            al[0] = Qlo[(kb + lt) * QP + m0 + g];
            al[1] = Qlo[(kb + lt) * QP + m0 + g + 8];
            al[2] = Qlo[(kb + lt + 4) * QP + m0 + g];
            al[3] = Qlo[(kb + lt + 4) * QP + m0 + g + 8];
            #pragma unroll
            for (int nt = 0; nt < 8; nt++) {
                const int n0 = nt * 8 + g;
                uint32_t bh_[2], bl_[2];
                bh_[0] = Khi[(kb + lt) * KP + n0];
                bh_[1] = Khi[(kb + lt + 4) * KP + n0];
                bl_[0] = Klo[(kb + lt) * KP + n0];
                bl_[1] = Klo[(kb + lt + 4) * KP + n0];
                mma_bf16(s[nt], ah, bh_);
                mma_bf16(s[nt], al, bh_);
                mma_bf16(s[nt], ah, bl_);
            }
        }

        // ---- online softmax (rows g and g+8, full 64 cols in-warp) ----
        const bool diag = (k0 >= q0);
        #pragma unroll
        for (int nt = 0; nt < 8; nt++) {
            const int c0 = k0 + nt * 8 + 2 * lt;
            float v0 = s[nt][0] * scale;
            float v1 = s[nt][1] * scale;
            float v2 = s[nt][2] * scale;
            float v3 = s[nt][3] * scale;
            if (diag) {
                if (c0     > row0)     v0 = -1e30f;
                if (c0 + 1 > row0)     v1 = -1e30f;
                if (c0     > row0 + 8) v2 = -1e30f;
                if (c0 + 1 > row0 + 8) v3 = -1e30f;
            }
            s[nt][0] = v0; s[nt][1] = v1; s[nt][2] = v2; s[nt][3] = v3;
        }
        float mx0 = -1e30f, mx1 = -1e30f;
        #pragma unroll
        for (int nt = 0; nt < 8; nt++) {
            mx0 = fmaxf(mx0, fmaxf(s[nt][0], s[nt][1]));
            mx1 = fmaxf(mx1, fmaxf(s[nt][2], s[nt][3]));
        }
        mx0 = fmaxf(mx0, __shfl_xor_sync(0xffffffffu, mx0, 1));
        mx0 = fmaxf(mx0, __shfl_xor_sync(0xffffffffu, mx0, 2));
        mx1 = fmaxf(mx1, __shfl_xor_sync(0xffffffffu, mx1, 1));
        mx1 = fmaxf(mx1, __shfl_xor_sync(0xffffffffu, mx1, 2));

        const float mn0 = fmaxf(m_s[0], mx0);
        const float mn1 = fmaxf(m_s[1], mx1);
        const float cr0 = __expf(m_s[0] - mn0);
        const float cr1 = __expf(m_s[1] - mn1);
        float rs0 = 0.f, rs1 = 0.f;
        #pragma unroll
        for (int nt = 0; nt < 8; nt++) {
            s[nt][0] = __expf(s[nt][0] - mn0);
            s[nt][1] = __expf(s[nt][1] - mn0);
            s[nt][2] = __expf(s[nt][2] - mn1);
            s[nt][3] = __expf(s[nt][3] - mn1);
            rs0 += s[nt][0] + s[nt][1];
            rs1 += s[nt][2] + s[nt][3];
        }
        rs0 += __shfl_xor_sync(0xffffffffu, rs0, 1);
        rs0 += __shfl_xor_sync(0xffffffffu, rs0, 2);
        rs1 += __shfl_xor_sync(0xffffffffu, rs1, 1);
        rs1 += __shfl_xor_sync(0xffffffffu, rs1, 2);
        l_s[0] = l_s[0] * cr0 + rs0;  m_s[0] = mn0;
        l_s[1] = l_s[1] * cr1 + rs1;  m_s[1] = mn1;
        #pragma unroll
        for (int nt = 0; nt < 16; nt++) {
            o[nt][0] *= cr0; o[nt][1] *= cr0;
            o[nt][2] *= cr1; o[nt][3] *= cr1;
        }

        __syncthreads();    // all warps done reading K before V/P overwrite

        // ---- store P split hi/lo (packed pairs along k), rows g and g+8 ----
        #pragma unroll
        for (int nt = 0; nt < 8; nt++) {
            const int kc = nt * 4 + lt;     // pair index
            float h0 = bf16rd(s[nt][0]), h1 = bf16rd(s[nt][1]);
            float h2 = bf16rd(s[nt][2]), h3 = bf16rd(s[nt][3]);
            Phi[(m0 + g) * PP + kc]     = pack2bf(h0, h1);
            Plo[(m0 + g) * PP + kc]     = pack2bf(s[nt][0] - h0, s[nt][1] - h1);
            Phi[(m0 + g + 8) * PP + kc] = pack2bf(h2, h3);
            Plo[(m0 + g + 8) * PP + kc] = pack2bf(s[nt][2] - h2, s[nt][3] - h3);
        }

        // ---- load V tile [k2=32][n=128], split hi/lo ----
        for (int i = tid; i < 32 * 32; i += ATT_THREADS) {
            int k2 = i >> 5;
            int c4 = (i & 31) << 2;
            const float* pv = &V[(size_t)(b * SEQ + k0 + 2 * k2) * KVDIM + kvh * HDIM + c4];
            float4 va = *(const float4*)pv;
            float4 vb = *(const float4*)(pv + KVDIM);
            const float fa[4] = {va.x, va.y, va.z, va.w};
            const float fb[4] = {vb.x, vb.y, vb.z, vb.w};
            uint32_t hi[4], lo[4];
            #pragma unroll
            for (int j = 0; j < 4; j++) {
                float ah = bf16rd(fa[j]);
                float bh_ = bf16rd(fb[j]);
                hi[j] = pack2bf(ah, bh_);
                lo[j] = pack2bf(fa[j] - ah, fb[j] - bh_);
            }
            *(uint4*)&Vhi[k2 * VP + c4] = make_uint4(hi[0], hi[1], hi[2], hi[3]);
            *(uint4*)&Vlo[k2 * VP + c4] = make_uint4(lo[0], lo[1], lo[2], lo[3]);
        }
        __syncthreads();

        // ---- O += P V : 4 k16 steps, 3 MMAs each ----
        #pragma unroll 2
        for (int ks = 0; ks < 4; ks++) {
            const int kb = ks * 8;
            uint32_t ph[4], pl[4];
            ph[0] = Phi[(m0 + g) * PP + kb + lt];
            ph[1] = Phi[(m0 + g + 8) * PP + kb + lt];
            ph[2] = Phi[(m0 + g) * PP + kb + 4 + lt];
            ph[3] = Phi[(m0 + g + 8) * PP + kb + 4 + lt];
            pl[0] = Plo[(m0 + g) * PP + kb + lt];
            pl[1] = Plo[(m0 + g + 8) * PP + kb + lt];
            pl[2] = Plo[(m0 + g) * PP + kb + 4 + lt];
            pl[3] = Plo[(m0 + g + 8) * PP + kb + 4 + lt];
            #pragma unroll
            for (int nt = 0; nt < 16; nt++) {
                const int n0 = nt * 8 + g;
                uint32_t vh[2], vl[2];
                vh[0] = Vhi[(kb + lt) * VP + n0];
                vh[1] = Vhi[(kb + 4 + lt) * VP + n0];
                vl[0] = Vlo[(kb + lt) * VP + n0];
                vl[1] = Vlo[(kb + 4 + lt) * VP + n0];
                mma_bf16(o[nt], ph, vh);
                mma_bf16(o[nt], pl, vh);
                mma_bf16(o[nt], ph, vl);
            }
        }
    }

    // ---- epilogue: normalize, store ----
    const float inv0 = 1.f / l_s[0];
    const float inv1 = 1.f / l_s[1];
    #pragma unroll
    for (int nt = 0; nt < 16; nt++) {
        const int col = h * HDIM + nt * 8 + 2 * lt;
        float2 v01 = make_float2(o[nt][0] * inv0, o[nt][1] * inv0);
        float2 v23 = make_float2(o[nt][2] * inv1, o[nt][3] * inv1);
        *(float2*)&O[(size_t)(b * SEQ + q0 + m0 + g) * DMODEL + col]     = v01;
        *(float2*)&O[(size_t)(b * SEQ + q0 + m0 + g + 8) * DMODEL + col] = v23;
    }
}

// ---------------- launch -----------------------------------------------------
extern "C" void kernel_launch(void* const* d_in, const int* in_sizes, int n_in,
                              void* d_out, int out_size) {
    const float* x  = (const float*)d_in[0];
    const float* wq = (const float*)d_in[1];
    const float* wk = (const float*)d_in[2];
    const float* wv = (const float*)d_in[3];
    const float* wo = (const float*)d_in[4];
    float* out = (float*)d_out;

    float *qT, *kT, *v, *att;
    cudaGetSymbolAddress((void**)&qT,  g_qT);
    cudaGetSymbolAddress((void**)&kT,  g_kT);
    cudaGetSymbolAddress((void**)&v,   g_v);
    cudaGetSymbolAddress((void**)&att, g_att);

    cudaFuncSetAttribute(attn_kernel, cudaFuncAttributeMaxDynamicSharedMemorySize, ATT_SMEM);
    cudaFuncSetAttribute(qkv_gemm, cudaFuncAttributeMaxDynamicSharedMemorySize, FUSED_SMEM);
    cudaFuncSetAttribute(o_gemm,   cudaFuncAttributeMaxDynamicSharedMemorySize, KLOOP_SMEM);

    dim3 blk(128);
    // fused Q/K/V projections: 24 x 32 CTAs, one launch
    qkv_gemm<<<dim3(24, MTOT / 128), blk, FUSED_SMEM>>>(x, wq, wk, wv, qT, kT, v);
    // attention: 32 q-tiles (64 rows each) x 32 (batch,head)
    attn_kernel<<<dim3(SEQ / 64, BATCH * NHEADS), dim3(ATT_THREADS), ATT_SMEM>>>(qT, kT, v, att);
    // output projection
    o_gemm<<<dim3(DMODEL / 128, MTOT / 128), blk, KLOOP_SMEM>>>(att, wo, out);
}

// round 15
// speedup vs baseline: 10.8598x; 1.0206x over previous
#include <cuda_runtime.h>
#include <cuda_bf16.h>
#include <math.h>
#include <stdint.h>

// Problem constants
#define BATCH    2
#define SEQ      2048
#define DMODEL   2048
#define NHEADS   16
#define NKV      4
#define HDIM     128
#define NREP     4
#define MTOT     (BATCH * SEQ)          // 4096
#define KVDIM    (NKV * HDIM)           // 512

// ---------------- scratch (device globals; no allocation allowed) -----------
__device__ float g_qT[DMODEL * MTOT];    // Q^T: [h*128+d][b*2048+s]
__device__ float g_kT[KVDIM * MTOT];     // K^T: [kv*128+d][b*2048+s]
__device__ float g_v[MTOT * KVDIM];      // V natural [b*2048+s][kv*128+d]
__device__ float g_att[MTOT * DMODEL];   // attention output, natural

// ---------------- mma helpers ------------------------------------------------
__device__ __forceinline__ uint32_t f2tf32(float x) {
    uint32_t u;
    asm("cvt.rna.tf32.f32 %0, %1;" : "=r"(u) : "f"(x));
    return u;
}

__device__ __forceinline__ void mma_tf32(float c[4], const uint32_t a[4],
                                         const uint32_t b[2]) {
    asm volatile(
        "mma.sync.aligned.m16n8k8.row.col.f32.tf32.tf32.f32 "
        "{%0,%1,%2,%3}, {%4,%5,%6,%7}, {%8,%9}, {%0,%1,%2,%3};\n"
        : "+f"(c[0]), "+f"(c[1]), "+f"(c[2]), "+f"(c[3])
        : "r"(a[0]), "r"(a[1]), "r"(a[2]), "r"(a[3]), "r"(b[0]), "r"(b[1]));
}

__device__ __forceinline__ void mma_bf16(float c[4], const uint32_t a[4],
                                         const uint32_t b[2]) {
    asm volatile(
        "mma.sync.aligned.m16n8k16.row.col.f32.bf16.bf16.f32 "
        "{%0,%1,%2,%3}, {%4,%5,%6,%7}, {%8,%9}, {%0,%1,%2,%3};\n"
        : "+f"(c[0]), "+f"(c[1]), "+f"(c[2]), "+f"(c[3])
        : "r"(a[0]), "r"(a[1]), "r"(a[2]), "r"(a[3]), "r"(b[0]), "r"(b[1]));
}

__device__ __forceinline__ uint32_t pack2bf(float x, float y) {
    __nv_bfloat162 h = __floats2bfloat162_rn(x, y);   // x -> low half (even k)
    return *reinterpret_cast<uint32_t*>(&h);
}
__device__ __forceinline__ float bf16rd(float x) {
    return __bfloat162float(__float2bfloat16_rn(x));
}

// ---------------- tf32 tensor-core GEMM core --------------------------------
// 128x128x16 CTA tile, 128 threads (4 warps, 64x64 each), 2 CTAs/SM.
#define AP 136
#define ASW(k, m) ((k) * AP + ((m) ^ (((((k) >> 2) & 3)) << 3)))
#define KLOOP_SMEM   (2 * 2 * 16 * AP * 4)      // 34816 B
#define TRANS_SMEM   (128 * 129 * 4)            // 66048 B
#define FUSED_SMEM   TRANS_SMEM                 // max of both paths

__device__ __forceinline__
void gemm_body(const float* __restrict__ A, const float* __restrict__ B,
               float* __restrict__ C, int M, int N, int K,
               int bx, int by, bool transc, float* sh) {
    float* As = sh;                    // 2 bufs x 16 x AP  (swizzled [k][m])
    float* Bs = sh + 2 * 16 * AP;      // 2 bufs x 16 x AP  (linear   [k][n])

    const int tid  = threadIdx.x;
    const int lane = tid & 31;
    const int g    = lane >> 2;
    const int t    = lane & 3;
    const int warp = tid >> 5;          // 0..3
    const int wm   = (warp & 1) * 64;
    const int wn   = (warp >> 1) * 64;

    const int am  = tid >> 2;                // 0..31 (+32,+64,+96)
    const int ac4 = (tid & 3) * 4;           // k offset 0/4/8/12
    const int brw = tid >> 5;                // 0..3 (+4,+8,+12)
    const int bn4 = (tid & 31) * 4;
    const float* Ag = A + (size_t)(by * 128 + am) * K + ac4;
    const float* Bg = B + (size_t)brw * N + bx * 128 + bn4;

    float c[4][8][4];
    #pragma unroll
    for (int mt = 0; mt < 4; mt++)
        #pragma unroll
        for (int nt = 0; nt < 8; nt++)
            #pragma unroll
            for (int r = 0; r < 4; r++) c[mt][nt][r] = 0.f;

    float4 pa[4], pb[4];
    #pragma unroll
    for (int r = 0; r < 4; r++) {
        pa[r] = *(const float4*)(Ag + (size_t)(32 * r) * K);
        pb[r] = *(const float4*)(Bg + (size_t)(4 * r) * N);
    }

    {
        float* Ab = As;
        float* Bb = Bs;
        #pragma unroll
        for (int r = 0; r < 4; r++) {
            const float av[4] = {pa[r].x, pa[r].y, pa[r].z, pa[r].w};
            #pragma unroll
            for (int j = 0; j < 4; j++)
                Ab[ASW(ac4 + j, am + 32 * r)] = __uint_as_float(f2tf32(av[j]));
            uint4 u = {f2tf32(pb[r].x), f2tf32(pb[r].y), f2tf32(pb[r].z), f2tf32(pb[r].w)};
            *(uint4*)&Bb[(brw + 4 * r) * AP + bn4] = u;
        }
    }
    __syncthreads();

    const int NT = K >> 4;
    for (int kt = 0; kt < NT; kt++) {
        if (kt + 1 < NT) {
            const float* Ap = Ag + (kt + 1) * 16;
            const float* Bp = Bg + (size_t)(kt + 1) * 16 * N;
            #pragma unroll
            for (int r = 0; r < 4; r++) {
                pa[r] = *(const float4*)(Ap + (size_t)(32 * r) * K);
                pb[r] = *(const float4*)(Bp + (size_t)(4 * r) * N);
            }
        }

        const uint32_t* Au = (const uint32_t*)(As + (kt & 1) * 16 * AP);
        const uint32_t* Bu = (const uint32_t*)(Bs + (kt & 1) * 16 * AP);

        #pragma unroll
        for (int s = 0; s < 2; s++) {
            const int kb = s * 8;
            uint32_t a[4][4], bf[8][2];
            #pragma unroll
            for (int mt = 0; mt < 4; mt++) {
                const int m0 = wm + mt * 16 + g;
                a[mt][0] = Au[ASW(kb + t,     m0)];
                a[mt][1] = Au[ASW(kb + t,     m0 + 8)];
                a[mt][2] = Au[ASW(kb + t + 4, m0)];
                a[mt][3] = Au[ASW(kb + t + 4, m0 + 8)];
            }
            #pragma unroll
            for (int nt = 0; nt < 8; nt++) {
                const int n0 = wn + nt * 8 + g;
                bf[nt][0] = Bu[(kb + t) * AP + n0];
                bf[nt][1] = Bu[(kb + t + 4) * AP + n0];
            }
            #pragma unroll
            for (int mt = 0; mt < 4; mt++)
                #pragma unroll
                for (int nt = 0; nt < 8; nt++)
                    mma_tf32(c[mt][nt], a[mt], bf[nt]);
        }

        if (kt + 1 < NT) {
            float* Ab = As + ((kt + 1) & 1) * 16 * AP;
            float* Bb = Bs + ((kt + 1) & 1) * 16 * AP;
            #pragma unroll
            for (int r = 0; r < 4; r++) {
                const float av[4] = {pa[r].x, pa[r].y, pa[r].z, pa[r].w};
                #pragma unroll
                for (int j = 0; j < 4; j++)
                    Ab[ASW(ac4 + j, am + 32 * r)] = __uint_as_float(f2tf32(av[j]));
                uint4 u = {f2tf32(pb[r].x), f2tf32(pb[r].y), f2tf32(pb[r].z), f2tf32(pb[r].w)};
                *(uint4*)&Bb[(brw + 4 * r) * AP + bn4] = u;
            }
            __syncthreads();
        }
    }

    if (!transc) {
        #pragma unroll
        for (int mt = 0; mt < 4; mt++) {
            #pragma unroll
            for (int nt = 0; nt < 8; nt++) {
                const int row = by * 128 + wm + mt * 16 + g;
                const int col = bx * 128 + wn + nt * 8 + t * 2;
                float2 v01 = make_float2(c[mt][nt][0], c[mt][nt][1]);
                float2 v23 = make_float2(c[mt][nt][2], c[mt][nt][3]);
                *(float2*)&C[(size_t)row * N + col]       = v01;
                *(float2*)&C[(size_t)(row + 8) * N + col] = v23;
            }
        }
    } else {
        __syncthreads();                 // compute done before overlay
        float* Cs = sh;                  // 128 x 129
        #pragma unroll
        for (int mt = 0; mt < 4; mt++) {
            #pragma unroll
            for (int nt = 0; nt < 8; nt++) {
                const int r  = wm + mt * 16 + g;
                const int cl = wn + nt * 8 + t * 2;
                Cs[r * 129 + cl]           = c[mt][nt][0];
                Cs[r * 129 + cl + 1]       = c[mt][nt][1];
                Cs[(r + 8) * 129 + cl]     = c[mt][nt][2];
                Cs[(r + 8) * 129 + cl + 1] = c[mt][nt][3];
            }
        }
        __syncthreads();
        #pragma unroll
        for (int r = 0; r < 32; r++) {
            const int i  = tid + 128 * r;
            const int n  = i >> 5;
            const int m4 = (i & 31) << 2;
            float4 v;
            v.x = Cs[(m4 + 0) * 129 + n];
            v.y = Cs[(m4 + 1) * 129 + n];
            v.z = Cs[(m4 + 2) * 129 + n];
            v.w = Cs[(m4 + 3) * 129 + n];
            *(float4*)&C[(size_t)(bx * 128 + n) * M + by * 128 + m4] = v;
        }
    }
}

// Fused Q/K/V projection: one launch, 24 x 32 CTAs.
__global__ __launch_bounds__(128, 2)
void qkv_gemm(const float* __restrict__ x,
              const float* __restrict__ wq, const float* __restrict__ wk,
              const float* __restrict__ wv,
              float* __restrict__ qT, float* __restrict__ kT,
              float* __restrict__ v) {
    extern __shared__ float sh[];
    const int bx = blockIdx.x;
    const int by = blockIdx.y;
    const float* B;
    float* C;
    int N, bxl;
    bool transc;
    if (bx < 16)      { B = wq; C = qT; N = DMODEL; bxl = bx;      transc = true;  }
    else if (bx < 20) { B = wk; C = kT; N = KVDIM;  bxl = bx - 16; transc = true;  }
    else              { B = wv; C = v;  N = KVDIM;  bxl = bx - 20; transc = false; }
    gemm_body(x, B, C, MTOT, N, DMODEL, bxl, by, transc, sh);
}

// O projection (natural store only).
__global__ __launch_bounds__(128, 2)
void o_gemm(const float* __restrict__ A, const float* __restrict__ B,
            float* __restrict__ C) {
    extern __shared__ float sh[];
    gemm_body(A, B, C, MTOT, DMODEL, DMODEL, blockIdx.x, blockIdx.y, false, sh);
}

// ---------------- Split-bf16 tensor-core flash attention --------------------
// 128 threads (4 warps), q tile 64 rows, kv tiles of 64. 3 CTAs/SM.
// P never touches smem: the QK^T C-fragment layout IS the PV A-fragment
// layout (rows g/g+8, col pairs 8nt+2lt), so P fragments are built in regs.
#define QP 72                               // Q [d2=64][m=64]
#define KP 72                               // K [d2=64][n=64]
#define VP 136                              // V [k2=32][n=128]
#define SM_QHI 0
#define SM_QLO (64 * QP)                    // 4608
#define SM_KHI (2 * 64 * QP)                // 9216
#define SM_KLO (SM_KHI + 64 * KP)           // 13824
#define SM_VHI SM_KHI                       // overlays K (sequenced)
#define SM_VLO (SM_VHI + 32 * VP)           // 13568 (fits inside K region)
#define ATT_SMEM_U32 (SM_KHI + 2 * 64 * KP) // 18432
#define ATT_SMEM (ATT_SMEM_U32 * 4)         // 73728 B -> 3 CTAs/SM

#define ATT_THREADS 128

__global__ __launch_bounds__(ATT_THREADS, 3)
void attn_kernel(const float* __restrict__ QT, const float* __restrict__ KT,
                 const float* __restrict__ V, float* __restrict__ O) {
    extern __shared__ uint32_t smu[];
    uint32_t* Qhi = smu + SM_QHI;
    uint32_t* Qlo = smu + SM_QLO;
    uint32_t* Khi = smu + SM_KHI;
    uint32_t* Klo = smu + SM_KLO;
    uint32_t* Vhi = smu + SM_VHI;
    uint32_t* Vlo = smu + SM_VLO;

    const int tid  = threadIdx.x;
    const int lane = tid & 31;
    const int g    = lane >> 2;         // 0..7
    const int lt   = lane & 3;          // 0..3
    const int warp = tid >> 5;          // 0..3
    const int m0   = warp * 16;         // warp's q-row block (within 64)
    const int bh   = blockIdx.y;
    const int b    = bh >> 4;
    const int h    = bh & 15;
    const int kvh  = h >> 2;
    const int bxe  = gridDim.x - 1 - blockIdx.x;   // heavy tiles first
    const int q0   = bxe * 64;

    // ---- load Q tile, split into hi/lo bf16x2 planes [d2=64][m=64] ----
    for (int i = tid; i < 64 * 16; i += ATT_THREADS) {
        int d2 = i >> 4;
        int m4 = (i & 15) << 2;
        const float* pa = &QT[(size_t)(h * HDIM + 2 * d2) * MTOT + b * SEQ + q0 + m4];
        float4 qa = *(const float4*)pa;
        float4 qb = *(const float4*)(pa + MTOT);
        const float fa[4] = {qa.x, qa.y, qa.z, qa.w};
        const float fb[4] = {qb.x, qb.y, qb.z, qb.w};
        uint32_t hi[4], lo[4];
        #pragma unroll
        for (int j = 0; j < 4; j++) {
            float ah = bf16rd(fa[j]);
            float bh_ = bf16rd(fb[j]);
            hi[j] = pack2bf(ah, bh_);
            lo[j] = pack2bf(fa[j] - ah, fb[j] - bh_);
        }
        *(uint4*)&Qhi[d2 * QP + m4] = make_uint4(hi[0], hi[1], hi[2], hi[3]);
        *(uint4*)&Qlo[d2 * QP + m4] = make_uint4(lo[0], lo[1], lo[2], lo[3]);
    }

    float m_s[2] = {-1e30f, -1e30f};
    float l_s[2] = {0.f, 0.f};
    float o[16][4];
    #pragma unroll
    for (int nt = 0; nt < 16; nt++)
        #pragma unroll
        for (int r = 0; r < 4; r++) o[nt][r] = 0.f;

    const float scale = 0.08838834764831845f;   // 1/sqrt(128)
    const int ntk = bxe + 1;
    const int row0 = q0 + m0 + g;               // global q row (and +8)

    for (int tt = 0; tt < ntk; tt++) {
        const int k0 = tt * 64;
        __syncthreads();     // prev PV done reading V before K overwrite

        // ---- load K tile [d2=64][n=64], split hi/lo ----
        for (int i = tid; i < 64 * 16; i += ATT_THREADS) {
            int d2 = i >> 4;
            int n4 = (i & 15) << 2;
            const float* pk = &KT[(size_t)(kvh * HDIM + 2 * d2) * MTOT + b * SEQ + k0 + n4];
            float4 ka = *(const float4*)pk;
            float4 kb = *(const float4*)(pk + MTOT);
            const float fa[4] = {ka.x, ka.y, ka.z, ka.w};
            const float fb[4] = {kb.x, kb.y, kb.z, kb.w};
            uint32_t hi[4], lo[4];
            #pragma unroll
            for (int j = 0; j < 4; j++) {
                float ah = bf16rd(fa[j]);
                float bh_ = bf16rd(fb[j]);
                hi[j] = pack2bf(ah, bh_);
                lo[j] = pack2bf(fa[j] - ah, fb[j] - bh_);
            }
            *(uint4*)&Khi[d2 * KP + n4] = make_uint4(hi[0], hi[1], hi[2], hi[3]);
            *(uint4*)&Klo[d2 * KP + n4] = make_uint4(lo[0], lo[1], lo[2], lo[3]);
        }
        __syncthreads();

        // ---- S = Q K^T : 8 k16 steps, 3 MMAs each ----
        float s[8][4];
        #pragma unroll
        for (int nt = 0; nt < 8; nt++)
            #pragma unroll
            for (int r = 0; r < 4; r++) s[nt][r] = 0.f;

        #pragma unroll 4
        for (int ks = 0; ks < 8; ks++) {
            const int kb = ks * 8;
            uint32_t ah[4], al[4];
            ah[0] = Qhi[(kb + lt) * QP + m0 + g];
            ah[1] = Qhi[(kb + lt) * QP + m0 + g + 8];
            ah[2] = Qhi[(kb + lt + 4) * QP + m0 + g];
            ah[3] = Qhi[(kb + lt + 4) * QP + m0 + g + 8];
            al[0] = Qlo[(kb + lt) * QP + m0 + g];
            al[1] = Qlo[(kb + lt) * QP + m0 + g + 8];
            al[2] = Qlo[(kb + lt + 4) * QP + m0 + g];
            al[3] = Qlo[(kb + lt + 4) * QP + m0 + g + 8];
            #pragma unroll
            for (int nt = 0; nt < 8; nt++) {
                const int n0 = nt * 8 + g;
                uint32_t bh_[2], bl_[2];
                bh_[0] = Khi[(kb + lt) * KP + n0];
                bh_[1] = Khi[(kb + lt + 4) * KP + n0];
                bl_[0] = Klo[(kb + lt) * KP + n0];
                bl_[1] = Klo[(kb + lt + 4) * KP + n0];
                mma_bf16(s[nt], ah, bh_);
                mma_bf16(s[nt], al, bh_);
                mma_bf16(s[nt], ah, bl_);
            }
        }

        // ---- online softmax (rows g and g+8, full 64 cols in-warp) ----
        const bool diag = (k0 >= q0);
        #pragma unroll
        for (int nt = 0; nt < 8; nt++) {
            const int c0 = k0 + nt * 8 + 2 * lt;
            float v0 = s[nt][0] * scale;
            float v1 = s[nt][1] * scale;
            float v2 = s[nt][2] * scale;
            float v3 = s[nt][3] * scale;
            if (diag) {
                if (c0     > row0)     v0 = -1e30f;
                if (c0 + 1 > row0)     v1 = -1e30f;
                if (c0     > row0 + 8) v2 = -1e30f;
                if (c0 + 1 > row0 + 8) v3 = -1e30f;
            }
            s[nt][0] = v0; s[nt][1] = v1; s[nt][2] = v2; s[nt][3] = v3;
        }
        float mx0 = -1e30f, mx1 = -1e30f;
        #pragma unroll
        for (int nt = 0; nt < 8; nt++) {
            mx0 = fmaxf(mx0, fmaxf(s[nt][0], s[nt][1]));
            mx1 = fmaxf(mx1, fmaxf(s[nt][2], s[nt][3]));
        }
        mx0 = fmaxf(mx0, __shfl_xor_sync(0xffffffffu, mx0, 1));
        mx0 = fmaxf(mx0, __shfl_xor_sync(0xffffffffu, mx0, 2));
        mx1 = fmaxf(mx1, __shfl_xor_sync(0xffffffffu, mx1, 1));
        mx1 = fmaxf(mx1, __shfl_xor_sync(0xffffffffu, mx1, 2));

        const float mn0 = fmaxf(m_s[0], mx0);
        const float mn1 = fmaxf(m_s[1], mx1);
        const float cr0 = __expf(m_s[0] - mn0);
        const float cr1 = __expf(m_s[1] - mn1);
        float rs0 = 0.f, rs1 = 0.f;
        #pragma unroll
        for (int nt = 0; nt < 8; nt++) {
            s[nt][0] = __expf(s[nt][0] - mn0);
            s[nt][1] = __expf(s[nt][1] - mn0);
            s[nt][2] = __expf(s[nt][2] - mn1);
            s[nt][3] = __expf(s[nt][3] - mn1);
            rs0 += s[nt][0] + s[nt][1];
            rs1 += s[nt][2] + s[nt][3];
        }
        rs0 += __shfl_xor_sync(0xffffffffu, rs0, 1);
        rs0 += __shfl_xor_sync(0xffffffffu, rs0, 2);
        rs1 += __shfl_xor_sync(0xffffffffu, rs1, 1);
        rs1 += __shfl_xor_sync(0xffffffffu, rs1, 2);
        l_s[0] = l_s[0] * cr0 + rs0;  m_s[0] = mn0;
        l_s[1] = l_s[1] * cr1 + rs1;  m_s[1] = mn1;
        #pragma unroll
        for (int nt = 0; nt < 16; nt++) {
            o[nt][0] *= cr0; o[nt][1] *= cr0;
            o[nt][2] *= cr1; o[nt][3] *= cr1;
        }

        // ---- build P fragments in registers (C-frag == A-frag layout) ----
        uint32_t pha[8], phb[8], pla[8], plb[8];
        #pragma unroll
        for (int nt = 0; nt < 8; nt++) {
            float h0 = bf16rd(s[nt][0]), h1 = bf16rd(s[nt][1]);
            float h2 = bf16rd(s[nt][2]), h3 = bf16rd(s[nt][3]);
            pha[nt] = pack2bf(h0, h1);
            pla[nt] = pack2bf(s[nt][0] - h0, s[nt][1] - h1);
            phb[nt] = pack2bf(h2, h3);
            plb[nt] = pack2bf(s[nt][2] - h2, s[nt][3] - h3);
        }

        __syncthreads();    // all warps done reading K before V overwrite

        // ---- load V tile [k2=32][n=128], split hi/lo ----
        for (int i = tid; i < 32 * 32; i += ATT_THREADS) {
            int k2 = i >> 5;
            int c4 = (i & 31) << 2;
            const float* pv = &V[(size_t)(b * SEQ + k0 + 2 * k2) * KVDIM + kvh * HDIM + c4];
            float4 va = *(const float4*)pv;
            float4 vb = *(const float4*)(pv + KVDIM);
            const float fa[4] = {va.x, va.y, va.z, va.w};
            const float fb[4] = {vb.x, vb.y, vb.z, vb.w};
            uint32_t hi[4], lo[4];
            #pragma unroll
            for (int j = 0; j < 4; j++) {
                float ah = bf16rd(fa[j]);
                float bh_ = bf16rd(fb[j]);
                hi[j] = pack2bf(ah, bh_);
                lo[j] = pack2bf(fa[j] - ah, fb[j] - bh_);
            }
            *(uint4*)&Vhi[k2 * VP + c4] = make_uint4(hi[0], hi[1], hi[2], hi[3]);
            *(uint4*)&Vlo[k2 * VP + c4] = make_uint4(lo[0], lo[1], lo[2], lo[3]);
        }
        __syncthreads();

        // ---- O += P V : 4 k16 steps, 3 MMAs each; P from registers ----
        #pragma unroll
        for (int ks = 0; ks < 4; ks++) {
            const int kb = ks * 8;
            uint32_t ph[4], pl[4];
            ph[0] = pha[2 * ks];     ph[1] = phb[2 * ks];
            ph[2] = pha[2 * ks + 1]; ph[3] = phb[2 * ks + 1];
            pl[0] = pla[2 * ks];     pl[1] = plb[2 * ks];
            pl[2] = pla[2 * ks + 1]; pl[3] = plb[2 * ks + 1];
            #pragma unroll
            for (int nt = 0; nt < 16; nt++) {
                const int n0 = nt * 8 + g;
                uint32_t vh[2], vl[2];
                vh[0] = Vhi[(kb + lt) * VP + n0];
                vh[1] = Vhi[(kb + 4 + lt) * VP + n0];
                vl[0] = Vlo[(kb + lt) * VP + n0];
                vl[1] = Vlo[(kb + 4 + lt) * VP + n0];
                mma_bf16(o[nt], ph, vh);
                mma_bf16(o[nt], pl, vh);
                mma_bf16(o[nt], ph, vl);
            }
        }
    }

    // ---- epilogue: normalize, store ----
    const float inv0 = 1.f / l_s[0];
    const float inv1 = 1.f / l_s[1];
    #pragma unroll
    for (int nt = 0; nt < 16; nt++) {
        const int col = h * HDIM + nt * 8 + 2 * lt;
        float2 v01 = make_float2(o[nt][0] * inv0, o[nt][1] * inv0);
        float2 v23 = make_float2(o[nt][2] * inv1, o[nt][3] * inv1);
        *(float2*)&O[(size_t)(b * SEQ + q0 + m0 + g) * DMODEL + col]     = v01;
        *(float2*)&O[(size_t)(b * SEQ + q0 + m0 + g + 8) * DMODEL + col] = v23;
    }
}

// ---------------- launch -----------------------------------------------------
extern "C" void kernel_launch(void* const* d_in, const int* in_sizes, int n_in,
                              void* d_out, int out_size) {
    const float* x  = (const float*)d_in[0];
    const float* wq = (const float*)d_in[1];
    const float* wk = (const float*)d_in[2];
    const float* wv = (const float*)d_in[3];
    const float* wo = (const float*)d_in[4];
    float* out = (float*)d_out;

    float *qT, *kT, *v, *att;
    cudaGetSymbolAddress((void**)&qT,  g_qT);
    cudaGetSymbolAddress((void**)&kT,  g_kT);
    cudaGetSymbolAddress((void**)&v,   g_v);
    cudaGetSymbolAddress((void**)&att, g_att);

    cudaFuncSetAttribute(attn_kernel, cudaFuncAttributeMaxDynamicSharedMemorySize, ATT_SMEM);
    cudaFuncSetAttribute(qkv_gemm, cudaFuncAttributeMaxDynamicSharedMemorySize, FUSED_SMEM);
    cudaFuncSetAttribute(o_gemm,   cudaFuncAttributeMaxDynamicSharedMemorySize, KLOOP_SMEM);

    dim3 blk(128);
    // fused Q/K/V projections: 24 x 32 CTAs, one launch
    qkv_gemm<<<dim3(24, MTOT / 128), blk, FUSED_SMEM>>>(x, wq, wk, wv, qT, kT, v);
    // attention: 32 q-tiles (64 rows each) x 32 (batch,head), 3 CTAs/SM
    attn_kernel<<<dim3(SEQ / 64, BATCH * NHEADS), dim3(ATT_THREADS), ATT_SMEM>>>(qT, kT, v, att);
    // output projection
    o_gemm<<<dim3(DMODEL / 128, MTOT / 128), blk, KLOOP_SMEM>>>(att, wo, out);
}

// round 16
// speedup vs baseline: 11.1536x; 1.0270x over previous
#include <cuda_runtime.h>
#include <cuda_bf16.h>
#include <math.h>
#include <stdint.h>

// Problem constants
#define BATCH    2
#define SEQ      2048
#define DMODEL   2048
#define NHEADS   16
#define NKV      4
#define HDIM     128
#define NREP     4
#define MTOT     (BATCH * SEQ)          // 4096
#define KVDIM    (NKV * HDIM)           // 512

// ---------------- scratch (device globals; no allocation allowed) -----------
__device__ float    g_qT[DMODEL * MTOT];            // Q^T fp32: [h*128+d][s]
__device__ uint32_t g_khi[(KVDIM / 2) * MTOT];      // K hi plane: [d2][s] bf16x2 (pairs along d)
__device__ uint32_t g_klo[(KVDIM / 2) * MTOT];      // K lo plane
__device__ uint32_t g_vhi[KVDIM * (MTOT / 2)];      // V hi plane: [d][s2] bf16x2 (pairs along s)
__device__ uint32_t g_vlo[KVDIM * (MTOT / 2)];      // V lo plane
__device__ float    g_att[MTOT * DMODEL];           // attention output, natural

// ---------------- mma helpers ------------------------------------------------
__device__ __forceinline__ uint32_t f2tf32(float x) {
    uint32_t u;
    asm("cvt.rna.tf32.f32 %0, %1;" : "=r"(u) : "f"(x));
    return u;
}

__device__ __forceinline__ void mma_tf32(float c[4], const uint32_t a[4],
                                         const uint32_t b[2]) {
    asm volatile(
        "mma.sync.aligned.m16n8k8.row.col.f32.tf32.tf32.f32 "
        "{%0,%1,%2,%3}, {%4,%5,%6,%7}, {%8,%9}, {%0,%1,%2,%3};\n"
        : "+f"(c[0]), "+f"(c[1]), "+f"(c[2]), "+f"(c[3])
        : "r"(a[0]), "r"(a[1]), "r"(a[2]), "r"(a[3]), "r"(b[0]), "r"(b[1]));
}

__device__ __forceinline__ void mma_bf16(float c[4], const uint32_t a[4],
                                         const uint32_t b[2]) {
    asm volatile(
        "mma.sync.aligned.m16n8k16.row.col.f32.bf16.bf16.f32 "
        "{%0,%1,%2,%3}, {%4,%5,%6,%7}, {%8,%9}, {%0,%1,%2,%3};\n"
        : "+f"(c[0]), "+f"(c[1]), "+f"(c[2]), "+f"(c[3])
        : "r"(a[0]), "r"(a[1]), "r"(a[2]), "r"(a[3]), "r"(b[0]), "r"(b[1]));
}

__device__ __forceinline__ uint32_t pack2bf(float x, float y) {
    __nv_bfloat162 h = __floats2bfloat162_rn(x, y);   // x -> low half (even k)
    return *reinterpret_cast<uint32_t*>(&h);
}
__device__ __forceinline__ float bf16rd(float x) {
    return __bfloat162float(__float2bfloat16_rn(x));
}

// ---------------- tf32 tensor-core GEMM core --------------------------------
// 128x128x16 CTA tile, 128 threads (4 warps, 64x64 each), 2 CTAs/SM.
#define AP 136
#define ASW(k, m) ((k) * AP + ((m) ^ (((((k) >> 2) & 3)) << 3)))
#define KLOOP_SMEM   (2 * 2 * 16 * AP * 4)      // 34816 B
#define TRANS_SMEM   (128 * 129 * 4)            // 66048 B
#define FUSED_SMEM   TRANS_SMEM                 // max of all paths

// Epilogue modes
#define EPI_NAT    0   // natural fp32 C store
#define EPI_QT     1   // transposed fp32 store (Q)
#define EPI_KPLANE 2   // packed bf16x2 hi/lo planes, pairs along d (K)
#define EPI_VPLANE 3   // packed bf16x2 hi/lo planes, pairs along s (V)

__device__ __forceinline__
void gemm_body(const float* __restrict__ A, const float* __restrict__ B,
               float* __restrict__ C, uint32_t* __restrict__ Phi,
               uint32_t* __restrict__ Plo,
               int M, int N, int K, int bx, int by, int mode, float* sh) {
    float* As = sh;                    // 2 bufs x 16 x AP  (swizzled [k][m])
    float* Bs = sh + 2 * 16 * AP;      // 2 bufs x 16 x AP  (linear   [k][n])

    const int tid  = threadIdx.x;
    const int lane = tid & 31;
    const int g    = lane >> 2;
    const int t    = lane & 3;
    const int warp = tid >> 5;          // 0..3
    const int wm   = (warp & 1) * 64;
    const int wn   = (warp >> 1) * 64;

    const int am  = tid >> 2;                // 0..31 (+32,+64,+96)
    const int ac4 = (tid & 3) * 4;           // k offset 0/4/8/12
    const int brw = tid >> 5;                // 0..3 (+4,+8,+12)
    const int bn4 = (tid & 31) * 4;
    const float* Ag = A + (size_t)(by * 128 + am) * K + ac4;
    const float* Bg = B + (size_t)brw * N + bx * 128 + bn4;

    float c[4][8][4];
    #pragma unroll
    for (int mt = 0; mt < 4; mt++)
        #pragma unroll
        for (int nt = 0; nt < 8; nt++)
            #pragma unroll
            for (int r = 0; r < 4; r++) c[mt][nt][r] = 0.f;

    float4 pa[4], pb[4];
    #pragma unroll
    for (int r = 0; r < 4; r++) {
        pa[r] = *(const float4*)(Ag + (size_t)(32 * r) * K);
        pb[r] = *(const float4*)(Bg + (size_t)(4 * r) * N);
    }

    {
        float* Ab = As;
        float* Bb = Bs;
        #pragma unroll
        for (int r = 0; r < 4; r++) {
            const float av[4] = {pa[r].x, pa[r].y, pa[r].z, pa[r].w};
            #pragma unroll
            for (int j = 0; j < 4; j++)
                Ab[ASW(ac4 + j, am + 32 * r)] = __uint_as_float(f2tf32(av[j]));
            uint4 u = {f2tf32(pb[r].x), f2tf32(pb[r].y), f2tf32(pb[r].z), f2tf32(pb[r].w)};
            *(uint4*)&Bb[(brw + 4 * r) * AP + bn4] = u;
        }
    }
    __syncthreads();

    const int NT = K >> 4;
    for (int kt = 0; kt < NT; kt++) {
        if (kt + 1 < NT) {
            const float* Ap = Ag + (kt + 1) * 16;
            const float* Bp = Bg + (size_t)(kt + 1) * 16 * N;
            #pragma unroll
            for (int r = 0; r < 4; r++) {
                pa[r] = *(const float4*)(Ap + (size_t)(32 * r) * K);
                pb[r] = *(const float4*)(Bp + (size_t)(4 * r) * N);
            }
        }

        const uint32_t* Au = (const uint32_t*)(As + (kt & 1) * 16 * AP);
        const uint32_t* Bu = (const uint32_t*)(Bs + (kt & 1) * 16 * AP);

        #pragma unroll
        for (int s = 0; s < 2; s++) {
            const int kb = s * 8;
            uint32_t a[4][4], bf[8][2];
            #pragma unroll
            for (int mt = 0; mt < 4; mt++) {
                const int m0 = wm + mt * 16 + g;
                a[mt][0] = Au[ASW(kb + t,     m0)];
                a[mt][1] = Au[ASW(kb + t,     m0 + 8)];
                a[mt][2] = Au[ASW(kb + t + 4, m0)];
                a[mt][3] = Au[ASW(kb + t + 4, m0 + 8)];
            }
            #pragma unroll
            for (int nt = 0; nt < 8; nt++) {
                const int n0 = wn + nt * 8 + g;
                bf[nt][0] = Bu[(kb + t) * AP + n0];
                bf[nt][1] = Bu[(kb + t + 4) * AP + n0];
            }
            #pragma unroll
            for (int mt = 0; mt < 4; mt++)
                #pragma unroll
                for (int nt = 0; nt < 8; nt++)
                    mma_tf32(c[mt][nt], a[mt], bf[nt]);
        }

        if (kt + 1 < NT) {
            float* Ab = As + ((kt + 1) & 1) * 16 * AP;
            float* Bb = Bs + ((kt + 1) & 1) * 16 * AP;
            #pragma unroll
            for (int r = 0; r < 4; r++) {
                const float av[4] = {pa[r].x, pa[r].y, pa[r].z, pa[r].w};
                #pragma unroll
                for (int j = 0; j < 4; j++)
                    Ab[ASW(ac4 + j, am + 32 * r)] = __uint_as_float(f2tf32(av[j]));
                uint4 u = {f2tf32(pb[r].x), f2tf32(pb[r].y), f2tf32(pb[r].z), f2tf32(pb[r].w)};
                *(uint4*)&Bb[(brw + 4 * r) * AP + bn4] = u;
            }
            __syncthreads();
        }
    }

    if (mode == EPI_NAT) {
        #pragma unroll
        for (int mt = 0; mt < 4; mt++) {
            #pragma unroll
            for (int nt = 0; nt < 8; nt++) {
                const int row = by * 128 + wm + mt * 16 + g;
                const int col = bx * 128 + wn + nt * 8 + t * 2;
                float2 v01 = make_float2(c[mt][nt][0], c[mt][nt][1]);
                float2 v23 = make_float2(c[mt][nt][2], c[mt][nt][3]);
                *(float2*)&C[(size_t)row * N + col]       = v01;
                *(float2*)&C[(size_t)(row + 8) * N + col] = v23;
            }
        }
        return;
    }

    // staging path: Cs[s_local][d_local], stride 129
    __syncthreads();                 // compute done before overlay
    float* Cs = sh;                  // 128 x 129
    #pragma unroll
    for (int mt = 0; mt < 4; mt++) {
        #pragma unroll
        for (int nt = 0; nt < 8; nt++) {
            const int r  = wm + mt * 16 + g;
            const int cl = wn + nt * 8 + t * 2;
            Cs[r * 129 + cl]           = c[mt][nt][0];
            Cs[r * 129 + cl + 1]       = c[mt][nt][1];
            Cs[(r + 8) * 129 + cl]     = c[mt][nt][2];
            Cs[(r + 8) * 129 + cl + 1] = c[mt][nt][3];
        }
    }
    __syncthreads();

    if (mode == EPI_QT) {
        #pragma unroll
        for (int r = 0; r < 32; r++) {
            const int i  = tid + 128 * r;
            const int n  = i >> 5;
            const int m4 = (i & 31) << 2;
            float4 v;
            v.x = Cs[(m4 + 0) * 129 + n];
            v.y = Cs[(m4 + 1) * 129 + n];
            v.z = Cs[(m4 + 2) * 129 + n];
            v.w = Cs[(m4 + 3) * 129 + n];
            *(float4*)&C[(size_t)(bx * 128 + n) * M + by * 128 + m4] = v;
        }
    } else if (mode == EPI_KPLANE) {
        // khi/klo[d2_glob][s], pairs along d. d2_glob = bx*64 + d2.
        #pragma unroll
        for (int r = 0; r < 16; r++) {
            const int i  = tid + 128 * r;
            const int d2 = i >> 5;
            const int s4 = (i & 31) << 2;
            uint32_t h[4], l[4];
            #pragma unroll
            for (int j = 0; j < 4; j++) {
                float a0 = Cs[(s4 + j) * 129 + 2 * d2];
                float a1 = Cs[(s4 + j) * 129 + 2 * d2 + 1];
                float h0 = bf16rd(a0), h1 = bf16rd(a1);
                h[j] = pack2bf(h0, h1);
                l[j] = pack2bf(a0 - h0, a1 - h1);
            }
            size_t base = (size_t)(bx * 64 + d2) * MTOT + by * 128 + s4;
            *(uint4*)&Phi[base] = make_uint4(h[0], h[1], h[2], h[3]);
            *(uint4*)&Plo[base] = make_uint4(l[0], l[1], l[2], l[3]);
        }
    } else {  // EPI_VPLANE: vhi/vlo[d_glob][s2], pairs along s. d_glob = bx*128 + d.
        #pragma unroll
        for (int r = 0; r < 16; r++) {
            const int i  = tid + 128 * r;
            const int d  = i >> 4;
            const int sg = (i & 15) << 2;
            uint32_t h[4], l[4];
            #pragma unroll
            for (int j = 0; j < 4; j++) {
                float a0 = Cs[(2 * (sg + j)) * 129 + d];
                float a1 = Cs[(2 * (sg + j) + 1) * 129 + d];
                float h0 = bf16rd(a0), h1 = bf16rd(a1);
                h[j] = pack2bf(h0, h1);
                l[j] = pack2bf(a0 - h0, a1 - h1);
            }
            size_t base = (size_t)(bx * 128 + d) * (MTOT / 2) + by * 64 + sg;
            *(uint4*)&Phi[base] = make_uint4(h[0], h[1], h[2], h[3]);
            *(uint4*)&Plo[base] = make_uint4(l[0], l[1], l[2], l[3]);
        }
    }
}

// Fused Q/K/V projection: one launch, 24 x 32 CTAs.
//   bx in [0,16)  -> Q  (fp32, transposed into qT)
//   bx in [16,20) -> K  (split-bf16 planes, pairs along d)
//   bx in [20,24) -> V  (split-bf16 planes, pairs along s)
__global__ __launch_bounds__(128, 2)
void qkv_gemm(const float* __restrict__ x,
              const float* __restrict__ wq, const float* __restrict__ wk,
              const float* __restrict__ wv,
              float* __restrict__ qT,
              uint32_t* __restrict__ khi, uint32_t* __restrict__ klo,
              uint32_t* __restrict__ vhi, uint32_t* __restrict__ vlo) {
    extern __shared__ float sh[];
    const int bx = blockIdx.x;
    const int by = blockIdx.y;
    if (bx < 16)
        gemm_body(x, wq, qT, nullptr, nullptr, MTOT, DMODEL, DMODEL, bx, by, EPI_QT, sh);
    else if (bx < 20)
        gemm_body(x, wk, nullptr, khi, klo, MTOT, KVDIM, DMODEL, bx - 16, by, EPI_KPLANE, sh);
    else
        gemm_body(x, wv, nullptr, vhi, vlo, MTOT, KVDIM, DMODEL, bx - 20, by, EPI_VPLANE, sh);
}

// O projection (natural store only).
__global__ __launch_bounds__(128, 2)
void o_gemm(const float* __restrict__ A, const float* __restrict__ B,
            float* __restrict__ C) {
    extern __shared__ float sh[];
    gemm_body(A, B, C, nullptr, nullptr, MTOT, DMODEL, DMODEL,
              blockIdx.x, blockIdx.y, EPI_NAT, sh);
}

// ---------------- Split-bf16 tensor-core flash attention --------------------
// 128 threads (4 warps), q tile 64 rows, kv tiles of 64. 3 CTAs/SM.
// K/V arrive as precomputed split-bf16 planes -> tile loads are pure copies.
#define QP 72                               // Q [d2=64][m=64]
#define KP 72                               // K [d2=64][n=64]
#define VP 137                              // V [k2=32][n=128] (conflict-free pad)
#define SM_QHI 0
#define SM_QLO (64 * QP)                    // 4608
#define SM_KHI (2 * 64 * QP)                // 9216
#define SM_KLO (SM_KHI + 64 * KP)           // 13824
#define SM_VHI SM_KHI                       // overlays K (sequenced)
#define SM_VLO (SM_VHI + 32 * VP)           // +4384 (fits inside K region)
#define ATT_SMEM_U32 (SM_KHI + 2 * 64 * KP) // 18432
#define ATT_SMEM (ATT_SMEM_U32 * 4)         // 73728 B -> 3 CTAs/SM

#define ATT_THREADS 128

__global__ __launch_bounds__(ATT_THREADS, 3)
void attn_kernel(const float* __restrict__ QT,
                 const uint32_t* __restrict__ KHI, const uint32_t* __restrict__ KLO,
                 const uint32_t* __restrict__ VHI, const uint32_t* __restrict__ VLO,
                 float* __restrict__ O) {
    extern __shared__ uint32_t smu[];
    uint32_t* Qhi = smu + SM_QHI;
    uint32_t* Qlo = smu + SM_QLO;
    uint32_t* Khi = smu + SM_KHI;
    uint32_t* Klo = smu + SM_KLO;
    uint32_t* Vhi = smu + SM_VHI;
    uint32_t* Vlo = smu + SM_VLO;

    const int tid  = threadIdx.x;
    const int lane = tid & 31;
    const int g    = lane >> 2;         // 0..7
    const int lt   = lane & 3;          // 0..3
    const int warp = tid >> 5;          // 0..3
    const int m0   = warp * 16;         // warp's q-row block (within 64)
    const int bh   = blockIdx.y;
    const int b    = bh >> 4;
    const int h    = bh & 15;
    const int kvh  = h >> 2;
    const int bxe  = gridDim.x - 1 - blockIdx.x;   // heavy tiles first
    const int q0   = bxe * 64;

    // ---- load Q tile, split into hi/lo bf16x2 planes [d2=64][m=64] ----
    for (int i = tid; i < 64 * 16; i += ATT_THREADS) {
        int d2 = i >> 4;
        int m4 = (i & 15) << 2;
        const float* pa = &QT[(size_t)(h * HDIM + 2 * d2) * MTOT + b * SEQ + q0 + m4];
        float4 qa = *(const float4*)pa;
        float4 qb = *(const float4*)(pa + MTOT);
        const float fa[4] = {qa.x, qa.y, qa.z, qa.w};
        const float fb[4] = {qb.x, qb.y, qb.z, qb.w};
        uint32_t hi[4], lo[4];
        #pragma unroll
        for (int j = 0; j < 4; j++) {
            float ah = bf16rd(fa[j]);
            float bh_ = bf16rd(fb[j]);
            hi[j] = pack2bf(ah, bh_);
            lo[j] = pack2bf(fa[j] - ah, fb[j] - bh_);
        }
        *(uint4*)&Qhi[d2 * QP + m4] = make_uint4(hi[0], hi[1], hi[2], hi[3]);
        *(uint4*)&Qlo[d2 * QP + m4] = make_uint4(lo[0], lo[1], lo[2], lo[3]);
    }

    float m_s[2] = {-1e30f, -1e30f};
    float l_s[2] = {0.f, 0.f};
    float o[16][4];
    #pragma unroll
    for (int nt = 0; nt < 16; nt++)
        #pragma unroll
        for (int r = 0; r < 4; r++) o[nt][r] = 0.f;

    const float scale = 0.08838834764831845f;   // 1/sqrt(128)
    const int ntk = bxe + 1;
    const int row0 = q0 + m0 + g;               // global q row (and +8)

    for (int tt = 0; tt < ntk; tt++) {
        const int k0 = tt * 64;
        __syncthreads();     // prev PV done reading V before K overwrite

        // ---- copy K tile [d2=64][n=64] from precomputed planes ----
        for (int i = tid; i < 64 * 16; i += ATT_THREADS) {
            int d2 = i >> 4;
            int n4 = (i & 15) << 2;
            size_t base = (size_t)(kvh * 64 + d2) * MTOT + b * SEQ + k0 + n4;
            *(uint4*)&Khi[d2 * KP + n4] = *(const uint4*)&KHI[base];
            *(uint4*)&Klo[d2 * KP + n4] = *(const uint4*)&KLO[base];
        }
        __syncthreads();

        // ---- S = Q K^T : 8 k16 steps, 3 MMAs each ----
        float s[8][4];
        #pragma unroll
        for (int nt = 0; nt < 8; nt++)
            #pragma unroll
            for (int r = 0; r < 4; r++) s[nt][r] = 0.f;

        #pragma unroll 4
        for (int ks = 0; ks < 8; ks++) {
            const int kb = ks * 8;
            uint32_t ah[4], al[4];
            ah[0] = Qhi[(kb + lt) * QP + m0 + g];
            ah[1] = Qhi[(kb + lt) * QP + m0 + g + 8];
            ah[2] = Qhi[(kb + lt + 4) * QP + m0 + g];
            ah[3] = Qhi[(kb + lt + 4) * QP + m0 + g + 8];
            al[0] = Qlo[(kb + lt) * QP + m0 + g];
            al[1] = Qlo[(kb + lt) * QP + m0 + g + 8];
            al[2] = Qlo[(kb + lt + 4) * QP + m0 + g];
            al[3] = Qlo[(kb + lt + 4) * QP + m0 + g + 8];
            #pragma unroll
            for (int nt = 0; nt < 8; nt++) {
                const int n0 = nt * 8 + g;
                uint32_t bh_[2], bl_[2];
                bh_[0] = Khi[(kb + lt) * KP + n0];
                bh_[1] = Khi[(kb + lt + 4) * KP + n0];
                bl_[0] = Klo[(kb + lt) * KP + n0];
                bl_[1] = Klo[(kb + lt + 4) * KP + n0];
                mma_bf16(s[nt], ah, bh_);
                mma_bf16(s[nt], al, bh_);
                mma_bf16(s[nt], ah, bl_);
            }
        }

        // ---- online softmax (rows g and g+8, full 64 cols in-warp) ----
        const bool diag = (k0 >= q0);
        #pragma unroll
        for (int nt = 0; nt < 8; nt++) {
            const int c0 = k0 + nt * 8 + 2 * lt;
            float v0 = s[nt][0] * scale;
            float v1 = s[nt][1] * scale;
            float v2 = s[nt][2] * scale;
            float v3 = s[nt][3] * scale;
            if (diag) {
                if (c0     > row0)     v0 = -1e30f;
                if (c0 + 1 > row0)     v1 = -1e30f;
                if (c0     > row0 + 8) v2 = -1e30f;
                if (c0 + 1 > row0 + 8) v3 = -1e30f;
            }
            s[nt][0] = v0; s[nt][1] = v1; s[nt][2] = v2; s[nt][3] = v3;
        }
        float mx0 = -1e30f, mx1 = -1e30f;
        #pragma unroll
        for (int nt = 0; nt < 8; nt++) {
            mx0 = fmaxf(mx0, fmaxf(s[nt][0], s[nt][1]));
            mx1 = fmaxf(mx1, fmaxf(s[nt][2], s[nt][3]));
        }
        mx0 = fmaxf(mx0, __shfl_xor_sync(0xffffffffu, mx0, 1));
        mx0 = fmaxf(mx0, __shfl_xor_sync(0xffffffffu, mx0, 2));
        mx1 = fmaxf(mx1, __shfl_xor_sync(0xffffffffu, mx1, 1));
        mx1 = fmaxf(mx1, __shfl_xor_sync(0xffffffffu, mx1, 2));

        const float mn0 = fmaxf(m_s[0], mx0);
        const float mn1 = fmaxf(m_s[1], mx1);
        const float cr0 = __expf(m_s[0] - mn0);
        const float cr1 = __expf(m_s[1] - mn1);
        float rs0 = 0.f, rs1 = 0.f;
        #pragma unroll
        for (int nt = 0; nt < 8; nt++) {
            s[nt][0] = __expf(s[nt][0] - mn0);
            s[nt][1] = __expf(s[nt][1] - mn0);
            s[nt][2] = __expf(s[nt][2] - mn1);
            s[nt][3] = __expf(s[nt][3] - mn1);
            rs0 += s[nt][0] + s[nt][1];
            rs1 += s[nt][2] + s[nt][3];
        }
        rs0 += __shfl_xor_sync(0xffffffffu, rs0, 1);
        rs0 += __shfl_xor_sync(0xffffffffu, rs0, 2);
        rs1 += __shfl_xor_sync(0xffffffffu, rs1, 1);
        rs1 += __shfl_xor_sync(0xffffffffu, rs1, 2);
        l_s[0] = l_s[0] * cr0 + rs0;  m_s[0] = mn0;
        l_s[1] = l_s[1] * cr1 + rs1;  m_s[1] = mn1;
        #pragma unroll
        for (int nt = 0; nt < 16; nt++) {
            o[nt][0] *= cr0; o[nt][1] *= cr0;
            o[nt][2] *= cr1; o[nt][3] *= cr1;
        }

        // ---- build P fragments in registers (C-frag == A-frag layout) ----
        uint32_t pha[8], phb[8], pla[8], plb[8];
        #pragma unroll
        for (int nt = 0; nt < 8; nt++) {
            float h0 = bf16rd(s[nt][0]), h1 = bf16rd(s[nt][1]);
            float h2 = bf16rd(s[nt][2]), h3 = bf16rd(s[nt][3]);
            pha[nt] = pack2bf(h0, h1);
            pla[nt] = pack2bf(s[nt][0] - h0, s[nt][1] - h1);
            phb[nt] = pack2bf(h2, h3);
            plb[nt] = pack2bf(s[nt][2] - h2, s[nt][3] - h3);
        }

        __syncthreads();    // all warps done reading K before V overwrite

        // ---- copy V tile [k2=32][n=128] from precomputed planes ----
        for (int i = tid; i < 128 * 8; i += ATT_THREADS) {
            int n  = i >> 3;
            int kg = (i & 7) << 2;
            size_t base = (size_t)(kvh * HDIM + n) * (MTOT / 2) + b * (SEQ / 2) + (k0 >> 1) + kg;
            uint4 hv = *(const uint4*)&VHI[base];
            uint4 lv = *(const uint4*)&VLO[base];
            Vhi[(kg + 0) * VP + n] = hv.x;
            Vhi[(kg + 1) * VP + n] = hv.y;
            Vhi[(kg + 2) * VP + n] = hv.z;
            Vhi[(kg + 3) * VP + n] = hv.w;
            Vlo[(kg + 0) * VP + n] = lv.x;
            Vlo[(kg + 1) * VP + n] = lv.y;
            Vlo[(kg + 2) * VP + n] = lv.z;
            Vlo[(kg + 3) * VP + n] = lv.w;
        }
        __syncthreads();

        // ---- O += P V : 4 k16 steps, 3 MMAs each; P from registers ----
        #pragma unroll
        for (int ks = 0; ks < 4; ks++) {
            const int kb = ks * 8;
            uint32_t ph[4], pl[4];
            ph[0] = pha[2 * ks];     ph[1] = phb[2 * ks];
            ph[2] = pha[2 * ks + 1]; ph[3] = phb[2 * ks + 1];
            pl[0] = pla[2 * ks];     pl[1] = plb[2 * ks];
            pl[2] = pla[2 * ks + 1]; pl[3] = plb[2 * ks + 1];
            #pragma unroll
            for (int nt = 0; nt < 16; nt++) {
                const int n0 = nt * 8 + g;
                uint32_t vh[2], vl[2];
                vh[0] = Vhi[(kb + lt) * VP + n0];
                vh[1] = Vhi[(kb + 4 + lt) * VP + n0];
                vl[0] = Vlo[(kb + lt) * VP + n0];
                vl[1] = Vlo[(kb + 4 + lt) * VP + n0];
                mma_bf16(o[nt], ph, vh);
                mma_bf16(o[nt], pl, vh);
                mma_bf16(o[nt], ph, vl);
            }
        }
    }

    // ---- epilogue: normalize, store ----
    const float inv0 = 1.f / l_s[0];
    const float inv1 = 1.f / l_s[1];
    #pragma unroll
    for (int nt = 0; nt < 16; nt++) {
        const int col = h * HDIM + nt * 8 + 2 * lt;
        float2 v01 = make_float2(o[nt][0] * inv0, o[nt][1] * inv0);
        float2 v23 = make_float2(o[nt][2] * inv1, o[nt][3] * inv1);
        *(float2*)&O[(size_t)(b * SEQ + q0 + m0 + g) * DMODEL + col]     = v01;
        *(float2*)&O[(size_t)(b * SEQ + q0 + m0 + g + 8) * DMODEL + col] = v23;
    }
}

// ---------------- launch -----------------------------------------------------
extern "C" void kernel_launch(void* const* d_in, const int* in_sizes, int n_in,
                              void* d_out, int out_size) {
    const float* x  = (const float*)d_in[0];
    const float* wq = (const float*)d_in[1];
    const float* wk = (const float*)d_in[2];
    const float* wv = (const float*)d_in[3];
    const float* wo = (const float*)d_in[4];
    float* out = (float*)d_out;

    float *qT, *att;
    uint32_t *khi, *klo, *vhi, *vlo;
    cudaGetSymbolAddress((void**)&qT,  g_qT);
    cudaGetSymbolAddress((void**)&khi, g_khi);
    cudaGetSymbolAddress((void**)&klo, g_klo);
    cudaGetSymbolAddress((void**)&vhi, g_vhi);
    cudaGetSymbolAddress((void**)&vlo, g_vlo);
    cudaGetSymbolAddress((void**)&att, g_att);

    cudaFuncSetAttribute(attn_kernel, cudaFuncAttributeMaxDynamicSharedMemorySize, ATT_SMEM);
    cudaFuncSetAttribute(qkv_gemm, cudaFuncAttributeMaxDynamicSharedMemorySize, FUSED_SMEM);
    cudaFuncSetAttribute(o_gemm,   cudaFuncAttributeMaxDynamicSharedMemorySize, FUSED_SMEM);

    dim3 blk(128);
    // fused Q/K/V projections: 24 x 32 CTAs, one launch
    qkv_gemm<<<dim3(24, MTOT / 128), blk, FUSED_SMEM>>>(x, wq, wk, wv, qT, khi, klo, vhi, vlo);
    // attention: 32 q-tiles (64 rows each) x 32 (batch,head), 3 CTAs/SM
    attn_kernel<<<dim3(SEQ / 64, BATCH * NHEADS), dim3(ATT_THREADS), ATT_SMEM>>>(
        qT, khi, klo, vhi, vlo, att);
    // output projection
    o_gemm<<<dim3(DMODEL / 128, MTOT / 128), blk, FUSED_SMEM>>>(att, wo, out);
}